// round 2
// baseline (speedup 1.0000x reference)
#include <cuda_runtime.h>
#include <cuda_bf16.h>
#include <math.h>

// ---------------- constants ----------------
#define BATCH   8
#define SEQ     512
#define HID     768
#define NHEADS  12
#define HDIM    64
#define FFDIM   3072
#define NLAYERS 12
#define ROWS    (BATCH*SEQ)          // 4096
#define NBH     (BATCH*NHEADS)       // 96

// ---------------- scratch (device globals; allocation-free) ----------------
__device__ float g_hidden[ROWS*HID];
__device__ float g_q     [ROWS*HID];      // [B,H,S,d]
__device__ float g_kt    [ROWS*HID];      // [B,H,d,S]
__device__ float g_v     [ROWS*HID];      // [B,H,S,d]
__device__ float g_ctx   [ROWS*HID];      // [B,S,H]
__device__ float g_tmp   [ROWS*HID];
__device__ float g_ff    [ROWS*FFDIM];
__device__ float g_scores[(long)NBH*SEQ*SEQ];
__device__ float g_pb    [NHEADS*SEQ*SEQ]; // [h,q,k]
__device__ float g_mask  [ROWS];           // [b,s] additive

// ---------------- helpers ----------------
__device__ __forceinline__ float warpReduceSum(float v){
#pragma unroll
    for (int o=16;o>0;o>>=1) v += __shfl_xor_sync(0xffffffffu, v, o);
    return v;
}
__device__ __forceinline__ float warpReduceMax(float v){
#pragma unroll
    for (int o=16;o>0;o>>=1) v = fmaxf(v, __shfl_xor_sync(0xffffffffu, v, o));
    return v;
}
__device__ float blockReduceSum(float v){
    __shared__ float sh[8];
    __shared__ float total;
    int lane = threadIdx.x & 31, wid = threadIdx.x >> 5;
    v = warpReduceSum(v);
    __syncthreads();               // protect sh reuse across calls
    if (lane == 0) sh[wid] = v;
    __syncthreads();
    if (wid == 0){
        float r = (lane < 8) ? sh[lane] : 0.f;
        r = warpReduceSum(r);
        if (lane == 0) total = r;
    }
    __syncthreads();
    return total;
}

// ---------------- small kernels ----------------
__global__ void copy4_k(const float4* __restrict__ src, float4* __restrict__ dst, int n4){
    int i = blockIdx.x*blockDim.x + threadIdx.x;
    if (i < n4) dst[i] = src[i];
}

__global__ void mask_k(const int* __restrict__ seg, float* __restrict__ mask){
    int i = blockIdx.x*blockDim.x + threadIdx.x;
    if (i < ROWS) mask[i] = (seg[i] > 0) ? 0.f : -10000.f;
}

__device__ __forceinline__ int rel_bucket(int qpos, int kpos){
    int rel = kpos - qpos;
    int off = (rel > 0) ? 16 : 0;
    int ar  = rel < 0 ? -rel : rel;
    if (ar < 8) return off + ar;
    float t = logf((float)ar / 8.0f) / 2.772588722239781f * 8.0f; // /log(16) * 8
    int v = 8 + (int)t;
    if (v > 15) v = 15;
    return off + v;
}

__global__ void posbias_k(const float* __restrict__ rel_emb, float* __restrict__ pb){
    int idx = blockIdx.x*blockDim.x + threadIdx.x;   // over SEQ*SEQ
    if (idx >= SEQ*SEQ) return;
    int q = idx >> 9, k = idx & 511;
    int bkt = rel_bucket(q, k);
#pragma unroll
    for (int h=0; h<NHEADS; h++)
        pb[((long)h*SEQ + q)*SEQ + k] = rel_emb[bkt*NHEADS + h];
}

__global__ void softmax_k(float* __restrict__ scores, int rows){
    int w = (blockIdx.x*blockDim.x + threadIdx.x) >> 5;
    if (w >= rows) return;
    int lane = threadIdx.x & 31;
    float* row = scores + (long)w * SEQ;
    float v[16]; float mx = -3.0e38f;
#pragma unroll
    for (int i=0;i<16;i++){ v[i] = row[lane + 32*i]; mx = fmaxf(mx, v[i]); }
    mx = warpReduceMax(mx);
    float s = 0.f;
#pragma unroll
    for (int i=0;i<16;i++){ v[i] = expf(v[i]-mx); s += v[i]; }
    s = warpReduceSum(s);
    float inv = 1.f/s;
#pragma unroll
    for (int i=0;i<16;i++) row[lane + 32*i] = v[i]*inv;
}

__global__ __launch_bounds__(256) void resln_k(
    const float* __restrict__ resid, const float* __restrict__ x,
    const float* __restrict__ g, const float* __restrict__ b,
    float* __restrict__ out)
{
    long base = (long)blockIdx.x * HID;
    int t = threadIdx.x;
    float v[3]; float s = 0.f;
#pragma unroll
    for (int i=0;i<3;i++){ v[i] = resid[base + t + 256*i] + x[base + t + 256*i]; s += v[i]; }
    s = blockReduceSum(s);
    float mean = s * (1.f/768.f);
    float q = 0.f;
#pragma unroll
    for (int i=0;i<3;i++){ float d = v[i]-mean; q += d*d; }
    q = blockReduceSum(q);
    float inv = 1.f / sqrtf(q*(1.f/768.f) + 1e-6f);
#pragma unroll
    for (int i=0;i<3;i++){
        int c = t + 256*i;
        out[base + c] = g[c]*(v[i]-mean)*inv + b[c];
    }
}

// ---------------- GEMM ----------------
#define BM 128
#define BN 128
#define BKK 8
#define TM 8
#define TN 8

enum { EPI_PLAIN=0, EPI_GELU=1, EPI_QKV=2, EPI_KT=3, EPI_SCORES=4, EPI_CTX=5 };

template<int EPI>
__global__ __launch_bounds__(256) void gemm_k(
    const float* __restrict__ A, const float* __restrict__ B, float* __restrict__ C,
    int M, int N, int K,
    long sA, long sB, long sC,
    const float* __restrict__ bias,
    const float* __restrict__ posbias,
    const float* __restrict__ mask)
{
    __shared__ float As[BKK][BM];
    __shared__ float Bs[BKK][BN];
    int tid = threadIdx.x;
    int z = blockIdx.z;
    const float* Ab = A + (long)z * sA;
    const float* Bb = B + (long)z * sB;
    int mBase = blockIdx.y * BM;
    int nBase = blockIdx.x * BN;
    int aRow = tid >> 1,  aCol = (tid & 1) * 4;
    int bRow = tid >> 5,  bCol = (tid & 31) * 4;
    int tx = tid & 15,    ty = tid >> 4;

    float acc[TM][TN];
#pragma unroll
    for (int i=0;i<TM;i++)
#pragma unroll
        for (int j=0;j<TN;j++) acc[i][j] = 0.f;

    for (int k0=0; k0<K; k0+=BKK){
        // A tile (M,K multiples of tile in all call sites)
        {
            const float* p = Ab + (long)(mBase + aRow) * K + (k0 + aCol);
            float4 av = *(const float4*)p;
            As[aCol+0][aRow] = av.x; As[aCol+1][aRow] = av.y;
            As[aCol+2][aRow] = av.z; As[aCol+3][aRow] = av.w;
        }
        // B tile (guard columns: N may be 64 with BN=128)
        {
            int gn = nBase + bCol;
            const float* p = Bb + (long)(k0 + bRow) * N + gn;
            float4 bv;
            if (gn + 3 < N) bv = *(const float4*)p;
            else {
                bv.x = (gn+0<N) ? p[0] : 0.f;
                bv.y = (gn+1<N) ? p[1] : 0.f;
                bv.z = (gn+2<N) ? p[2] : 0.f;
                bv.w = (gn+3<N) ? p[3] : 0.f;
            }
            *(float4*)&Bs[bRow][bCol] = bv;
        }
        __syncthreads();
#pragma unroll
        for (int k=0;k<BKK;k++){
            float a[TM], b[TN];
            *(float4*)&a[0] = *(const float4*)&As[k][ty*TM];
            *(float4*)&a[4] = *(const float4*)&As[k][ty*TM+4];
            *(float4*)&b[0] = *(const float4*)&Bs[k][tx*TN];
            *(float4*)&b[4] = *(const float4*)&Bs[k][tx*TN+4];
#pragma unroll
            for (int i=0;i<TM;i++)
#pragma unroll
                for (int j=0;j<TN;j++)
                    acc[i][j] = fmaf(a[i], b[j], acc[i][j]);
        }
        __syncthreads();
    }

    // epilogue
#pragma unroll
    for (int i=0;i<TM;i++){
        int m = mBase + ty*TM + i;
#pragma unroll
        for (int j=0;j<TN;j++){
            int n = nBase + tx*TN + j;
            if (n >= N) continue;
            float v = acc[i][j];
            if (EPI == EPI_PLAIN){
                v += bias[n];
                C[sC*z + (long)m*N + n] = v;
            } else if (EPI == EPI_GELU){
                v += bias[n];
                v = 0.5f*v*(1.f + erff(v*0.70710678118654752f));
                C[(long)m*N + n] = v;
            } else if (EPI == EPI_QKV){
                v += bias[n];
                int b_ = m >> 9, s = m & 511;
                int h = n >> 6, dd = n & 63;
                C[(((long)(b_*NHEADS + h)*SEQ + s) << 6) + dd] = v;
            } else if (EPI == EPI_KT){
                v += bias[n];
                int b_ = m >> 9, s = m & 511;
                int h = n >> 6, dd = n & 63;
                C[((long)(b_*NHEADS + h)*HDIM + dd)*SEQ + s] = v;
            } else if (EPI == EPI_SCORES){
                int b_ = z / NHEADS, h = z % NHEADS;
                v = v * 0.125f + posbias[((long)h*SEQ + m)*SEQ + n] + mask[b_*SEQ + n];
                C[(long)z*sC + (long)m*SEQ + n] = v;
            } else if (EPI == EPI_CTX){
                int b_ = z / NHEADS, h = z % NHEADS;
                C[((long)(b_*SEQ + m))*HID + h*HDIM + n] = v;
            }
        }
    }
}

// ---------------- host side ----------------
static void launch_gemm(int epi, const float* A, const float* B, float* C,
                        int M, int N, int K, long sA, long sB, long sC, int batches,
                        const float* bias, const float* pb, const float* mask)
{
    dim3 grid((N+BN-1)/BN, (M+BM-1)/BM, batches);
    switch (epi){
    case EPI_PLAIN:  gemm_k<EPI_PLAIN ><<<grid,256>>>(A,B,C,M,N,K,sA,sB,sC,bias,pb,mask); break;
    case EPI_GELU:   gemm_k<EPI_GELU  ><<<grid,256>>>(A,B,C,M,N,K,sA,sB,sC,bias,pb,mask); break;
    case EPI_QKV:    gemm_k<EPI_QKV   ><<<grid,256>>>(A,B,C,M,N,K,sA,sB,sC,bias,pb,mask); break;
    case EPI_KT:     gemm_k<EPI_KT    ><<<grid,256>>>(A,B,C,M,N,K,sA,sB,sC,bias,pb,mask); break;
    case EPI_SCORES: gemm_k<EPI_SCORES><<<grid,256>>>(A,B,C,M,N,K,sA,sB,sC,bias,pb,mask); break;
    case EPI_CTX:    gemm_k<EPI_CTX   ><<<grid,256>>>(A,B,C,M,N,K,sA,sB,sC,bias,pb,mask); break;
    }
}

extern "C" void kernel_launch(void* const* d_in, const int* in_sizes, int n_in,
                              void* d_out, int out_size)
{
    const float* emb     = (const float*)d_in[0];
    const int*   seg     = (const int*)  d_in[1];
    const float* rel_emb = (const float*)d_in[2];
    const float* Wq = (const float*)d_in[3];  const float* bq = (const float*)d_in[4];
    const float* Wk = (const float*)d_in[5];  const float* bk = (const float*)d_in[6];
    const float* Wv = (const float*)d_in[7];  const float* bv = (const float*)d_in[8];
    const float* Wo = (const float*)d_in[9];  const float* bo = (const float*)d_in[10];
    const float* ln1_g = (const float*)d_in[11]; const float* ln1_b = (const float*)d_in[12];
    const float* W1 = (const float*)d_in[13]; const float* b1 = (const float*)d_in[14];
    const float* W2 = (const float*)d_in[15]; const float* b2 = (const float*)d_in[16];
    const float* ln2_g = (const float*)d_in[17]; const float* ln2_b = (const float*)d_in[18];
    float* out = (float*)d_out;

    // Symbol lookups happen once, on the uncaptured correctness call.
    static float *hid=nullptr,*q,*kt,*v,*ctx,*tmp,*ff,*sc,*pb,*mk;
    if (!hid){
        cudaGetSymbolAddress((void**)&hid, g_hidden);
        cudaGetSymbolAddress((void**)&q,   g_q);
        cudaGetSymbolAddress((void**)&kt,  g_kt);
        cudaGetSymbolAddress((void**)&v,   g_v);
        cudaGetSymbolAddress((void**)&ctx, g_ctx);
        cudaGetSymbolAddress((void**)&tmp, g_tmp);
        cudaGetSymbolAddress((void**)&ff,  g_ff);
        cudaGetSymbolAddress((void**)&sc,  g_scores);
        cudaGetSymbolAddress((void**)&pb,  g_pb);
        cudaGetSymbolAddress((void**)&mk,  g_mask);
    }

    // setup
    copy4_k<<<(ROWS*HID/4 + 255)/256, 256>>>((const float4*)emb, (float4*)hid, ROWS*HID/4);
    mask_k<<<(ROWS+255)/256, 256>>>(seg, mk);
    posbias_k<<<(SEQ*SEQ+255)/256, 256>>>(rel_emb, pb);

    const long sQK = (long)SEQ*HDIM;   // 32768
    const long sSC = (long)SEQ*SEQ;    // 262144

    for (int L=0; L<NLAYERS; L++){
        launch_gemm(EPI_QKV, hid, Wq, q,  ROWS, HID, HID, 0,0,0, 1, bq, nullptr, nullptr);
        launch_gemm(EPI_KT,  hid, Wk, kt, ROWS, HID, HID, 0,0,0, 1, bk, nullptr, nullptr);
        launch_gemm(EPI_QKV, hid, Wv, v,  ROWS, HID, HID, 0,0,0, 1, bv, nullptr, nullptr);

        launch_gemm(EPI_SCORES, q, kt, sc, SEQ, SEQ, HDIM, sQK, sQK, sSC, NBH,
                    nullptr, pb, mk);

        softmax_k<<<(NBH*SEQ*32)/256, 256>>>(sc, NBH*SEQ);

        launch_gemm(EPI_CTX, sc, v, ctx, SEQ, HDIM, SEQ, sSC, sQK, 0, NBH,
                    nullptr, nullptr, nullptr);

        launch_gemm(EPI_PLAIN, ctx, Wo, tmp, ROWS, HID, HID, 0,0,0, 1, bo, nullptr, nullptr);
        resln_k<<<ROWS, 256>>>(hid, tmp, ln1_g, ln1_b, hid);

        launch_gemm(EPI_GELU,  hid, W1, ff,  ROWS, FFDIM, HID, 0,0,0, 1, b1, nullptr, nullptr);
        launch_gemm(EPI_PLAIN, ff,  W2, tmp, ROWS, HID, FFDIM, 0,0,0, 1, b2, nullptr, nullptr);
        resln_k<<<ROWS, 256>>>(hid, tmp, ln2_g, ln2_b, (L == NLAYERS-1) ? out : hid);
    }
}

// round 4
// speedup vs baseline: 1.7767x; 1.7767x over previous
#include <cuda_runtime.h>
#include <cuda_bf16.h>
#include <math.h>
#include <stdint.h>

// ---------------- constants ----------------
#define BATCH   8
#define SEQ     512
#define HID     768
#define NHEADS  12
#define HDIM    64
#define FFDIM   3072
#define NLAYERS 12
#define ROWS    (BATCH*SEQ)          // 4096
#define NBH     (BATCH*NHEADS)       // 96

typedef __nv_bfloat16 bf;

// ---------------- scratch (device globals; allocation-free) ----------------
__device__ float g_hidden[ROWS*HID];
__device__ float g_tmp   [ROWS*HID];
__device__ float g_scores[(long)NBH*SEQ*SEQ];
__device__ float g_pb    [NHEADS*SEQ*SEQ];
__device__ float g_mask  [ROWS];

__device__ bf g_hidA_hi[ROWS*HID], g_hidA_lo[ROWS*HID];
__device__ bf g_q_hi [ROWS*HID], g_q_lo [ROWS*HID];   // [B,H,S,64]
__device__ bf g_k_hi [ROWS*HID], g_k_lo [ROWS*HID];   // [B,H,S,64]
__device__ bf g_vt_hi[ROWS*HID], g_vt_lo[ROWS*HID];   // [B,H,64,S]
__device__ bf g_ctx_hi[ROWS*HID], g_ctx_lo[ROWS*HID]; // [B*S,768]
__device__ bf g_ff_hi[ROWS*FFDIM], g_ff_lo[ROWS*FFDIM];
__device__ bf g_p_hi[(long)NBH*SEQ*SEQ], g_p_lo[(long)NBH*SEQ*SEQ];

__device__ bf g_WqT_hi[HID*HID],  g_WqT_lo[HID*HID];
__device__ bf g_WkT_hi[HID*HID],  g_WkT_lo[HID*HID];
__device__ bf g_WvT_hi[HID*HID],  g_WvT_lo[HID*HID];
__device__ bf g_WoT_hi[HID*HID],  g_WoT_lo[HID*HID];
__device__ bf g_W1T_hi[HID*FFDIM], g_W1T_lo[HID*FFDIM]; // [3072,768]
__device__ bf g_W2T_hi[HID*FFDIM], g_W2T_lo[HID*FFDIM]; // [768,3072]

// ---------------- PTX helpers (sm_100 baseline only) ----------------
__device__ __forceinline__ uint32_t smem_u32(const void* p){
    uint32_t a;
    asm("{ .reg .u64 t; cvta.to.shared.u64 t, %1; cvt.u32.u64 %0, t; }" : "=r"(a) : "l"(p));
    return a;
}
__device__ __forceinline__ void cp16(uint32_t dst, const void* src){
    asm volatile("cp.async.cg.shared.global [%0], [%1], 16;" :: "r"(dst), "l"(src));
}
#define CP_COMMIT() asm volatile("cp.async.commit_group;" ::: "memory")
#define CP_WAIT(n)  asm volatile("cp.async.wait_group %0;" :: "n"(n) : "memory")

__device__ __forceinline__ void mma16816(float* d, uint32_t a0, uint32_t a1,
                                         uint32_t a2, uint32_t a3,
                                         uint32_t b0, uint32_t b1){
    asm volatile(
        "mma.sync.aligned.m16n8k16.row.col.f32.bf16.bf16.f32 "
        "{%0,%1,%2,%3}, {%4,%5,%6,%7}, {%8,%9}, {%0,%1,%2,%3};"
        : "+f"(d[0]), "+f"(d[1]), "+f"(d[2]), "+f"(d[3])
        : "r"(a0), "r"(a1), "r"(a2), "r"(a3), "r"(b0), "r"(b1));
}

__device__ __forceinline__ void bsplit(float v, bf& h, bf& l){
    h = __float2bfloat16(v);
    l = __float2bfloat16(v - __bfloat162float(h));
}

// ---------------- reductions ----------------
__device__ __forceinline__ float warpSum(float v){
#pragma unroll
    for (int o=16;o>0;o>>=1) v += __shfl_xor_sync(0xffffffffu, v, o);
    return v;
}
__device__ __forceinline__ float warpMax(float v){
#pragma unroll
    for (int o=16;o>0;o>>=1) v = fmaxf(v, __shfl_xor_sync(0xffffffffu, v, o));
    return v;
}
__device__ float blockSum(float v){
    __shared__ float sh[8];
    __shared__ float total;
    int lane = threadIdx.x & 31, wid = threadIdx.x >> 5;
    v = warpSum(v);
    __syncthreads();
    if (lane == 0) sh[wid] = v;
    __syncthreads();
    if (wid == 0){
        float r = (lane < 8) ? sh[lane] : 0.f;
        r = warpSum(r);
        if (lane == 0) total = r;
    }
    __syncthreads();
    return total;
}

// ---------------- small kernels ----------------
__global__ void split_copy_k(const float* __restrict__ src, float* __restrict__ dstF,
                             bf* __restrict__ hi, bf* __restrict__ lo, int n){
    int i = blockIdx.x*blockDim.x + threadIdx.x;
    if (i >= n) return;
    float v = src[i];
    dstF[i] = v;
    bf h, l; bsplit(v, h, l);
    hi[i] = h; lo[i] = l;
}

__global__ void mask_k(const int* __restrict__ seg, float* __restrict__ mask){
    int i = blockIdx.x*blockDim.x + threadIdx.x;
    if (i < ROWS) mask[i] = (seg[i] > 0) ? 0.f : -10000.f;
}

__device__ __forceinline__ int rel_bucket(int qpos, int kpos){
    int rel = kpos - qpos;
    int off = (rel > 0) ? 16 : 0;
    int ar  = rel < 0 ? -rel : rel;
    if (ar < 8) return off + ar;
    float t = logf((float)ar / 8.0f) / 2.772588722239781f * 8.0f;
    int v = 8 + (int)t;
    if (v > 15) v = 15;
    return off + v;
}

__global__ void posbias_k(const float* __restrict__ rel_emb, float* __restrict__ pb){
    int idx = blockIdx.x*blockDim.x + threadIdx.x;
    if (idx >= SEQ*SEQ) return;
    int q = idx >> 9, k = idx & 511;
    int bkt = rel_bucket(q, k);
#pragma unroll
    for (int h=0; h<NHEADS; h++)
        pb[((long)h*SEQ + q)*SEQ + k] = rel_emb[bkt*NHEADS + h];
}

// W[K,N] fp32 -> WT hi/lo [N,K] bf16, 32x32 smem-tiled
__global__ void tsplit_k(const float* __restrict__ W,
                         bf* __restrict__ Thi, bf* __restrict__ Tlo,
                         int K, int N){
    __shared__ float t[32][33];
    int k0 = blockIdx.y*32, n0 = blockIdx.x*32;
    int x = threadIdx.x, y = threadIdx.y;
#pragma unroll
    for (int i=y; i<32; i+=8) t[i][x] = W[(long)(k0+i)*N + n0 + x];
    __syncthreads();
#pragma unroll
    for (int i=y; i<32; i+=8){
        float v = t[x][i];
        bf h, l; bsplit(v, h, l);
        long o = (long)(n0+i)*K + k0 + x;
        Thi[o] = h; Tlo[o] = l;
    }
}

__global__ void softmax_k(const float* __restrict__ scores,
                          bf* __restrict__ phi, bf* __restrict__ plo){
    int w = (blockIdx.x*blockDim.x + threadIdx.x) >> 5;
    int lane = threadIdx.x & 31;
    const float* row = scores + (long)w * SEQ;
    float v[16]; float mx = -3.0e38f;
#pragma unroll
    for (int i=0;i<16;i++){ v[i] = row[lane + 32*i]; mx = fmaxf(mx, v[i]); }
    mx = warpMax(mx);
    float s = 0.f;
#pragma unroll
    for (int i=0;i<16;i++){ v[i] = expf(v[i]-mx); s += v[i]; }
    s = warpSum(s);
    float inv = 1.f/s;
    long base = (long)w * SEQ;
#pragma unroll
    for (int i=0;i<16;i++){
        float p = v[i]*inv;
        bf h, l; bsplit(p, h, l);
        phi[base + lane + 32*i] = h;
        plo[base + lane + 32*i] = l;
    }
}

__global__ __launch_bounds__(256) void resln_k(
    const float* __restrict__ resid, const float* __restrict__ x,
    const float* __restrict__ g, const float* __restrict__ b,
    float* __restrict__ out,
    bf* __restrict__ ohi, bf* __restrict__ olo)
{
    long base = (long)blockIdx.x * HID;
    int t = threadIdx.x;
    float v[3]; float s = 0.f;
#pragma unroll
    for (int i=0;i<3;i++){ v[i] = resid[base + t + 256*i] + x[base + t + 256*i]; s += v[i]; }
    s = blockSum(s);
    float mean = s * (1.f/768.f);
    float q = 0.f;
#pragma unroll
    for (int i=0;i<3;i++){ float d = v[i]-mean; q += d*d; }
    q = blockSum(q);
    float inv = 1.f / sqrtf(q*(1.f/768.f) + 1e-6f);
#pragma unroll
    for (int i=0;i<3;i++){
        int c = t + 256*i;
        float r = g[c]*(v[i]-mean)*inv + b[c];
        out[base + c] = r;
        bf h, l; bsplit(r, h, l);
        ohi[base + c] = h; olo[base + c] = l;
    }
}

// ---------------- mma.sync GEMM ----------------
// D[128/CTA, BN_] = Ahi*Bhi + Ahi*Blo + Alo*Bhi over K (chunks of 32)
// A: [rows,K] bf16 K-major (lda). B: [N,K] bf16 K-major (ldb).
enum { EPI_PLAIN=0, EPI_GELU=1, EPI_QKV=2, EPI_VT=3, EPI_SCORES=4, EPI_CTX=5 };

template<int BN_, int EPI>
__global__ __launch_bounds__(256,1) void mma_gemm(
    const bf* __restrict__ Ahi, const bf* __restrict__ Alo,
    const bf* __restrict__ Bhi, const bf* __restrict__ Blo,
    int K, int lda, int ldb, long sA, long sB,
    const float* __restrict__ bias,
    float* __restrict__ outF, bf* __restrict__ outHi, bf* __restrict__ outLo,
    int ldc,
    const float* __restrict__ pb, const float* __restrict__ msk)
{
    constexpr int WGM = (BN_ == 128) ? 2 : 4;
    constexpr int WGN = 8 / WGM;
    constexpr int WM  = 128 / WGM;      // 64 or 32
    constexpr int WN  = BN_ / WGN;      // 32
    constexpr int MT  = WM / 16;        // 4 or 2
    constexpr int NTT = WN / 8;         // 4
    constexpr int SK  = 40;             // padded smem row stride (bf16)
    constexpr int A_HI = 0;
    constexpr int A_LO = 128*SK;
    constexpr int B_HI = 2*128*SK;
    constexpr int B_LO = 2*128*SK + BN_*SK;
    constexpr int STAGE = 2*128*SK + 2*BN_*SK;   // bf16 units

    extern __shared__ __align__(16) char smem[];
    bf* sm = (bf*)smem;
    const uint32_t sbase = smem_u32(smem);

    const int tid = threadIdx.x, lane = tid & 31, warp = tid >> 5;
    const int warpM = warp / WGN, warpN = warp % WGN;
    const int z = blockIdx.z;
    const int mBase = blockIdx.y * 128, nBase = blockIdx.x * BN_;
    const bf* Ah = Ahi + (long)z * sA;
    const bf* Al = Alo + (long)z * sA;
    const bf* Bh = Bhi + (long)z * sB;
    const bf* Bl = Blo + (long)z * sB;

    auto issue = [&](int c){
        const int s = c & 1, k0 = c << 5;
        const uint32_t segbase = sbase + (uint32_t)(s * STAGE * 2);
        for (int r = tid; r < 256 + 2*BN_; r += 256){
            const bf* src; uint32_t doff;
            if (r < 128)          { src = Ah + (long)(mBase+r)*lda + k0;            doff = (A_HI + r*SK)*2u; }
            else if (r < 256)     { int rr=r-128;     src = Al + (long)(mBase+rr)*lda + k0; doff = (A_LO + rr*SK)*2u; }
            else if (r < 256+BN_) { int rr=r-256;     src = Bh + (long)(nBase+rr)*ldb + k0; doff = (B_HI + rr*SK)*2u; }
            else                  { int rr=r-256-BN_; src = Bl + (long)(nBase+rr)*ldb + k0; doff = (B_LO + rr*SK)*2u; }
            uint32_t d = segbase + doff;
            cp16(d,    src);
            cp16(d+16, src+8);
            cp16(d+32, src+16);
            cp16(d+48, src+24);
        }
        CP_COMMIT();
    };

    float acc[MT][NTT][4];
#pragma unroll
    for (int i=0;i<MT;i++)
#pragma unroll
        for (int j=0;j<NTT;j++)
#pragma unroll
            for (int e=0;e<4;e++) acc[i][j][e] = 0.f;

    const int CH = K >> 5;
    issue(0);
    for (int c = 0; c < CH; ++c){
        if (c+1 < CH){ issue(c+1); CP_WAIT(1); }
        else         { CP_WAIT(0); }
        __syncthreads();
        const bf* st = sm + (c & 1) * STAGE;
#pragma unroll
        for (int k16 = 0; k16 < 2; ++k16){
            const int kk = k16*16 + (lane & 3)*2;
            uint32_t ah[MT][4], al[MT][4];
#pragma unroll
            for (int mt = 0; mt < MT; ++mt){
                int r0 = warpM*WM + mt*16 + (lane >> 2);
                ah[mt][0] = *(const uint32_t*)(st + A_HI + r0*SK + kk);
                ah[mt][1] = *(const uint32_t*)(st + A_HI + (r0+8)*SK + kk);
                ah[mt][2] = *(const uint32_t*)(st + A_HI + r0*SK + kk + 8);
                ah[mt][3] = *(const uint32_t*)(st + A_HI + (r0+8)*SK + kk + 8);
                al[mt][0] = *(const uint32_t*)(st + A_LO + r0*SK + kk);
                al[mt][1] = *(const uint32_t*)(st + A_LO + (r0+8)*SK + kk);
                al[mt][2] = *(const uint32_t*)(st + A_LO + r0*SK + kk + 8);
                al[mt][3] = *(const uint32_t*)(st + A_LO + (r0+8)*SK + kk + 8);
            }
            uint32_t bh[NTT][2], bl[NTT][2];
#pragma unroll
            for (int nt = 0; nt < NTT; ++nt){
                int n0 = warpN*WN + nt*8 + (lane >> 2);
                bh[nt][0] = *(const uint32_t*)(st + B_HI + n0*SK + kk);
                bh[nt][1] = *(const uint32_t*)(st + B_HI + n0*SK + kk + 8);
                bl[nt][0] = *(const uint32_t*)(st + B_LO + n0*SK + kk);
                bl[nt][1] = *(const uint32_t*)(st + B_LO + n0*SK + kk + 8);
            }
#pragma unroll
            for (int mt = 0; mt < MT; ++mt)
#pragma unroll
                for (int nt = 0; nt < NTT; ++nt){
                    mma16816(acc[mt][nt], ah[mt][0],ah[mt][1],ah[mt][2],ah[mt][3], bh[nt][0],bh[nt][1]);
                    mma16816(acc[mt][nt], ah[mt][0],ah[mt][1],ah[mt][2],ah[mt][3], bl[nt][0],bl[nt][1]);
                    mma16816(acc[mt][nt], al[mt][0],al[mt][1],al[mt][2],al[mt][3], bh[nt][0],bh[nt][1]);
                }
        }
        __syncthreads();
    }

    // ---------------- epilogue: stage D via padded smem ----------------
    float* sD = (float*)smem;
    constexpr int LDD = BN_ + 1;
#pragma unroll
    for (int mt = 0; mt < MT; ++mt)
#pragma unroll
        for (int nt = 0; nt < NTT; ++nt){
            int r0 = warpM*WM + mt*16 + (lane >> 2);
            int c0 = warpN*WN + nt*8 + (lane & 3)*2;
            sD[r0*LDD + c0]       = acc[mt][nt][0];
            sD[r0*LDD + c0 + 1]   = acc[mt][nt][1];
            sD[(r0+8)*LDD + c0]   = acc[mt][nt][2];
            sD[(r0+8)*LDD + c0+1] = acc[mt][nt][3];
        }
    __syncthreads();

    if (EPI == EPI_VT){
        for (int t = tid; t < 128*BN_; t += 256){
            int m = t & 127, n = t >> 7;
            int nn = nBase + n, h = nn >> 6, dd = nn & 63;
            int mm = mBase + m, b_ = mm >> 9, sidx = mm & 511;
            float v = sD[m*LDD + n] + bias[nn];
            bf hh, ll; bsplit(v, hh, ll);
            long idx = ((long)(b_*NHEADS + h)*HDIM + dd)*SEQ + sidx;
            outHi[idx] = hh; outLo[idx] = ll;
        }
    } else {
        constexpr int NQ = BN_ / 4;
        for (int t = tid; t < 128*NQ; t += 256){
            int m = t / NQ, nq = t % NQ;
            int n0 = nBase + nq*4;
            int mg = mBase + m;
            float e[4];
#pragma unroll
            for (int j=0;j<4;j++) e[j] = sD[m*LDD + nq*4 + j];
            if (EPI == EPI_PLAIN){
#pragma unroll
                for (int j=0;j<4;j++) e[j] += bias[n0+j];
                float4 v = {e[0],e[1],e[2],e[3]};
                *(float4*)&outF[(long)mg*ldc + n0] = v;
            } else if (EPI == EPI_SCORES){
                int b_ = z / NHEADS, h = z % NHEADS;
                float4 pbv = *(const float4*)&pb[((long)h*SEQ + mg)*SEQ + n0];
                float4 mkv = *(const float4*)&msk[b_*SEQ + n0];
                float4 v;
                v.x = e[0]*0.125f + pbv.x + mkv.x;
                v.y = e[1]*0.125f + pbv.y + mkv.y;
                v.z = e[2]*0.125f + pbv.z + mkv.z;
                v.w = e[3]*0.125f + pbv.w + mkv.w;
                *(float4*)&outF[(long)z*SEQ*SEQ + (long)mg*SEQ + n0] = v;
            } else {
                if (EPI == EPI_GELU){
#pragma unroll
                    for (int j=0;j<4;j++){
                        float t2 = e[j] + bias[n0+j];
                        e[j] = 0.5f*t2*(1.f + erff(t2*0.70710678118654752f));
                    }
                } else if (EPI == EPI_QKV){
#pragma unroll
                    for (int j=0;j<4;j++) e[j] += bias[n0+j];
                }
                bf h0,h1,h2,h3,l0,l1,l2,l3;
                bsplit(e[0],h0,l0); bsplit(e[1],h1,l1);
                bsplit(e[2],h2,l2); bsplit(e[3],h3,l3);
                long idx;
                if (EPI == EPI_GELU){
                    idx = (long)mg*ldc + n0;
                } else if (EPI == EPI_QKV){
                    int b_ = mg >> 9, sidx = mg & 511, h = n0 >> 6, dd = n0 & 63;
                    idx = ((long)(b_*NHEADS + h)*SEQ + sidx)*HDIM + dd;
                } else { // EPI_CTX
                    int b_ = z / NHEADS, h = z % NHEADS;
                    idx = ((long)(b_*SEQ + mg))*HID + h*HDIM + n0;
                }
                *(__nv_bfloat162*)&outHi[idx]   = __nv_bfloat162(h0,h1);
                *(__nv_bfloat162*)&outHi[idx+2] = __nv_bfloat162(h2,h3);
                *(__nv_bfloat162*)&outLo[idx]   = __nv_bfloat162(l0,l1);
                *(__nv_bfloat162*)&outLo[idx+2] = __nv_bfloat162(l2,l3);
            }
        }
    }
}

// ---------------- host ----------------
#define SMEM128 81920   // max(2*40960, 128*129*4=66048)
#define SMEM64  61440   // max(2*30720, 128*65*4=33280)

extern "C" void kernel_launch(void* const* d_in, const int* in_sizes, int n_in,
                              void* d_out, int out_size)
{
    const float* emb     = (const float*)d_in[0];
    const int*   seg     = (const int*)  d_in[1];
    const float* rel_emb = (const float*)d_in[2];
    const float* Wq = (const float*)d_in[3];  const float* bq = (const float*)d_in[4];
    const float* Wk = (const float*)d_in[5];  const float* bk = (const float*)d_in[6];
    const float* Wv = (const float*)d_in[7];  const float* bv = (const float*)d_in[8];
    const float* Wo = (const float*)d_in[9];  const float* bo = (const float*)d_in[10];
    const float* ln1_g = (const float*)d_in[11]; const float* ln1_b = (const float*)d_in[12];
    const float* W1 = (const float*)d_in[13]; const float* b1 = (const float*)d_in[14];
    const float* W2 = (const float*)d_in[15]; const float* b2 = (const float*)d_in[16];
    const float* ln2_g = (const float*)d_in[17]; const float* ln2_b = (const float*)d_in[18];
    float* out = (float*)d_out;

    static bool inited = false;
    static float *hid, *tmp, *sc, *pb, *mk;
    static bf *hA_h,*hA_l,*q_h,*q_l,*k_h,*k_l,*vt_h,*vt_l,*cx_h,*cx_l,*ff_h,*ff_l,*p_h,*p_l;
    static bf *wq_h,*wq_l,*wk_h,*wk_l,*wv_h,*wv_l,*wo_h,*wo_l,*w1_h,*w1_l,*w2_h,*w2_l;
    if (!inited){
        inited = true;
        cudaGetSymbolAddress((void**)&hid, g_hidden);
        cudaGetSymbolAddress((void**)&tmp, g_tmp);
        cudaGetSymbolAddress((void**)&sc,  g_scores);
        cudaGetSymbolAddress((void**)&pb,  g_pb);
        cudaGetSymbolAddress((void**)&mk,  g_mask);
        cudaGetSymbolAddress((void**)&hA_h, g_hidA_hi); cudaGetSymbolAddress((void**)&hA_l, g_hidA_lo);
        cudaGetSymbolAddress((void**)&q_h,  g_q_hi);    cudaGetSymbolAddress((void**)&q_l,  g_q_lo);
        cudaGetSymbolAddress((void**)&k_h,  g_k_hi);    cudaGetSymbolAddress((void**)&k_l,  g_k_lo);
        cudaGetSymbolAddress((void**)&vt_h, g_vt_hi);   cudaGetSymbolAddress((void**)&vt_l, g_vt_lo);
        cudaGetSymbolAddress((void**)&cx_h, g_ctx_hi);  cudaGetSymbolAddress((void**)&cx_l, g_ctx_lo);
        cudaGetSymbolAddress((void**)&ff_h, g_ff_hi);   cudaGetSymbolAddress((void**)&ff_l, g_ff_lo);
        cudaGetSymbolAddress((void**)&p_h,  g_p_hi);    cudaGetSymbolAddress((void**)&p_l,  g_p_lo);
        cudaGetSymbolAddress((void**)&wq_h, g_WqT_hi);  cudaGetSymbolAddress((void**)&wq_l, g_WqT_lo);
        cudaGetSymbolAddress((void**)&wk_h, g_WkT_hi);  cudaGetSymbolAddress((void**)&wk_l, g_WkT_lo);
        cudaGetSymbolAddress((void**)&wv_h, g_WvT_hi);  cudaGetSymbolAddress((void**)&wv_l, g_WvT_lo);
        cudaGetSymbolAddress((void**)&wo_h, g_WoT_hi);  cudaGetSymbolAddress((void**)&wo_l, g_WoT_lo);
        cudaGetSymbolAddress((void**)&w1_h, g_W1T_hi);  cudaGetSymbolAddress((void**)&w1_l, g_W1T_lo);
        cudaGetSymbolAddress((void**)&w2_h, g_W2T_hi);  cudaGetSymbolAddress((void**)&w2_l, g_W2T_lo);
        cudaFuncSetAttribute(mma_gemm<128,EPI_PLAIN>,  cudaFuncAttributeMaxDynamicSharedMemorySize, SMEM128);
        cudaFuncSetAttribute(mma_gemm<128,EPI_GELU>,   cudaFuncAttributeMaxDynamicSharedMemorySize, SMEM128);
        cudaFuncSetAttribute(mma_gemm<128,EPI_QKV>,    cudaFuncAttributeMaxDynamicSharedMemorySize, SMEM128);
        cudaFuncSetAttribute(mma_gemm<128,EPI_VT>,     cudaFuncAttributeMaxDynamicSharedMemorySize, SMEM128);
        cudaFuncSetAttribute(mma_gemm<128,EPI_SCORES>, cudaFuncAttributeMaxDynamicSharedMemorySize, SMEM128);
        cudaFuncSetAttribute(mma_gemm<64, EPI_CTX>,    cudaFuncAttributeMaxDynamicSharedMemorySize, SMEM64);
    }

    // ---- setup ----
    tsplit_k<<<dim3(HID/32, HID/32),   dim3(32,8)>>>(Wq, wq_h, wq_l, HID, HID);
    tsplit_k<<<dim3(HID/32, HID/32),   dim3(32,8)>>>(Wk, wk_h, wk_l, HID, HID);
    tsplit_k<<<dim3(HID/32, HID/32),   dim3(32,8)>>>(Wv, wv_h, wv_l, HID, HID);
    tsplit_k<<<dim3(HID/32, HID/32),   dim3(32,8)>>>(Wo, wo_h, wo_l, HID, HID);
    tsplit_k<<<dim3(FFDIM/32, HID/32), dim3(32,8)>>>(W1, w1_h, w1_l, HID, FFDIM);
    tsplit_k<<<dim3(HID/32, FFDIM/32), dim3(32,8)>>>(W2, w2_h, w2_l, FFDIM, HID);
    split_copy_k<<<(ROWS*HID+255)/256, 256>>>(emb, hid, hA_h, hA_l, ROWS*HID);
    mask_k<<<(ROWS+255)/256, 256>>>(seg, mk);
    posbias_k<<<(SEQ*SEQ+255)/256, 256>>>(rel_emb, pb);

    const long sQK = (long)SEQ*HDIM;   // 32768
    const long sSC = (long)SEQ*SEQ;    // 262144

    for (int L=0; L<NLAYERS; L++){
        // QKV projections (M=4096, N=768, K=768)
        mma_gemm<128,EPI_QKV><<<dim3(6,32,1),256,SMEM128>>>(
            hA_h,hA_l, wq_h,wq_l, HID, HID, HID, 0,0, bq, nullptr, q_h,q_l, 0, nullptr,nullptr);
        mma_gemm<128,EPI_QKV><<<dim3(6,32,1),256,SMEM128>>>(
            hA_h,hA_l, wk_h,wk_l, HID, HID, HID, 0,0, bk, nullptr, k_h,k_l, 0, nullptr,nullptr);
        mma_gemm<128,EPI_VT><<<dim3(6,32,1),256,SMEM128>>>(
            hA_h,hA_l, wv_h,wv_l, HID, HID, HID, 0,0, bv, nullptr, vt_h,vt_l, 0, nullptr,nullptr);

        // scores = Q K^T * scale + pb + mask  (96 x [512,512,64])
        mma_gemm<128,EPI_SCORES><<<dim3(4,4,NBH),256,SMEM128>>>(
            q_h,q_l, k_h,k_l, HDIM, HDIM, HDIM, sQK,sQK, nullptr, sc, nullptr,nullptr, 0, pb, mk);

        softmax_k<<<(NBH*SEQ)/8, 256>>>(sc, p_h, p_l);

        // ctx = P V  (96 x [512,64,512]) -> [B*S, 768] bf16 split
        mma_gemm<64,EPI_CTX><<<dim3(1,4,NBH),256,SMEM64>>>(
            p_h,p_l, vt_h,vt_l, SEQ, SEQ, SEQ, sSC, sQK, nullptr, nullptr, cx_h,cx_l, 0, nullptr,nullptr);

        // O projection
        mma_gemm<128,EPI_PLAIN><<<dim3(6,32,1),256,SMEM128>>>(
            cx_h,cx_l, wo_h,wo_l, HID, HID, HID, 0,0, bo, tmp, nullptr,nullptr, HID, nullptr,nullptr);
        resln_k<<<ROWS,256>>>(hid, tmp, ln1_g, ln1_b, hid, hA_h, hA_l);

        // FF1 (M=4096, N=3072, K=768) with GELU
        mma_gemm<128,EPI_GELU><<<dim3(24,32,1),256,SMEM128>>>(
            hA_h,hA_l, w1_h,w1_l, HID, HID, HID, 0,0, b1, nullptr, ff_h,ff_l, FFDIM, nullptr,nullptr);
        // FF2 (M=4096, N=768, K=3072)
        mma_gemm<128,EPI_PLAIN><<<dim3(6,32,1),256,SMEM128>>>(
            ff_h,ff_l, w2_h,w2_l, FFDIM, FFDIM, FFDIM, 0,0, b2, tmp, nullptr,nullptr, HID, nullptr,nullptr);
        resln_k<<<ROWS,256>>>(hid, tmp, ln2_g, ln2_b, (L==NLAYERS-1) ? out : hid, hA_h, hA_l);
    }
}

// round 7
// speedup vs baseline: 2.0864x; 1.1743x over previous
#include <cuda_runtime.h>
#include <cuda_bf16.h>
#include <math.h>
#include <stdint.h>

// ---------------- constants ----------------
#define BATCH   8
#define SEQ     512
#define HID     768
#define NHEADS  12
#define HDIM    64
#define FFDIM   3072
#define NLAYERS 12
#define ROWS    (BATCH*SEQ)          // 4096
#define NBH     (BATCH*NHEADS)       // 96

typedef __nv_bfloat16 bf;

// ---------------- scratch (device globals; allocation-free) ----------------
__device__ float g_hidden[ROWS*HID];
__device__ float g_tmp   [ROWS*HID];
__device__ float g_scores[(long)NBH*SEQ*SEQ];
__device__ float g_pb    [NHEADS*SEQ*SEQ];
__device__ float g_mask  [ROWS];

__device__ bf g_hidA_hi[ROWS*HID], g_hidA_lo[ROWS*HID];
__device__ bf g_q_hi [ROWS*HID], g_q_lo [ROWS*HID];   // [B,H,S,64]
__device__ bf g_k_hi [ROWS*HID], g_k_lo [ROWS*HID];   // [B,H,S,64]
__device__ bf g_vt_hi[ROWS*HID], g_vt_lo[ROWS*HID];   // [B,H,64,S]
__device__ bf g_ctx_hi[ROWS*HID], g_ctx_lo[ROWS*HID]; // [B*S,768]
__device__ bf g_ff_hi[ROWS*FFDIM], g_ff_lo[ROWS*FFDIM];
__device__ bf g_p_hi[(long)NBH*SEQ*SEQ], g_p_lo[(long)NBH*SEQ*SEQ];

__device__ bf g_WqT_hi[HID*HID],  g_WqT_lo[HID*HID];
__device__ bf g_WkT_hi[HID*HID],  g_WkT_lo[HID*HID];
__device__ bf g_WvT_hi[HID*HID],  g_WvT_lo[HID*HID];
__device__ bf g_WoT_hi[HID*HID],  g_WoT_lo[HID*HID];
__device__ bf g_W1T_hi[HID*FFDIM], g_W1T_lo[HID*FFDIM]; // [3072,768]
__device__ bf g_W2T_hi[HID*FFDIM], g_W2T_lo[HID*FFDIM]; // [768,3072]

// ---------------- PTX helpers (sm_100 baseline only) ----------------
__device__ __forceinline__ uint32_t smem_u32(const void* p){
    uint32_t a;
    asm("{ .reg .u64 t; cvta.to.shared.u64 t, %1; cvt.u32.u64 %0, t; }" : "=r"(a) : "l"(p));
    return a;
}
__device__ __forceinline__ void cp16(uint32_t dst, const void* src){
    asm volatile("cp.async.cg.shared.global [%0], [%1], 16;" :: "r"(dst), "l"(src));
}
#define CP_COMMIT() asm volatile("cp.async.commit_group;" ::: "memory")
#define CP_WAIT(n)  asm volatile("cp.async.wait_group %0;" :: "n"(n) : "memory")

__device__ __forceinline__ void ldsm4(uint32_t* r, uint32_t addr){
    asm volatile("ldmatrix.sync.aligned.m8n8.x4.shared.b16 {%0,%1,%2,%3}, [%4];"
                 : "=r"(r[0]), "=r"(r[1]), "=r"(r[2]), "=r"(r[3]) : "r"(addr));
}

__device__ __forceinline__ void mma16816(float* d, const uint32_t* a,
                                         uint32_t b0, uint32_t b1){
    asm volatile(
        "mma.sync.aligned.m16n8k16.row.col.f32.bf16.bf16.f32 "
        "{%0,%1,%2,%3}, {%4,%5,%6,%7}, {%8,%9}, {%0,%1,%2,%3};"
        : "+f"(d[0]), "+f"(d[1]), "+f"(d[2]), "+f"(d[3])
        : "r"(a[0]), "r"(a[1]), "r"(a[2]), "r"(a[3]), "r"(b0), "r"(b1));
}

__device__ __forceinline__ void bsplit(float v, bf& h, bf& l){
    h = __float2bfloat16(v);
    l = __float2bfloat16(v - __bfloat162float(h));
}

// ---------------- reductions ----------------
__device__ __forceinline__ float warpSum(float v){
#pragma unroll
    for (int o=16;o>0;o>>=1) v += __shfl_xor_sync(0xffffffffu, v, o);
    return v;
}
__device__ __forceinline__ float warpMax(float v){
#pragma unroll
    for (int o=16;o>0;o>>=1) v = fmaxf(v, __shfl_xor_sync(0xffffffffu, v, o));
    return v;
}
__device__ float blockSum(float v){
    __shared__ float sh[8];
    __shared__ float total;
    int lane = threadIdx.x & 31, wid = threadIdx.x >> 5;
    v = warpSum(v);
    __syncthreads();
    if (lane == 0) sh[wid] = v;
    __syncthreads();
    if (wid == 0){
        float r = (lane < 8) ? sh[lane] : 0.f;
        r = warpSum(r);
        if (lane == 0) total = r;
    }
    __syncthreads();
    return total;
}

// ---------------- small kernels ----------------
__global__ void split_copy_k(const float* __restrict__ src, float* __restrict__ dstF,
                             bf* __restrict__ hi, bf* __restrict__ lo, int n){
    int i = blockIdx.x*blockDim.x + threadIdx.x;
    if (i >= n) return;
    float v = src[i];
    dstF[i] = v;
    bf h, l; bsplit(v, h, l);
    hi[i] = h; lo[i] = l;
}

__global__ void mask_k(const int* __restrict__ seg, float* __restrict__ mask){
    int i = blockIdx.x*blockDim.x + threadIdx.x;
    if (i < ROWS) mask[i] = (seg[i] > 0) ? 0.f : -10000.f;
}

__device__ __forceinline__ int rel_bucket(int qpos, int kpos){
    int rel = kpos - qpos;
    int off = (rel > 0) ? 16 : 0;
    int ar  = rel < 0 ? -rel : rel;
    if (ar < 8) return off + ar;
    float t = logf((float)ar / 8.0f) / 2.772588722239781f * 8.0f;
    int v = 8 + (int)t;
    if (v > 15) v = 15;
    return off + v;
}

__global__ void posbias_k(const float* __restrict__ rel_emb, float* __restrict__ pb){
    int idx = blockIdx.x*blockDim.x + threadIdx.x;
    if (idx >= SEQ*SEQ) return;
    int q = idx >> 9, k = idx & 511;
    int bkt = rel_bucket(q, k);
#pragma unroll
    for (int h=0; h<NHEADS; h++)
        pb[((long)h*SEQ + q)*SEQ + k] = rel_emb[bkt*NHEADS + h];
}

// W[K,N] fp32 -> WT hi/lo [N,K] bf16, 32x32 smem-tiled
__global__ void tsplit_k(const float* __restrict__ W,
                         bf* __restrict__ Thi, bf* __restrict__ Tlo,
                         int K, int N){
    __shared__ float t[32][33];
    int k0 = blockIdx.y*32, n0 = blockIdx.x*32;
    int x = threadIdx.x, y = threadIdx.y;
#pragma unroll
    for (int i=y; i<32; i+=8) t[i][x] = W[(long)(k0+i)*N + n0 + x];
    __syncthreads();
#pragma unroll
    for (int i=y; i<32; i+=8){
        float v = t[x][i];
        bf h, l; bsplit(v, h, l);
        long o = (long)(n0+i)*K + k0 + x;
        Thi[o] = h; Tlo[o] = l;
    }
}

__global__ void softmax_k(const float* __restrict__ scores,
                          bf* __restrict__ phi, bf* __restrict__ plo){
    int w = (blockIdx.x*blockDim.x + threadIdx.x) >> 5;
    int lane = threadIdx.x & 31;
    const float* row = scores + (long)w * SEQ;
    float v[16]; float mx = -3.0e38f;
#pragma unroll
    for (int i=0;i<16;i++){ v[i] = row[lane + 32*i]; mx = fmaxf(mx, v[i]); }
    mx = warpMax(mx);
    float s = 0.f;
#pragma unroll
    for (int i=0;i<16;i++){ v[i] = expf(v[i]-mx); s += v[i]; }
    s = warpSum(s);
    float inv = 1.f/s;
    long base = (long)w * SEQ;
#pragma unroll
    for (int i=0;i<16;i++){
        float p = v[i]*inv;
        bf h, l; bsplit(p, h, l);
        phi[base + lane + 32*i] = h;
        plo[base + lane + 32*i] = l;
    }
}

__global__ __launch_bounds__(256) void resln_k(
    const float* __restrict__ resid, const float* __restrict__ x,
    const float* __restrict__ g, const float* __restrict__ b,
    float* __restrict__ out,
    bf* __restrict__ ohi, bf* __restrict__ olo)
{
    long base = (long)blockIdx.x * HID;
    int t = threadIdx.x;
    float v[3]; float s = 0.f;
#pragma unroll
    for (int i=0;i<3;i++){ v[i] = resid[base + t + 256*i] + x[base + t + 256*i]; s += v[i]; }
    s = blockSum(s);
    float mean = s * (1.f/768.f);
    float q = 0.f;
#pragma unroll
    for (int i=0;i<3;i++){ float d = v[i]-mean; q += d*d; }
    q = blockSum(q);
    float inv = 1.f / sqrtf(q*(1.f/768.f) + 1e-6f);
#pragma unroll
    for (int i=0;i<3;i++){
        int c = t + 256*i;
        float r = g[c]*(v[i]-mean)*inv + b[c];
        out[base + c] = r;
        bf h, l; bsplit(r, h, l);
        ohi[base + c] = h; olo[base + c] = l;
    }
}

// ---------------- mma.sync GEMM (BK=64, 3-stage cp.async, ldmatrix) ----------------
// D[128/CTA, BN_] = Ahi*Bhi + Ahi*Blo + Alo*Bhi over K (chunks of 64)
// A: [rows,K] bf16 K-major (lda). B: [N,K] bf16 K-major (ldb).
enum { EPI_PLAIN=0, EPI_GELU=1, EPI_QKV=2, EPI_VT=3, EPI_SCORES=4, EPI_CTX=5 };

template<int BN_, int EPI>
__global__ __launch_bounds__(256,1) void mma_gemm(
    const bf* __restrict__ Ahi, const bf* __restrict__ Alo,
    const bf* __restrict__ Bhi, const bf* __restrict__ Blo,
    int K, int lda, int ldb, long sA, long sB,
    const float* __restrict__ bias,
    float* __restrict__ outF, bf* __restrict__ outHi, bf* __restrict__ outLo,
    int ldc,
    const float* __restrict__ pb, const float* __restrict__ msk)
{
    constexpr int WGM = (BN_ == 128) ? 2 : 4;
    constexpr int WGN = 8 / WGM;
    constexpr int WM  = 128 / WGM;      // 64 or 32
    constexpr int WN  = BN_ / WGN;      // 32
    constexpr int MT  = WM / 16;        // 4 or 2
    constexpr int NTT = WN / 8;         // 4
    constexpr int NG  = NTT / 2;        // 2 n16-groups
    // byte offsets within one stage (all rows are 64 bf16 = 128B)
    constexpr int A_HI = 0;
    constexpr int A_LO = 128*128;          // 16384
    constexpr int B_HI = 2*128*128;        // 32768
    constexpr int B_LO = 2*128*128 + BN_*128;
    constexpr int STAGE = 2*128*128 + 2*BN_*128;  // bytes: 64K / 48K
    constexpr int TOT_ROWS = 256 + 2*BN_;

    extern __shared__ __align__(16) char smem[];
    const uint32_t sbase = smem_u32(smem);

    const int tid = threadIdx.x, lane = tid & 31, warp = tid >> 5;
    const int warpM = warp / WGN, warpN = warp % WGN;
    const int z = blockIdx.z;
    const int mBase = blockIdx.y * 128, nBase = blockIdx.x * BN_;
    const bf* Ah = Ahi + (long)z * sA;
    const bf* Al = Alo + (long)z * sA;
    const bf* Bh = Bhi + (long)z * sB;
    const bf* Bl = Blo + (long)z * sB;

    auto issue = [&](int c){
        const int s = c % 3, k0 = c << 6;
        const uint32_t segbase = sbase + (uint32_t)(s * STAGE);
#pragma unroll 4
        for (int ci = tid; ci < TOT_ROWS*8; ci += 256){
            int r = ci >> 3, c16 = ci & 7;
            const bf* src; uint32_t toff; int rr;
            if (r < 128)          { rr = r;         src = Ah + (long)(mBase+rr)*lda + k0; toff = A_HI; }
            else if (r < 256)     { rr = r-128;     src = Al + (long)(mBase+rr)*lda + k0; toff = A_LO; }
            else if (r < 256+BN_) { rr = r-256;     src = Bh + (long)(nBase+rr)*ldb + k0; toff = B_HI; }
            else                  { rr = r-256-BN_; src = Bl + (long)(nBase+rr)*ldb + k0; toff = B_LO; }
            uint32_t dst = segbase + toff + (uint32_t)(rr*128) + (uint32_t)((c16*16) ^ ((rr&7)<<4));
            cp16(dst, src + c16*8);
        }
        CP_COMMIT();
    };

    float acc[MT][NTT][4];
#pragma unroll
    for (int i=0;i<MT;i++)
#pragma unroll
        for (int j=0;j<NTT;j++)
#pragma unroll
            for (int e=0;e<4;e++) acc[i][j][e] = 0.f;

    // per-lane ldmatrix row/col decomposition
    const int lt  = lane >> 3;                 // tile 0..3
    const int lrow = ((lt & 1) << 3) + (lane & 7);   // row within 16
    const int lcol = (lt >> 1) << 4;                 // 0 or 16 bytes (k half)

    const int CH = K >> 6;
    issue(0);
    if (CH > 1) issue(1);

    for (int c = 0; c < CH; ++c){
        if (c + 1 < CH) { CP_WAIT(1); } else { CP_WAIT(0); }
        __syncthreads();
        if (c + 2 < CH) issue(c + 2);

        const uint32_t st = sbase + (uint32_t)((c % 3) * STAGE);
#pragma unroll
        for (int kk = 0; kk < 4; ++kk){
            const uint32_t kb = (uint32_t)(kk << 5);   // byte offset of k16 within row
            uint32_t ah[MT][4], al[MT][4];
#pragma unroll
            for (int mt = 0; mt < MT; ++mt){
                int r = warpM*WM + mt*16 + lrow;
                uint32_t cb = (kb + lcol) ^ ((uint32_t)(r&7) << 4);
                ldsm4(ah[mt], st + A_HI + r*128 + cb);
                ldsm4(al[mt], st + A_LO + r*128 + cb);
            }
            uint32_t bh[NG][4], bl[NG][4];
#pragma unroll
            for (int g = 0; g < NG; ++g){
                int r = warpN*WN + g*16 + lrow;
                uint32_t cb = (kb + lcol) ^ ((uint32_t)(r&7) << 4);
                ldsm4(bh[g], st + B_HI + r*128 + cb);
                ldsm4(bl[g], st + B_LO + r*128 + cb);
            }
#pragma unroll
            for (int mt = 0; mt < MT; ++mt)
#pragma unroll
                for (int nt = 0; nt < NTT; ++nt){
                    int g = nt >> 1, sH = nt & 1;
                    mma16816(acc[mt][nt], ah[mt], bh[g][sH], bh[g][sH+2]);
                    mma16816(acc[mt][nt], ah[mt], bl[g][sH], bl[g][sH+2]);
                    mma16816(acc[mt][nt], al[mt], bh[g][sH], bh[g][sH+2]);
                }
        }
    }
    __syncthreads();

    // ---------------- epilogue: stage D via padded smem ----------------
    float* sD = (float*)smem;
    constexpr int LDD = BN_ + 1;
#pragma unroll
    for (int mt = 0; mt < MT; ++mt)
#pragma unroll
        for (int nt = 0; nt < NTT; ++nt){
            int r0 = warpM*WM + mt*16 + (lane >> 2);
            int c0 = warpN*WN + nt*8 + (lane & 3)*2;
            sD[r0*LDD + c0]       = acc[mt][nt][0];
            sD[r0*LDD + c0 + 1]   = acc[mt][nt][1];
            sD[(r0+8)*LDD + c0]   = acc[mt][nt][2];
            sD[(r0+8)*LDD + c0+1] = acc[mt][nt][3];
        }
    __syncthreads();

    if (EPI == EPI_VT){
        for (int t = tid; t < 128*BN_; t += 256){
            int m = t & 127, n = t >> 7;
            int nn = nBase + n, h = nn >> 6, dd = nn & 63;
            int mm = mBase + m, b_ = mm >> 9, sidx = mm & 511;
            float v = sD[m*LDD + n] + bias[nn];
            bf hh, ll; bsplit(v, hh, ll);
            long idx = ((long)(b_*NHEADS + h)*HDIM + dd)*SEQ + sidx;
            outHi[idx] = hh; outLo[idx] = ll;
        }
    } else {
        constexpr int NQ = BN_ / 4;
        for (int t = tid; t < 128*NQ; t += 256){
            int m = t / NQ, nq = t % NQ;
            int n0 = nBase + nq*4;
            int mg = mBase + m;
            float e[4];
#pragma unroll
            for (int j=0;j<4;j++) e[j] = sD[m*LDD + nq*4 + j];
            if (EPI == EPI_PLAIN){
#pragma unroll
                for (int j=0;j<4;j++) e[j] += bias[n0+j];
                float4 v = {e[0],e[1],e[2],e[3]};
                *(float4*)&outF[(long)mg*ldc + n0] = v;
            } else if (EPI == EPI_SCORES){
                int b_ = z / NHEADS, h = z % NHEADS;
                float4 pbv = *(const float4*)&pb[((long)h*SEQ + mg)*SEQ + n0];
                float4 mkv = *(const float4*)&msk[b_*SEQ + n0];
                float4 v;
                v.x = e[0]*0.125f + pbv.x + mkv.x;
                v.y = e[1]*0.125f + pbv.y + mkv.y;
                v.z = e[2]*0.125f + pbv.z + mkv.z;
                v.w = e[3]*0.125f + pbv.w + mkv.w;
                *(float4*)&outF[(long)z*SEQ*SEQ + (long)mg*SEQ + n0] = v;
            } else {
                if (EPI == EPI_GELU){
#pragma unroll
                    for (int j=0;j<4;j++){
                        float t2 = e[j] + bias[n0+j];
                        e[j] = 0.5f*t2*(1.f + erff(t2*0.70710678118654752f));
                    }
                } else if (EPI == EPI_QKV){
#pragma unroll
                    for (int j=0;j<4;j++) e[j] += bias[n0+j];
                }
                bf h0,h1,h2,h3,l0,l1,l2,l3;
                bsplit(e[0],h0,l0); bsplit(e[1],h1,l1);
                bsplit(e[2],h2,l2); bsplit(e[3],h3,l3);
                long idx;
                if (EPI == EPI_GELU){
                    idx = (long)mg*ldc + n0;
                } else if (EPI == EPI_QKV){
                    int b_ = mg >> 9, sidx = mg & 511, h = n0 >> 6, dd = n0 & 63;
                    idx = ((long)(b_*NHEADS + h)*SEQ + sidx)*HDIM + dd;
                } else { // EPI_CTX
                    int b_ = z / NHEADS, h = z % NHEADS;
                    idx = ((long)(b_*SEQ + mg))*HID + h*HDIM + n0;
                }
                *(__nv_bfloat162*)&outHi[idx]   = __nv_bfloat162(h0,h1);
                *(__nv_bfloat162*)&outHi[idx+2] = __nv_bfloat162(h2,h3);
                *(__nv_bfloat162*)&outLo[idx]   = __nv_bfloat162(l0,l1);
                *(__nv_bfloat162*)&outLo[idx+2] = __nv_bfloat162(l2,l3);
            }
        }
    }
}

// ---------------- host ----------------
#define SMEM128 196608   // 3 stages * 64KB  (>= 128*129*4 = 66048 epilogue)
#define SMEM64  147456   // 3 stages * 48KB

extern "C" void kernel_launch(void* const* d_in, const int* in_sizes, int n_in,
                              void* d_out, int out_size)
{
    const float* emb     = (const float*)d_in[0];
    const int*   seg     = (const int*)  d_in[1];
    const float* rel_emb = (const float*)d_in[2];
    const float* Wq = (const float*)d_in[3];  const float* bq = (const float*)d_in[4];
    const float* Wk = (const float*)d_in[5];  const float* bk = (const float*)d_in[6];
    const float* Wv = (const float*)d_in[7];  const float* bv = (const float*)d_in[8];
    const float* Wo = (const float*)d_in[9];  const float* bo = (const float*)d_in[10];
    const float* ln1_g = (const float*)d_in[11]; const float* ln1_b = (const float*)d_in[12];
    const float* W1 = (const float*)d_in[13]; const float* b1 = (const float*)d_in[14];
    const float* W2 = (const float*)d_in[15]; const float* b2 = (const float*)d_in[16];
    const float* ln2_g = (const float*)d_in[17]; const float* ln2_b = (const float*)d_in[18];
    float* out = (float*)d_out;

    static bool inited = false;
    static float *hid, *tmp, *sc, *pb, *mk;
    static bf *hA_h,*hA_l,*q_h,*q_l,*k_h,*k_l,*vt_h,*vt_l,*cx_h,*cx_l,*ff_h,*ff_l,*p_h,*p_l;
    static bf *wq_h,*wq_l,*wk_h,*wk_l,*wv_h,*wv_l,*wo_h,*wo_l,*w1_h,*w1_l,*w2_h,*w2_l;
    if (!inited){
        inited = true;
        cudaGetSymbolAddress((void**)&hid, g_hidden);
        cudaGetSymbolAddress((void**)&tmp, g_tmp);
        cudaGetSymbolAddress((void**)&sc,  g_scores);
        cudaGetSymbolAddress((void**)&pb,  g_pb);
        cudaGetSymbolAddress((void**)&mk,  g_mask);
        cudaGetSymbolAddress((void**)&hA_h, g_hidA_hi); cudaGetSymbolAddress((void**)&hA_l, g_hidA_lo);
        cudaGetSymbolAddress((void**)&q_h,  g_q_hi);    cudaGetSymbolAddress((void**)&q_l,  g_q_lo);
        cudaGetSymbolAddress((void**)&k_h,  g_k_hi);    cudaGetSymbolAddress((void**)&k_l,  g_k_lo);
        cudaGetSymbolAddress((void**)&vt_h, g_vt_hi);   cudaGetSymbolAddress((void**)&vt_l, g_vt_lo);
        cudaGetSymbolAddress((void**)&cx_h, g_ctx_hi);  cudaGetSymbolAddress((void**)&cx_l, g_ctx_lo);
        cudaGetSymbolAddress((void**)&ff_h, g_ff_hi);   cudaGetSymbolAddress((void**)&ff_l, g_ff_lo);
        cudaGetSymbolAddress((void**)&p_h,  g_p_hi);    cudaGetSymbolAddress((void**)&p_l,  g_p_lo);
        cudaGetSymbolAddress((void**)&wq_h, g_WqT_hi);  cudaGetSymbolAddress((void**)&wq_l, g_WqT_lo);
        cudaGetSymbolAddress((void**)&wk_h, g_WkT_hi);  cudaGetSymbolAddress((void**)&wk_l, g_WkT_lo);
        cudaGetSymbolAddress((void**)&wv_h, g_WvT_hi);  cudaGetSymbolAddress((void**)&wv_l, g_WvT_lo);
        cudaGetSymbolAddress((void**)&wo_h, g_WoT_hi);  cudaGetSymbolAddress((void**)&wo_l, g_WoT_lo);
        cudaGetSymbolAddress((void**)&w1_h, g_W1T_hi);  cudaGetSymbolAddress((void**)&w1_l, g_W1T_lo);
        cudaGetSymbolAddress((void**)&w2_h, g_W2T_hi);  cudaGetSymbolAddress((void**)&w2_l, g_W2T_lo);
        cudaFuncSetAttribute(mma_gemm<128,EPI_PLAIN>,  cudaFuncAttributeMaxDynamicSharedMemorySize, SMEM128);
        cudaFuncSetAttribute(mma_gemm<128,EPI_GELU>,   cudaFuncAttributeMaxDynamicSharedMemorySize, SMEM128);
        cudaFuncSetAttribute(mma_gemm<128,EPI_QKV>,    cudaFuncAttributeMaxDynamicSharedMemorySize, SMEM128);
        cudaFuncSetAttribute(mma_gemm<128,EPI_VT>,     cudaFuncAttributeMaxDynamicSharedMemorySize, SMEM128);
        cudaFuncSetAttribute(mma_gemm<128,EPI_SCORES>, cudaFuncAttributeMaxDynamicSharedMemorySize, SMEM128);
        cudaFuncSetAttribute(mma_gemm<64, EPI_CTX>,    cudaFuncAttributeMaxDynamicSharedMemorySize, SMEM64);
    }

    // ---- setup ----
    tsplit_k<<<dim3(HID/32, HID/32),   dim3(32,8)>>>(Wq, wq_h, wq_l, HID, HID);
    tsplit_k<<<dim3(HID/32, HID/32),   dim3(32,8)>>>(Wk, wk_h, wk_l, HID, HID);
    tsplit_k<<<dim3(HID/32, HID/32),   dim3(32,8)>>>(Wv, wv_h, wv_l, HID, HID);
    tsplit_k<<<dim3(HID/32, HID/32),   dim3(32,8)>>>(Wo, wo_h, wo_l, HID, HID);
    tsplit_k<<<dim3(FFDIM/32, HID/32), dim3(32,8)>>>(W1, w1_h, w1_l, HID, FFDIM);
    tsplit_k<<<dim3(HID/32, FFDIM/32), dim3(32,8)>>>(W2, w2_h, w2_l, FFDIM, HID);
    split_copy_k<<<(ROWS*HID+255)/256, 256>>>(emb, hid, hA_h, hA_l, ROWS*HID);
    mask_k<<<(ROWS+255)/256, 256>>>(seg, mk);
    posbias_k<<<(SEQ*SEQ+255)/256, 256>>>(rel_emb, pb);

    const long sQK = (long)SEQ*HDIM;   // 32768
    const long sSC = (long)SEQ*SEQ;    // 262144

    for (int L=0; L<NLAYERS; L++){
        // QKV projections (M=4096, N=768, K=768)
        mma_gemm<128,EPI_QKV><<<dim3(6,32,1),256,SMEM128>>>(
            hA_h,hA_l, wq_h,wq_l, HID, HID, HID, 0,0, bq, nullptr, q_h,q_l, 0, nullptr,nullptr);
        mma_gemm<128,EPI_QKV><<<dim3(6,32,1),256,SMEM128>>>(
            hA_h,hA_l, wk_h,wk_l, HID, HID, HID, 0,0, bk, nullptr, k_h,k_l, 0, nullptr,nullptr);
        mma_gemm<128,EPI_VT><<<dim3(6,32,1),256,SMEM128>>>(
            hA_h,hA_l, wv_h,wv_l, HID, HID, HID, 0,0, bv, nullptr, vt_h,vt_l, 0, nullptr,nullptr);

        // scores = Q K^T * scale + pb + mask  (96 x [512,512,64])
        mma_gemm<128,EPI_SCORES><<<dim3(4,4,NBH),256,SMEM128>>>(
            q_h,q_l, k_h,k_l, HDIM, HDIM, HDIM, sQK,sQK, nullptr, sc, nullptr,nullptr, 0, pb, mk);

        softmax_k<<<(NBH*SEQ)/8, 256>>>(sc, p_h, p_l);

        // ctx = P V  (96 x [512,64,512]) -> [B*S, 768] bf16 split
        mma_gemm<64,EPI_CTX><<<dim3(1,4,NBH),256,SMEM64>>>(
            p_h,p_l, vt_h,vt_l, SEQ, SEQ, SEQ, sSC, sQK, nullptr, nullptr, cx_h,cx_l, 0, nullptr,nullptr);

        // O projection
        mma_gemm<128,EPI_PLAIN><<<dim3(6,32,1),256,SMEM128>>>(
            cx_h,cx_l, wo_h,wo_l, HID, HID, HID, 0,0, bo, tmp, nullptr,nullptr, HID, nullptr,nullptr);
        resln_k<<<ROWS,256>>>(hid, tmp, ln1_g, ln1_b, hid, hA_h, hA_l);

        // FF1 (M=4096, N=3072, K=768) with GELU
        mma_gemm<128,EPI_GELU><<<dim3(24,32,1),256,SMEM128>>>(
            hA_h,hA_l, w1_h,w1_l, HID, HID, HID, 0,0, b1, nullptr, ff_h,ff_l, FFDIM, nullptr,nullptr);
        // FF2 (M=4096, N=768, K=3072)
        mma_gemm<128,EPI_PLAIN><<<dim3(6,32,1),256,SMEM128>>>(
            ff_h,ff_l, w2_h,w2_l, FFDIM, FFDIM, FFDIM, 0,0, b2, tmp, nullptr,nullptr, HID, nullptr,nullptr);
        resln_k<<<ROWS,256>>>(hid, tmp, ln2_g, ln2_b, (L==NLAYERS-1) ? out : hid, hA_h, hA_l);
    }
}

// round 8
// speedup vs baseline: 2.5163x; 1.2061x over previous
#include <cuda_runtime.h>
#include <cuda_bf16.h>
#include <math.h>
#include <stdint.h>

// ---------------- constants ----------------
#define BATCH   8
#define SEQ     512
#define HID     768
#define NHEADS  12
#define HDIM    64
#define FFDIM   3072
#define NLAYERS 12
#define ROWS    (BATCH*SEQ)          // 4096
#define NBH     (BATCH*NHEADS)       // 96

typedef __nv_bfloat16 bf;

// ---------------- scratch (device globals; allocation-free) ----------------
__device__ float g_hidden[ROWS*HID];
__device__ float g_tmp   [ROWS*HID];
__device__ float g_scores[(long)NBH*SEQ*SEQ];
__device__ float g_pb    [NHEADS*SEQ*SEQ];
__device__ float g_mask  [ROWS];

__device__ bf g_hidA_hi[ROWS*HID], g_hidA_lo[ROWS*HID];
__device__ bf g_q_hi [ROWS*HID], g_q_lo [ROWS*HID];   // [B,H,S,64]
__device__ bf g_k_hi [ROWS*HID], g_k_lo [ROWS*HID];   // [B,H,S,64]
__device__ bf g_vt_hi[ROWS*HID], g_vt_lo[ROWS*HID];   // [B,H,64,S]
__device__ bf g_ctx_hi[ROWS*HID], g_ctx_lo[ROWS*HID]; // [B*S,768]
__device__ bf g_ff_hi[ROWS*FFDIM], g_ff_lo[ROWS*FFDIM];
__device__ bf g_p_hi[(long)NBH*SEQ*SEQ], g_p_lo[(long)NBH*SEQ*SEQ];

__device__ bf g_WqkvT_hi[3*HID*HID], g_WqkvT_lo[3*HID*HID];  // [2304,768]
__device__ bf g_WoT_hi[HID*HID],  g_WoT_lo[HID*HID];
__device__ bf g_W1T_hi[HID*FFDIM], g_W1T_lo[HID*FFDIM]; // [3072,768]
__device__ bf g_W2T_hi[HID*FFDIM], g_W2T_lo[HID*FFDIM]; // [768,3072]

// ---------------- PTX helpers (sm_100 baseline only) ----------------
__device__ __forceinline__ uint32_t smem_u32(const void* p){
    uint32_t a;
    asm("{ .reg .u64 t; cvta.to.shared.u64 t, %1; cvt.u32.u64 %0, t; }" : "=r"(a) : "l"(p));
    return a;
}
__device__ __forceinline__ void cp16(uint32_t dst, const void* src){
    asm volatile("cp.async.cg.shared.global [%0], [%1], 16;" :: "r"(dst), "l"(src));
}
#define CP_COMMIT() asm volatile("cp.async.commit_group;" ::: "memory")
#define CP_WAIT(n)  asm volatile("cp.async.wait_group %0;" :: "n"(n) : "memory")

__device__ __forceinline__ void ldsm4(uint32_t* r, uint32_t addr){
    asm volatile("ldmatrix.sync.aligned.m8n8.x4.shared.b16 {%0,%1,%2,%3}, [%4];"
                 : "=r"(r[0]), "=r"(r[1]), "=r"(r[2]), "=r"(r[3]) : "r"(addr));
}

__device__ __forceinline__ void mma16816(float* d, const uint32_t* a,
                                         uint32_t b0, uint32_t b1){
    asm volatile(
        "mma.sync.aligned.m16n8k16.row.col.f32.bf16.bf16.f32 "
        "{%0,%1,%2,%3}, {%4,%5,%6,%7}, {%8,%9}, {%0,%1,%2,%3};"
        : "+f"(d[0]), "+f"(d[1]), "+f"(d[2]), "+f"(d[3])
        : "r"(a[0]), "r"(a[1]), "r"(a[2]), "r"(a[3]), "r"(b0), "r"(b1));
}

__device__ __forceinline__ void bsplit(float v, bf& h, bf& l){
    h = __float2bfloat16(v);
    l = __float2bfloat16(v - __bfloat162float(h));
}

// ---------------- reductions ----------------
__device__ __forceinline__ float warpSum(float v){
#pragma unroll
    for (int o=16;o>0;o>>=1) v += __shfl_xor_sync(0xffffffffu, v, o);
    return v;
}
__device__ __forceinline__ float warpMax(float v){
#pragma unroll
    for (int o=16;o>0;o>>=1) v = fmaxf(v, __shfl_xor_sync(0xffffffffu, v, o));
    return v;
}
__device__ float blockSum(float v){
    __shared__ float sh[8];
    __shared__ float total;
    int lane = threadIdx.x & 31, wid = threadIdx.x >> 5;
    v = warpSum(v);
    __syncthreads();
    if (lane == 0) sh[wid] = v;
    __syncthreads();
    if (wid == 0){
        float r = (lane < 8) ? sh[lane] : 0.f;
        r = warpSum(r);
        if (lane == 0) total = r;
    }
    __syncthreads();
    return total;
}

// ---------------- small kernels ----------------
__global__ void split_copy_k(const float* __restrict__ src, float* __restrict__ dstF,
                             bf* __restrict__ hi, bf* __restrict__ lo, int n){
    int i = blockIdx.x*blockDim.x + threadIdx.x;
    if (i >= n) return;
    float v = src[i];
    dstF[i] = v;
    bf h, l; bsplit(v, h, l);
    hi[i] = h; lo[i] = l;
}

__global__ void mask_k(const int* __restrict__ seg, float* __restrict__ mask){
    int i = blockIdx.x*blockDim.x + threadIdx.x;
    if (i < ROWS) mask[i] = (seg[i] > 0) ? 0.f : -10000.f;
}

__device__ __forceinline__ int rel_bucket(int qpos, int kpos){
    int rel = kpos - qpos;
    int off = (rel > 0) ? 16 : 0;
    int ar  = rel < 0 ? -rel : rel;
    if (ar < 8) return off + ar;
    float t = logf((float)ar / 8.0f) / 2.772588722239781f * 8.0f;
    int v = 8 + (int)t;
    if (v > 15) v = 15;
    return off + v;
}

__global__ void posbias_k(const float* __restrict__ rel_emb, float* __restrict__ pb){
    int idx = blockIdx.x*blockDim.x + threadIdx.x;
    if (idx >= SEQ*SEQ) return;
    int q = idx >> 9, k = idx & 511;
    int bkt = rel_bucket(q, k);
#pragma unroll
    for (int h=0; h<NHEADS; h++)
        pb[((long)h*SEQ + q)*SEQ + k] = rel_emb[bkt*NHEADS + h];
}

// W[K,N] fp32 -> WT hi/lo [N,K] bf16, 32x32 smem-tiled
__global__ void tsplit_k(const float* __restrict__ W,
                         bf* __restrict__ Thi, bf* __restrict__ Tlo,
                         int K, int N){
    __shared__ float t[32][33];
    int k0 = blockIdx.y*32, n0 = blockIdx.x*32;
    int x = threadIdx.x, y = threadIdx.y;
#pragma unroll
    for (int i=y; i<32; i+=8) t[i][x] = W[(long)(k0+i)*N + n0 + x];
    __syncthreads();
#pragma unroll
    for (int i=y; i<32; i+=8){
        float v = t[x][i];
        bf h, l; bsplit(v, h, l);
        long o = (long)(n0+i)*K + k0 + x;
        Thi[o] = h; Tlo[o] = l;
    }
}

__global__ void softmax_k(const float* __restrict__ scores,
                          bf* __restrict__ phi, bf* __restrict__ plo){
    int w = (blockIdx.x*blockDim.x + threadIdx.x) >> 5;
    int lane = threadIdx.x & 31;
    const float* row = scores + (long)w * SEQ;
    float v[16]; float mx = -3.0e38f;
#pragma unroll
    for (int i=0;i<16;i++){ v[i] = row[lane + 32*i]; mx = fmaxf(mx, v[i]); }
    mx = warpMax(mx);
    float s = 0.f;
#pragma unroll
    for (int i=0;i<16;i++){ v[i] = expf(v[i]-mx); s += v[i]; }
    s = warpSum(s);
    float inv = 1.f/s;
    long base = (long)w * SEQ;
#pragma unroll
    for (int i=0;i<16;i++){
        float p = v[i]*inv;
        bf h, l; bsplit(p, h, l);
        phi[base + lane + 32*i] = h;
        plo[base + lane + 32*i] = l;
    }
}

__global__ __launch_bounds__(256) void resln_k(
    const float* __restrict__ resid, const float* __restrict__ x,
    const float* __restrict__ g, const float* __restrict__ b,
    float* __restrict__ out,
    bf* __restrict__ ohi, bf* __restrict__ olo)
{
    long base = (long)blockIdx.x * HID;
    int t = threadIdx.x;
    float v[3]; float s = 0.f;
#pragma unroll
    for (int i=0;i<3;i++){ v[i] = resid[base + t + 256*i] + x[base + t + 256*i]; s += v[i]; }
    s = blockSum(s);
    float mean = s * (1.f/768.f);
    float q = 0.f;
#pragma unroll
    for (int i=0;i<3;i++){ float d = v[i]-mean; q += d*d; }
    q = blockSum(q);
    float inv = 1.f / sqrtf(q*(1.f/768.f) + 1e-6f);
#pragma unroll
    for (int i=0;i<3;i++){
        int c = t + 256*i;
        float r = g[c]*(v[i]-mean)*inv + b[c];
        out[base + c] = r;
        bf h, l; bsplit(r, h, l);
        ohi[base + c] = h; olo[base + c] = l;
    }
}

// ---------------- mma.sync GEMM (BK=64, 3-stage cp.async, ldmatrix, 512 thr) ----------------
// D[128/CTA, BN_] = Ahi*Bhi + Ahi*Blo + Alo*Bhi over K (chunks of 64)
// A: [rows,K] bf16 K-major (lda). B: [N,K] bf16 K-major (ldb).
enum { EPI_PLAIN=0, EPI_GELU=1, EPI_QKV3=2, EPI_SCORES=4, EPI_CTX=5 };

template<int BN_, int EPI>
__global__ __launch_bounds__(512,1) void mma_gemm(
    const bf* __restrict__ Ahi, const bf* __restrict__ Alo,
    const bf* __restrict__ Bhi, const bf* __restrict__ Blo,
    int K, int lda, int ldb, long sA, long sB,
    const float* __restrict__ bias, const float* __restrict__ bias2, const float* __restrict__ bias3,
    float* __restrict__ outF,
    bf* __restrict__ outHi, bf* __restrict__ outLo,
    bf* __restrict__ out2Hi, bf* __restrict__ out2Lo,
    bf* __restrict__ out3Hi, bf* __restrict__ out3Lo,
    int ldc,
    const float* __restrict__ pb, const float* __restrict__ msk)
{
    constexpr int WGN = 4;
    constexpr int WM  = 32;             // 128/4 warps in M
    constexpr int WN  = BN_ / 4;        // 32 or 16
    constexpr int MT  = 2;              // 2 m16 tiles
    constexpr int NTT = WN / 8;         // 4 or 2
    constexpr int NG  = NTT / 2 ? NTT/2 : 1; // 2 or 1
    constexpr int A_HI = 0;
    constexpr int A_LO = 128*128;          // 16384
    constexpr int B_HI = 2*128*128;        // 32768
    constexpr int B_LO = 2*128*128 + BN_*128;
    constexpr int STAGE = 2*128*128 + 2*BN_*128;  // bytes: 64K / 48K
    constexpr int TOT_ROWS = 256 + 2*BN_;

    extern __shared__ __align__(16) char smem[];
    const uint32_t sbase = smem_u32(smem);

    const int tid = threadIdx.x, lane = tid & 31, warp = tid >> 5;
    const int warpM = warp >> 2, warpN = warp & 3;
    const int z = blockIdx.z;
    const int mBase = blockIdx.y * 128, nBase = blockIdx.x * BN_;
    const bf* Ah = Ahi + (long)z * sA;
    const bf* Al = Alo + (long)z * sA;
    const bf* Bh = Bhi + (long)z * sB;
    const bf* Bl = Blo + (long)z * sB;

    auto issue = [&](int c){
        const int s = c % 3, k0 = c << 6;
        const uint32_t segbase = sbase + (uint32_t)(s * STAGE);
#pragma unroll 2
        for (int ci = tid; ci < TOT_ROWS*8; ci += 512){
            int r = ci >> 3, c16 = ci & 7;
            const bf* src; uint32_t toff; int rr;
            if (r < 128)          { rr = r;         src = Ah + (long)(mBase+rr)*lda + k0; toff = A_HI; }
            else if (r < 256)     { rr = r-128;     src = Al + (long)(mBase+rr)*lda + k0; toff = A_LO; }
            else if (r < 256+BN_) { rr = r-256;     src = Bh + (long)(nBase+rr)*ldb + k0; toff = B_HI; }
            else                  { rr = r-256-BN_; src = Bl + (long)(nBase+rr)*ldb + k0; toff = B_LO; }
            uint32_t dst = segbase + toff + (uint32_t)(rr*128) + (uint32_t)((c16*16) ^ ((rr&7)<<4));
            cp16(dst, src + c16*8);
        }
        CP_COMMIT();
    };

    float acc[MT][NTT][4];
#pragma unroll
    for (int i=0;i<MT;i++)
#pragma unroll
        for (int j=0;j<NTT;j++)
#pragma unroll
            for (int e=0;e<4;e++) acc[i][j][e] = 0.f;

    // per-lane ldmatrix row/col decomposition
    const int lt  = lane >> 3;
    const int lrow = ((lt & 1) << 3) + (lane & 7);
    const int lcol = (lt >> 1) << 4;

    const int CH = K >> 6;
    issue(0);
    if (CH > 1) issue(1);

    for (int c = 0; c < CH; ++c){
        if (c + 1 < CH) { CP_WAIT(1); } else { CP_WAIT(0); }
        __syncthreads();
        if (c + 2 < CH) issue(c + 2);

        const uint32_t st = sbase + (uint32_t)((c % 3) * STAGE);
#pragma unroll
        for (int kk = 0; kk < 4; ++kk){
            const uint32_t kb = (uint32_t)(kk << 5);
            uint32_t ah[MT][4], al[MT][4];
#pragma unroll
            for (int mt = 0; mt < MT; ++mt){
                int r = warpM*WM + mt*16 + lrow;
                uint32_t cb = (kb + lcol) ^ ((uint32_t)(r&7) << 4);
                ldsm4(ah[mt], st + A_HI + r*128 + cb);
                ldsm4(al[mt], st + A_LO + r*128 + cb);
            }
            uint32_t bh[NG][4], bl[NG][4];
#pragma unroll
            for (int g = 0; g < NG; ++g){
                int r = warpN*WN + g*16 + lrow;
                uint32_t cb = (kb + lcol) ^ ((uint32_t)(r&7) << 4);
                ldsm4(bh[g], st + B_HI + r*128 + cb);
                ldsm4(bl[g], st + B_LO + r*128 + cb);
            }
#pragma unroll
            for (int mt = 0; mt < MT; ++mt)
#pragma unroll
                for (int nt = 0; nt < NTT; ++nt){
                    int g = nt >> 1, sH = nt & 1;
                    mma16816(acc[mt][nt], ah[mt], bh[g][sH], bh[g][sH+2]);
                    mma16816(acc[mt][nt], ah[mt], bl[g][sH], bl[g][sH+2]);
                    mma16816(acc[mt][nt], al[mt], bh[g][sH], bh[g][sH+2]);
                }
        }
    }
    __syncthreads();

    // ---------------- epilogue: stage D via padded smem ----------------
    float* sD = (float*)smem;
    constexpr int LDD = BN_ + 1;
#pragma unroll
    for (int mt = 0; mt < MT; ++mt)
#pragma unroll
        for (int nt = 0; nt < NTT; ++nt){
            int r0 = warpM*WM + mt*16 + (lane >> 2);
            int c0 = warpN*WN + nt*8 + (lane & 3)*2;
            sD[r0*LDD + c0]       = acc[mt][nt][0];
            sD[r0*LDD + c0 + 1]   = acc[mt][nt][1];
            sD[(r0+8)*LDD + c0]   = acc[mt][nt][2];
            sD[(r0+8)*LDD + c0+1] = acc[mt][nt][3];
        }
    __syncthreads();

    if (EPI == EPI_QKV3){
        // which 768-section does this 128-wide tile belong to? (tiles never straddle)
        const int which = nBase / HID;          // 0=Q, 1=K, 2=V
        const int nloc0 = nBase - which*HID;    // 0..640
        const float* bs = (which==0) ? bias : (which==1) ? bias2 : bias3;
        bf* oHi = (which==0) ? outHi : (which==1) ? out2Hi : out3Hi;
        bf* oLo = (which==0) ? outLo : (which==1) ? out2Lo : out3Lo;
        if (which < 2){
            // Q/K scatter [B,H,S,64], vectorized 4-wide within head
            for (int t = tid; t < 128*32; t += 512){
                int m = t >> 5, nq = t & 31;
                int nl = nloc0 + nq*4;
                int mg = mBase + m, b_ = mg >> 9, sidx = mg & 511;
                int h = nl >> 6, dd = nl & 63;
                float e[4];
#pragma unroll
                for (int j=0;j<4;j++) e[j] = sD[m*LDD + nq*4 + j] + bs[nl+j];
                bf h0,h1,h2,h3,l0,l1,l2,l3;
                bsplit(e[0],h0,l0); bsplit(e[1],h1,l1);
                bsplit(e[2],h2,l2); bsplit(e[3],h3,l3);
                long idx = ((long)(b_*NHEADS + h)*SEQ + sidx)*HDIM + dd;
                *(__nv_bfloat162*)&oHi[idx]   = __nv_bfloat162(h0,h1);
                *(__nv_bfloat162*)&oHi[idx+2] = __nv_bfloat162(h2,h3);
                *(__nv_bfloat162*)&oLo[idx]   = __nv_bfloat162(l0,l1);
                *(__nv_bfloat162*)&oLo[idx+2] = __nv_bfloat162(l2,l3);
            }
        } else {
            // V^T scatter [B,H,64,S]
            for (int t = tid; t < 128*128; t += 512){
                int m = t & 127, n = t >> 7;
                int nl = nloc0 + n, h = nl >> 6, dd = nl & 63;
                int mg = mBase + m, b_ = mg >> 9, sidx = mg & 511;
                float v = sD[m*LDD + n] + bs[nl];
                bf hh, ll; bsplit(v, hh, ll);
                long idx = ((long)(b_*NHEADS + h)*HDIM + dd)*SEQ + sidx;
                oHi[idx] = hh; oLo[idx] = ll;
            }
        }
    } else {
        constexpr int NQ = BN_ / 4;
        for (int t = tid; t < 128*NQ; t += 512){
            int m = t / NQ, nq = t % NQ;
            int n0 = nBase + nq*4;
            int mg = mBase + m;
            float e[4];
#pragma unroll
            for (int j=0;j<4;j++) e[j] = sD[m*LDD + nq*4 + j];
            if (EPI == EPI_PLAIN){
#pragma unroll
                for (int j=0;j<4;j++) e[j] += bias[n0+j];
                float4 v = {e[0],e[1],e[2],e[3]};
                *(float4*)&outF[(long)mg*ldc + n0] = v;
            } else if (EPI == EPI_SCORES){
                int b_ = z / NHEADS, h = z % NHEADS;
                float4 pbv = *(const float4*)&pb[((long)h*SEQ + mg)*SEQ + n0];
                float4 mkv = *(const float4*)&msk[b_*SEQ + n0];
                float4 v;
                v.x = e[0]*0.125f + pbv.x + mkv.x;
                v.y = e[1]*0.125f + pbv.y + mkv.y;
                v.z = e[2]*0.125f + pbv.z + mkv.z;
                v.w = e[3]*0.125f + pbv.w + mkv.w;
                *(float4*)&outF[(long)z*SEQ*SEQ + (long)mg*SEQ + n0] = v;
            } else {
                if (EPI == EPI_GELU){
#pragma unroll
                    for (int j=0;j<4;j++){
                        float t2 = e[j] + bias[n0+j];
                        e[j] = 0.5f*t2*(1.f + erff(t2*0.70710678118654752f));
                    }
                }
                bf h0,h1,h2,h3,l0,l1,l2,l3;
                bsplit(e[0],h0,l0); bsplit(e[1],h1,l1);
                bsplit(e[2],h2,l2); bsplit(e[3],h3,l3);
                long idx;
                if (EPI == EPI_GELU){
                    idx = (long)mg*ldc + n0;
                } else { // EPI_CTX
                    int b_ = z / NHEADS, h = z % NHEADS;
                    idx = ((long)(b_*SEQ + mg))*HID + h*HDIM + n0;
                }
                *(__nv_bfloat162*)&outHi[idx]   = __nv_bfloat162(h0,h1);
                *(__nv_bfloat162*)&outHi[idx+2] = __nv_bfloat162(h2,h3);
                *(__nv_bfloat162*)&outLo[idx]   = __nv_bfloat162(l0,l1);
                *(__nv_bfloat162*)&outLo[idx+2] = __nv_bfloat162(l2,l3);
            }
        }
    }
}

// ---------------- host ----------------
#define SMEM128 196608   // 3 stages * 64KB  (>= 128*129*4 = 66048 epilogue)
#define SMEM64  147456   // 3 stages * 48KB

extern "C" void kernel_launch(void* const* d_in, const int* in_sizes, int n_in,
                              void* d_out, int out_size)
{
    const float* emb     = (const float*)d_in[0];
    const int*   seg     = (const int*)  d_in[1];
    const float* rel_emb = (const float*)d_in[2];
    const float* Wq = (const float*)d_in[3];  const float* bq = (const float*)d_in[4];
    const float* Wk = (const float*)d_in[5];  const float* bk = (const float*)d_in[6];
    const float* Wv = (const float*)d_in[7];  const float* bv = (const float*)d_in[8];
    const float* Wo = (const float*)d_in[9];  const float* bo = (const float*)d_in[10];
    const float* ln1_g = (const float*)d_in[11]; const float* ln1_b = (const float*)d_in[12];
    const float* W1 = (const float*)d_in[13]; const float* b1 = (const float*)d_in[14];
    const float* W2 = (const float*)d_in[15]; const float* b2 = (const float*)d_in[16];
    const float* ln2_g = (const float*)d_in[17]; const float* ln2_b = (const float*)d_in[18];
    float* out = (float*)d_out;

    static bool inited = false;
    static float *hid, *tmp, *sc, *pb, *mk;
    static bf *hA_h,*hA_l,*q_h,*q_l,*k_h,*k_l,*vt_h,*vt_l,*cx_h,*cx_l,*ff_h,*ff_l,*p_h,*p_l;
    static bf *wqkv_h,*wqkv_l,*wo_h,*wo_l,*w1_h,*w1_l,*w2_h,*w2_l;
    if (!inited){
        inited = true;
        cudaGetSymbolAddress((void**)&hid, g_hidden);
        cudaGetSymbolAddress((void**)&tmp, g_tmp);
        cudaGetSymbolAddress((void**)&sc,  g_scores);
        cudaGetSymbolAddress((void**)&pb,  g_pb);
        cudaGetSymbolAddress((void**)&mk,  g_mask);
        cudaGetSymbolAddress((void**)&hA_h, g_hidA_hi); cudaGetSymbolAddress((void**)&hA_l, g_hidA_lo);
        cudaGetSymbolAddress((void**)&q_h,  g_q_hi);    cudaGetSymbolAddress((void**)&q_l,  g_q_lo);
        cudaGetSymbolAddress((void**)&k_h,  g_k_hi);    cudaGetSymbolAddress((void**)&k_l,  g_k_lo);
        cudaGetSymbolAddress((void**)&vt_h, g_vt_hi);   cudaGetSymbolAddress((void**)&vt_l, g_vt_lo);
        cudaGetSymbolAddress((void**)&cx_h, g_ctx_hi);  cudaGetSymbolAddress((void**)&cx_l, g_ctx_lo);
        cudaGetSymbolAddress((void**)&ff_h, g_ff_hi);   cudaGetSymbolAddress((void**)&ff_l, g_ff_lo);
        cudaGetSymbolAddress((void**)&p_h,  g_p_hi);    cudaGetSymbolAddress((void**)&p_l,  g_p_lo);
        cudaGetSymbolAddress((void**)&wqkv_h, g_WqkvT_hi); cudaGetSymbolAddress((void**)&wqkv_l, g_WqkvT_lo);
        cudaGetSymbolAddress((void**)&wo_h, g_WoT_hi);  cudaGetSymbolAddress((void**)&wo_l, g_WoT_lo);
        cudaGetSymbolAddress((void**)&w1_h, g_W1T_hi);  cudaGetSymbolAddress((void**)&w1_l, g_W1T_lo);
        cudaGetSymbolAddress((void**)&w2_h, g_W2T_hi);  cudaGetSymbolAddress((void**)&w2_l, g_W2T_lo);
        cudaFuncSetAttribute(mma_gemm<128,EPI_PLAIN>,  cudaFuncAttributeMaxDynamicSharedMemorySize, SMEM128);
        cudaFuncSetAttribute(mma_gemm<128,EPI_GELU>,   cudaFuncAttributeMaxDynamicSharedMemorySize, SMEM128);
        cudaFuncSetAttribute(mma_gemm<128,EPI_QKV3>,   cudaFuncAttributeMaxDynamicSharedMemorySize, SMEM128);
        cudaFuncSetAttribute(mma_gemm<128,EPI_SCORES>, cudaFuncAttributeMaxDynamicSharedMemorySize, SMEM128);
        cudaFuncSetAttribute(mma_gemm<64, EPI_CTX>,    cudaFuncAttributeMaxDynamicSharedMemorySize, SMEM64);
    }

    // ---- setup ----
    tsplit_k<<<dim3(HID/32, HID/32),   dim3(32,8)>>>(Wq, wqkv_h,            wqkv_l,            HID, HID);
    tsplit_k<<<dim3(HID/32, HID/32),   dim3(32,8)>>>(Wk, wqkv_h + HID*HID,  wqkv_l + HID*HID,  HID, HID);
    tsplit_k<<<dim3(HID/32, HID/32),   dim3(32,8)>>>(Wv, wqkv_h + 2*HID*HID,wqkv_l + 2*HID*HID,HID, HID);
    tsplit_k<<<dim3(HID/32, HID/32),   dim3(32,8)>>>(Wo, wo_h, wo_l, HID, HID);
    tsplit_k<<<dim3(FFDIM/32, HID/32), dim3(32,8)>>>(W1, w1_h, w1_l, HID, FFDIM);
    tsplit_k<<<dim3(HID/32, FFDIM/32), dim3(32,8)>>>(W2, w2_h, w2_l, FFDIM, HID);
    split_copy_k<<<(ROWS*HID+255)/256, 256>>>(emb, hid, hA_h, hA_l, ROWS*HID);
    mask_k<<<(ROWS+255)/256, 256>>>(seg, mk);
    posbias_k<<<(SEQ*SEQ+255)/256, 256>>>(rel_emb, pb);

    const long sQK = (long)SEQ*HDIM;   // 32768
    const long sSC = (long)SEQ*SEQ;    // 262144

    for (int L=0; L<NLAYERS; L++){
        // fused QKV projection (M=4096, N=2304, K=768)
        mma_gemm<128,EPI_QKV3><<<dim3(18,32,1),512,SMEM128>>>(
            hA_h,hA_l, wqkv_h,wqkv_l, HID, HID, HID, 0,0,
            bq, bk, bv, nullptr, q_h,q_l, k_h,k_l, vt_h,vt_l, 0, nullptr,nullptr);

        // scores = Q K^T * scale + pb + mask  (96 x [512,512,64])
        mma_gemm<128,EPI_SCORES><<<dim3(4,4,NBH),512,SMEM128>>>(
            q_h,q_l, k_h,k_l, HDIM, HDIM, HDIM, sQK,sQK,
            nullptr,nullptr,nullptr, sc, nullptr,nullptr, nullptr,nullptr, nullptr,nullptr, 0, pb, mk);

        softmax_k<<<(NBH*SEQ)/8, 256>>>(sc, p_h, p_l);

        // ctx = P V  (96 x [512,64,512]) -> [B*S, 768] bf16 split
        mma_gemm<64,EPI_CTX><<<dim3(1,4,NBH),512,SMEM64>>>(
            p_h,p_l, vt_h,vt_l, SEQ, SEQ, SEQ, sSC, sQK,
            nullptr,nullptr,nullptr, nullptr, cx_h,cx_l, nullptr,nullptr, nullptr,nullptr, 0, nullptr,nullptr);

        // O projection
        mma_gemm<128,EPI_PLAIN><<<dim3(6,32,1),512,SMEM128>>>(
            cx_h,cx_l, wo_h,wo_l, HID, HID, HID, 0,0,
            bo,nullptr,nullptr, tmp, nullptr,nullptr, nullptr,nullptr, nullptr,nullptr, HID, nullptr,nullptr);
        resln_k<<<ROWS,256>>>(hid, tmp, ln1_g, ln1_b, hid, hA_h, hA_l);

        // FF1 (M=4096, N=3072, K=768) with GELU
        mma_gemm<128,EPI_GELU><<<dim3(24,32,1),512,SMEM128>>>(
            hA_h,hA_l, w1_h,w1_l, HID, HID, HID, 0,0,
            b1,nullptr,nullptr, nullptr, ff_h,ff_l, nullptr,nullptr, nullptr,nullptr, FFDIM, nullptr,nullptr);
        // FF2 (M=4096, N=768, K=3072)
        mma_gemm<128,EPI_PLAIN><<<dim3(6,32,1),512,SMEM128>>>(
            ff_h,ff_l, w2_h,w2_l, FFDIM, FFDIM, FFDIM, 0,0,
            b2,nullptr,nullptr, tmp, nullptr,nullptr, nullptr,nullptr, nullptr,nullptr, HID, nullptr,nullptr);
        resln_k<<<ROWS,256>>>(hid, tmp, ln2_g, ln2_b, (L==NLAYERS-1) ? out : hid, hA_h, hA_l);
    }
}

// round 9
// speedup vs baseline: 2.6182x; 1.0405x over previous
#include <cuda_runtime.h>
#include <cuda_bf16.h>
#include <math.h>
#include <stdint.h>

// ---------------- constants ----------------
#define BATCH   8
#define SEQ     512
#define HID     768
#define NHEADS  12
#define HDIM    64
#define FFDIM   3072
#define NLAYERS 12
#define ROWS    (BATCH*SEQ)          // 4096
#define NBH     (BATCH*NHEADS)       // 96

typedef __nv_bfloat16 bf;

// ---------------- scratch (device globals; allocation-free) ----------------
__device__ float g_hidden[ROWS*HID];
__device__ float g_tmp   [ROWS*HID];
__device__ float g_scores[(long)NBH*SEQ*SEQ];
__device__ float g_pb    [NHEADS*SEQ*SEQ];
__device__ float g_mask  [ROWS];

__device__ bf g_hidA_hi[ROWS*HID], g_hidA_lo[ROWS*HID];
__device__ bf g_q_hi [ROWS*HID], g_q_lo [ROWS*HID];   // [B,H,S,64]
__device__ bf g_k_hi [ROWS*HID], g_k_lo [ROWS*HID];   // [B,H,S,64]
__device__ bf g_vt_hi[ROWS*HID], g_vt_lo[ROWS*HID];   // [B,H,64,S]
__device__ bf g_ctx_hi[ROWS*HID], g_ctx_lo[ROWS*HID]; // [B*S,768]
__device__ bf g_ff_hi[ROWS*FFDIM], g_ff_lo[ROWS*FFDIM];
__device__ bf g_p_hi[(long)NBH*SEQ*SEQ], g_p_lo[(long)NBH*SEQ*SEQ];

__device__ bf g_WqkvT_hi[3*HID*HID], g_WqkvT_lo[3*HID*HID];  // [2304,768]
__device__ bf g_WoT_hi[HID*HID],  g_WoT_lo[HID*HID];
__device__ bf g_W1T_hi[HID*FFDIM], g_W1T_lo[HID*FFDIM]; // [3072,768]
__device__ bf g_W2T_hi[HID*FFDIM], g_W2T_lo[HID*FFDIM]; // [768,3072]

// ---------------- PTX helpers (sm_100 baseline only) ----------------
__device__ __forceinline__ uint32_t smem_u32(const void* p){
    uint32_t a;
    asm("{ .reg .u64 t; cvta.to.shared.u64 t, %1; cvt.u32.u64 %0, t; }" : "=r"(a) : "l"(p));
    return a;
}
__device__ __forceinline__ void cp16(uint32_t dst, const void* src){
    asm volatile("cp.async.cg.shared.global [%0], [%1], 16;" :: "r"(dst), "l"(src));
}
#define CP_COMMIT() asm volatile("cp.async.commit_group;" ::: "memory")
#define CP_WAIT(n)  asm volatile("cp.async.wait_group %0;" :: "n"(n) : "memory")

__device__ __forceinline__ void ldsm4(uint32_t* r, uint32_t addr){
    asm volatile("ldmatrix.sync.aligned.m8n8.x4.shared.b16 {%0,%1,%2,%3}, [%4];"
                 : "=r"(r[0]), "=r"(r[1]), "=r"(r[2]), "=r"(r[3]) : "r"(addr));
}

__device__ __forceinline__ void mma16816(float* d, const uint32_t* a,
                                         uint32_t b0, uint32_t b1){
    asm volatile(
        "mma.sync.aligned.m16n8k16.row.col.f32.bf16.bf16.f32 "
        "{%0,%1,%2,%3}, {%4,%5,%6,%7}, {%8,%9}, {%0,%1,%2,%3};"
        : "+f"(d[0]), "+f"(d[1]), "+f"(d[2]), "+f"(d[3])
        : "r"(a[0]), "r"(a[1]), "r"(a[2]), "r"(a[3]), "r"(b0), "r"(b1));
}

__device__ __forceinline__ void bsplit(float v, bf& h, bf& l){
    h = __float2bfloat16(v);
    l = __float2bfloat16(v - __bfloat162float(h));
}

// ---------------- reductions ----------------
__device__ __forceinline__ float warpSum(float v){
#pragma unroll
    for (int o=16;o>0;o>>=1) v += __shfl_xor_sync(0xffffffffu, v, o);
    return v;
}
__device__ __forceinline__ float warpMax(float v){
#pragma unroll
    for (int o=16;o>0;o>>=1) v = fmaxf(v, __shfl_xor_sync(0xffffffffu, v, o));
    return v;
}
__device__ float blockSum(float v){
    __shared__ float sh[8];
    __shared__ float total;
    int lane = threadIdx.x & 31, wid = threadIdx.x >> 5;
    v = warpSum(v);
    __syncthreads();
    if (lane == 0) sh[wid] = v;
    __syncthreads();
    if (wid == 0){
        float r = (lane < 8) ? sh[lane] : 0.f;
        r = warpSum(r);
        if (lane == 0) total = r;
    }
    __syncthreads();
    return total;
}

// ---------------- small kernels ----------------
__global__ void split_copy_k(const float* __restrict__ src, float* __restrict__ dstF,
                             bf* __restrict__ hi, bf* __restrict__ lo, int n){
    int i = blockIdx.x*blockDim.x + threadIdx.x;
    if (i >= n) return;
    float v = src[i];
    dstF[i] = v;
    bf h, l; bsplit(v, h, l);
    hi[i] = h; lo[i] = l;
}

__global__ void mask_k(const int* __restrict__ seg, float* __restrict__ mask){
    int i = blockIdx.x*blockDim.x + threadIdx.x;
    if (i < ROWS) mask[i] = (seg[i] > 0) ? 0.f : -10000.f;
}

__device__ __forceinline__ int rel_bucket(int qpos, int kpos){
    int rel = kpos - qpos;
    int off = (rel > 0) ? 16 : 0;
    int ar  = rel < 0 ? -rel : rel;
    if (ar < 8) return off + ar;
    float t = logf((float)ar / 8.0f) / 2.772588722239781f * 8.0f;
    int v = 8 + (int)t;
    if (v > 15) v = 15;
    return off + v;
}

__global__ void posbias_k(const float* __restrict__ rel_emb, float* __restrict__ pb){
    int idx = blockIdx.x*blockDim.x + threadIdx.x;
    if (idx >= SEQ*SEQ) return;
    int q = idx >> 9, k = idx & 511;
    int bkt = rel_bucket(q, k);
#pragma unroll
    for (int h=0; h<NHEADS; h++)
        pb[((long)h*SEQ + q)*SEQ + k] = rel_emb[bkt*NHEADS + h];
}

// W[K,N] fp32 -> WT hi/lo [N,K] bf16, 32x32 smem-tiled
__global__ void tsplit_k(const float* __restrict__ W,
                         bf* __restrict__ Thi, bf* __restrict__ Tlo,
                         int K, int N){
    __shared__ float t[32][33];
    int k0 = blockIdx.y*32, n0 = blockIdx.x*32;
    int x = threadIdx.x, y = threadIdx.y;
#pragma unroll
    for (int i=y; i<32; i+=8) t[i][x] = W[(long)(k0+i)*N + n0 + x];
    __syncthreads();
#pragma unroll
    for (int i=y; i<32; i+=8){
        float v = t[x][i];
        bf h, l; bsplit(v, h, l);
        long o = (long)(n0+i)*K + k0 + x;
        Thi[o] = h; Tlo[o] = l;
    }
}

__global__ void softmax_k(const float* __restrict__ scores,
                          bf* __restrict__ phi, bf* __restrict__ plo){
    int w = (blockIdx.x*blockDim.x + threadIdx.x) >> 5;
    int lane = threadIdx.x & 31;
    const float* row = scores + (long)w * SEQ;
    float v[16]; float mx = -3.0e38f;
#pragma unroll
    for (int i=0;i<16;i++){ v[i] = row[lane + 32*i]; mx = fmaxf(mx, v[i]); }
    mx = warpMax(mx);
    float s = 0.f;
#pragma unroll
    for (int i=0;i<16;i++){ v[i] = expf(v[i]-mx); s += v[i]; }
    s = warpSum(s);
    float inv = 1.f/s;
    long base = (long)w * SEQ;
#pragma unroll
    for (int i=0;i<16;i++){
        float p = v[i]*inv;
        bf h, l; bsplit(p, h, l);
        phi[base + lane + 32*i] = h;
        plo[base + lane + 32*i] = l;
    }
}

__global__ __launch_bounds__(256) void resln_k(
    const float* __restrict__ resid, const float* __restrict__ x,
    const float* __restrict__ g, const float* __restrict__ b,
    float* __restrict__ out,
    bf* __restrict__ ohi, bf* __restrict__ olo)
{
    long base = (long)blockIdx.x * HID;
    int t = threadIdx.x;
    float v[3]; float s = 0.f;
#pragma unroll
    for (int i=0;i<3;i++){ v[i] = resid[base + t + 256*i] + x[base + t + 256*i]; s += v[i]; }
    s = blockSum(s);
    float mean = s * (1.f/768.f);
    float q = 0.f;
#pragma unroll
    for (int i=0;i<3;i++){ float d = v[i]-mean; q += d*d; }
    q = blockSum(q);
    float inv = 1.f / sqrtf(q*(1.f/768.f) + 1e-6f);
#pragma unroll
    for (int i=0;i<3;i++){
        int c = t + 256*i;
        float r = g[c]*(v[i]-mean)*inv + b[c];
        out[base + c] = r;
        bf h, l; bsplit(r, h, l);
        ohi[base + c] = h; olo[base + c] = l;
    }
}

// ---------------- mma.sync GEMM (BK=64, 3-stage cp.async, ldmatrix, 512 thr) ----------------
// D[BM_/CTA, BN_] = Ahi*Bhi + Ahi*Blo + Alo*Bhi over K (chunks of 64)
// A: [rows,K] bf16 K-major (lda). B: [N,K] bf16 K-major (ldb).
enum { EPI_PLAIN=0, EPI_GELU=1, EPI_QKV3=2, EPI_SCORES=4, EPI_CTX=5 };

template<int BM_, int BN_, int EPI>
__global__ __launch_bounds__(512,1) void mma_gemm(
    const bf* __restrict__ Ahi, const bf* __restrict__ Alo,
    const bf* __restrict__ Bhi, const bf* __restrict__ Blo,
    int K, int lda, int ldb, long sA, long sB,
    const float* __restrict__ bias, const float* __restrict__ bias2, const float* __restrict__ bias3,
    float* __restrict__ outF,
    bf* __restrict__ outHi, bf* __restrict__ outLo,
    bf* __restrict__ out2Hi, bf* __restrict__ out2Lo,
    bf* __restrict__ out3Hi, bf* __restrict__ out3Lo,
    int ldc,
    const float* __restrict__ pb, const float* __restrict__ msk)
{
    constexpr int WGM = BM_ / 32;           // 4 or 2
    constexpr int WGN = 16 / WGM;           // 4 or 8
    constexpr int WM  = 32;
    constexpr int WN  = BN_ / WGN;          // 32 or 16
    constexpr int MT  = 2;
    constexpr int NTT = WN / 8;             // 4 or 2
    constexpr int NG  = (NTT/2 > 0) ? NTT/2 : 1;
    constexpr int A_HI = 0;
    constexpr int A_LO = BM_*128;
    constexpr int B_HI = 2*BM_*128;
    constexpr int B_LO = 2*BM_*128 + BN_*128;
    constexpr int STAGE = 2*BM_*128 + 2*BN_*128;  // bytes
    constexpr int TOT_ROWS = 2*BM_ + 2*BN_;

    extern __shared__ __align__(16) char smem[];
    const uint32_t sbase = smem_u32(smem);

    const int tid = threadIdx.x, lane = tid & 31, warp = tid >> 5;
    const int warpM = warp / WGN, warpN = warp % WGN;
    const int z = blockIdx.z;
    const int mBase = blockIdx.y * BM_, nBase = blockIdx.x * BN_;
    const bf* Ah = Ahi + (long)z * sA;
    const bf* Al = Alo + (long)z * sA;
    const bf* Bh = Bhi + (long)z * sB;
    const bf* Bl = Blo + (long)z * sB;

    auto issue = [&](int c){
        const int s = c % 3, k0 = c << 6;
        const uint32_t segbase = sbase + (uint32_t)(s * STAGE);
#pragma unroll 2
        for (int ci = tid; ci < TOT_ROWS*8; ci += 512){
            int r = ci >> 3, c16 = ci & 7;
            const bf* src; uint32_t toff; int rr;
            if (r < BM_)            { rr = r;          src = Ah + (long)(mBase+rr)*lda + k0; toff = A_HI; }
            else if (r < 2*BM_)     { rr = r-BM_;      src = Al + (long)(mBase+rr)*lda + k0; toff = A_LO; }
            else if (r < 2*BM_+BN_) { rr = r-2*BM_;    src = Bh + (long)(nBase+rr)*ldb + k0; toff = B_HI; }
            else                    { rr = r-2*BM_-BN_;src = Bl + (long)(nBase+rr)*ldb + k0; toff = B_LO; }
            uint32_t dst = segbase + toff + (uint32_t)(rr*128) + (uint32_t)((c16*16) ^ ((rr&7)<<4));
            cp16(dst, src + c16*8);
        }
        CP_COMMIT();
    };

    float acc[MT][NTT][4];
#pragma unroll
    for (int i=0;i<MT;i++)
#pragma unroll
        for (int j=0;j<NTT;j++)
#pragma unroll
            for (int e=0;e<4;e++) acc[i][j][e] = 0.f;

    // per-lane ldmatrix row/col decomposition
    const int lt  = lane >> 3;
    const int lrow = ((lt & 1) << 3) + (lane & 7);
    const int lcol = (lt >> 1) << 4;

    const int CH = K >> 6;
    issue(0);
    if (CH > 1) issue(1);

    for (int c = 0; c < CH; ++c){
        if (c + 1 < CH) { CP_WAIT(1); } else { CP_WAIT(0); }
        __syncthreads();
        if (c + 2 < CH) issue(c + 2);

        const uint32_t st = sbase + (uint32_t)((c % 3) * STAGE);
#pragma unroll
        for (int kk = 0; kk < 4; ++kk){
            const uint32_t kb = (uint32_t)(kk << 5);
            uint32_t ah[MT][4], al[MT][4];
#pragma unroll
            for (int mt = 0; mt < MT; ++mt){
                int r = warpM*WM + mt*16 + lrow;
                uint32_t cb = (kb + lcol) ^ ((uint32_t)(r&7) << 4);
                ldsm4(ah[mt], st + A_HI + r*128 + cb);
                ldsm4(al[mt], st + A_LO + r*128 + cb);
            }
            uint32_t bh[NG][4], bl[NG][4];
#pragma unroll
            for (int g = 0; g < NG; ++g){
                int r = warpN*WN + g*16 + lrow;
                uint32_t cb = (kb + lcol) ^ ((uint32_t)(r&7) << 4);
                ldsm4(bh[g], st + B_HI + r*128 + cb);
                ldsm4(bl[g], st + B_LO + r*128 + cb);
            }
#pragma unroll
            for (int mt = 0; mt < MT; ++mt)
#pragma unroll
                for (int nt = 0; nt < NTT; ++nt){
                    int g = nt >> 1, sH = nt & 1;
                    mma16816(acc[mt][nt], ah[mt], bh[g][sH], bh[g][sH+2]);
                    mma16816(acc[mt][nt], ah[mt], bl[g][sH], bl[g][sH+2]);
                    mma16816(acc[mt][nt], al[mt], bh[g][sH], bh[g][sH+2]);
                }
        }
    }
    __syncthreads();

    // ---------------- epilogue: stage D via padded smem ----------------
    float* sD = (float*)smem;
    constexpr int LDD = BN_ + 1;
#pragma unroll
    for (int mt = 0; mt < MT; ++mt)
#pragma unroll
        for (int nt = 0; nt < NTT; ++nt){
            int r0 = warpM*WM + mt*16 + (lane >> 2);
            int c0 = warpN*WN + nt*8 + (lane & 3)*2;
            sD[r0*LDD + c0]       = acc[mt][nt][0];
            sD[r0*LDD + c0 + 1]   = acc[mt][nt][1];
            sD[(r0+8)*LDD + c0]   = acc[mt][nt][2];
            sD[(r0+8)*LDD + c0+1] = acc[mt][nt][3];
        }
    __syncthreads();

    if (EPI == EPI_QKV3){
        // which 768-section does this 128-wide tile belong to? (tiles never straddle)
        const int which = nBase / HID;          // 0=Q, 1=K, 2=V
        const int nloc0 = nBase - which*HID;    // 0..640
        const float* bs = (which==0) ? bias : (which==1) ? bias2 : bias3;
        bf* oHi = (which==0) ? outHi : (which==1) ? out2Hi : out3Hi;
        bf* oLo = (which==0) ? outLo : (which==1) ? out2Lo : out3Lo;
        if (which < 2){
            // Q/K scatter [B,H,S,64], vectorized 4-wide within head
            for (int t = tid; t < BM_*32; t += 512){
                int m = t >> 5, nq = t & 31;
                int nl = nloc0 + nq*4;
                int mg = mBase + m, b_ = mg >> 9, sidx = mg & 511;
                int h = nl >> 6, dd = nl & 63;
                float e[4];
#pragma unroll
                for (int j=0;j<4;j++) e[j] = sD[m*LDD + nq*4 + j] + bs[nl+j];
                bf h0,h1,h2,h3,l0,l1,l2,l3;
                bsplit(e[0],h0,l0); bsplit(e[1],h1,l1);
                bsplit(e[2],h2,l2); bsplit(e[3],h3,l3);
                long idx = ((long)(b_*NHEADS + h)*SEQ + sidx)*HDIM + dd;
                *(__nv_bfloat162*)&oHi[idx]   = __nv_bfloat162(h0,h1);
                *(__nv_bfloat162*)&oHi[idx+2] = __nv_bfloat162(h2,h3);
                *(__nv_bfloat162*)&oLo[idx]   = __nv_bfloat162(l0,l1);
                *(__nv_bfloat162*)&oLo[idx+2] = __nv_bfloat162(l2,l3);
            }
        } else {
            // V^T scatter [B,H,64,S]
            for (int t = tid; t < BM_*128; t += 512){
                int m = t & (BM_-1), n = t / BM_;
                int nl = nloc0 + n, h = nl >> 6, dd = nl & 63;
                int mg = mBase + m, b_ = mg >> 9, sidx = mg & 511;
                float v = sD[m*LDD + n] + bs[nl];
                bf hh, ll; bsplit(v, hh, ll);
                long idx = ((long)(b_*NHEADS + h)*HDIM + dd)*SEQ + sidx;
                oHi[idx] = hh; oLo[idx] = ll;
            }
        }
    } else {
        constexpr int NQ = BN_ / 4;
        for (int t = tid; t < BM_*NQ; t += 512){
            int m = t / NQ, nq = t % NQ;
            int n0 = nBase + nq*4;
            int mg = mBase + m;
            float e[4];
#pragma unroll
            for (int j=0;j<4;j++) e[j] = sD[m*LDD + nq*4 + j];
            if (EPI == EPI_PLAIN){
#pragma unroll
                for (int j=0;j<4;j++) e[j] += bias[n0+j];
                float4 v = {e[0],e[1],e[2],e[3]};
                *(float4*)&outF[(long)mg*ldc + n0] = v;
            } else if (EPI == EPI_SCORES){
                int b_ = z / NHEADS, h = z % NHEADS;
                float4 pbv = *(const float4*)&pb[((long)h*SEQ + mg)*SEQ + n0];
                float4 mkv = *(const float4*)&msk[b_*SEQ + n0];
                float4 v;
                v.x = e[0]*0.125f + pbv.x + mkv.x;
                v.y = e[1]*0.125f + pbv.y + mkv.y;
                v.z = e[2]*0.125f + pbv.z + mkv.z;
                v.w = e[3]*0.125f + pbv.w + mkv.w;
                *(float4*)&outF[(long)z*SEQ*SEQ + (long)mg*SEQ + n0] = v;
            } else {
                if (EPI == EPI_GELU){
#pragma unroll
                    for (int j=0;j<4;j++){
                        float t2 = e[j] + bias[n0+j];
                        e[j] = 0.5f*t2*(1.f + erff(t2*0.70710678118654752f));
                    }
                }
                bf h0,h1,h2,h3,l0,l1,l2,l3;
                bsplit(e[0],h0,l0); bsplit(e[1],h1,l1);
                bsplit(e[2],h2,l2); bsplit(e[3],h3,l3);
                long idx;
                if (EPI == EPI_GELU){
                    idx = (long)mg*ldc + n0;
                } else { // EPI_CTX
                    int b_ = z / NHEADS, h = z % NHEADS;
                    idx = ((long)(b_*SEQ + mg))*HID + h*HDIM + n0;
                }
                *(__nv_bfloat162*)&outHi[idx]   = __nv_bfloat162(h0,h1);
                *(__nv_bfloat162*)&outHi[idx+2] = __nv_bfloat162(h2,h3);
                *(__nv_bfloat162*)&outLo[idx]   = __nv_bfloat162(l0,l1);
                *(__nv_bfloat162*)&outLo[idx+2] = __nv_bfloat162(l2,l3);
            }
        }
    }
}

// ---------------- host ----------------
#define SMEM_128_128 196608   // 3 stages * 64KB  (>= 128*129*4 epilogue)
#define SMEM_128_64  147456   // 3 stages * 48KB
#define SMEM_64_128  147456   // 3 stages * 48KB

extern "C" void kernel_launch(void* const* d_in, const int* in_sizes, int n_in,
                              void* d_out, int out_size)
{
    const float* emb     = (const float*)d_in[0];
    const int*   seg     = (const int*)  d_in[1];
    const float* rel_emb = (const float*)d_in[2];
    const float* Wq = (const float*)d_in[3];  const float* bq = (const float*)d_in[4];
    const float* Wk = (const float*)d_in[5];  const float* bk = (const float*)d_in[6];
    const float* Wv = (const float*)d_in[7];  const float* bv = (const float*)d_in[8];
    const float* Wo = (const float*)d_in[9];  const float* bo = (const float*)d_in[10];
    const float* ln1_g = (const float*)d_in[11]; const float* ln1_b = (const float*)d_in[12];
    const float* W1 = (const float*)d_in[13]; const float* b1 = (const float*)d_in[14];
    const float* W2 = (const float*)d_in[15]; const float* b2 = (const float*)d_in[16];
    const float* ln2_g = (const float*)d_in[17]; const float* ln2_b = (const float*)d_in[18];
    float* out = (float*)d_out;

    static bool inited = false;
    static float *hid, *tmp, *sc, *pb, *mk;
    static bf *hA_h,*hA_l,*q_h,*q_l,*k_h,*k_l,*vt_h,*vt_l,*cx_h,*cx_l,*ff_h,*ff_l,*p_h,*p_l;
    static bf *wqkv_h,*wqkv_l,*wo_h,*wo_l,*w1_h,*w1_l,*w2_h,*w2_l;
    if (!inited){
        inited = true;
        cudaGetSymbolAddress((void**)&hid, g_hidden);
        cudaGetSymbolAddress((void**)&tmp, g_tmp);
        cudaGetSymbolAddress((void**)&sc,  g_scores);
        cudaGetSymbolAddress((void**)&pb,  g_pb);
        cudaGetSymbolAddress((void**)&mk,  g_mask);
        cudaGetSymbolAddress((void**)&hA_h, g_hidA_hi); cudaGetSymbolAddress((void**)&hA_l, g_hidA_lo);
        cudaGetSymbolAddress((void**)&q_h,  g_q_hi);    cudaGetSymbolAddress((void**)&q_l,  g_q_lo);
        cudaGetSymbolAddress((void**)&k_h,  g_k_hi);    cudaGetSymbolAddress((void**)&k_l,  g_k_lo);
        cudaGetSymbolAddress((void**)&vt_h, g_vt_hi);   cudaGetSymbolAddress((void**)&vt_l, g_vt_lo);
        cudaGetSymbolAddress((void**)&cx_h, g_ctx_hi);  cudaGetSymbolAddress((void**)&cx_l, g_ctx_lo);
        cudaGetSymbolAddress((void**)&ff_h, g_ff_hi);   cudaGetSymbolAddress((void**)&ff_l, g_ff_lo);
        cudaGetSymbolAddress((void**)&p_h,  g_p_hi);    cudaGetSymbolAddress((void**)&p_l,  g_p_lo);
        cudaGetSymbolAddress((void**)&wqkv_h, g_WqkvT_hi); cudaGetSymbolAddress((void**)&wqkv_l, g_WqkvT_lo);
        cudaGetSymbolAddress((void**)&wo_h, g_WoT_hi);  cudaGetSymbolAddress((void**)&wo_l, g_WoT_lo);
        cudaGetSymbolAddress((void**)&w1_h, g_W1T_hi);  cudaGetSymbolAddress((void**)&w1_l, g_W1T_lo);
        cudaGetSymbolAddress((void**)&w2_h, g_W2T_hi);  cudaGetSymbolAddress((void**)&w2_l, g_W2T_lo);
        cudaFuncSetAttribute(mma_gemm<128,128,EPI_QKV3>,   cudaFuncAttributeMaxDynamicSharedMemorySize, SMEM_128_128);
        cudaFuncSetAttribute(mma_gemm<128,128,EPI_SCORES>, cudaFuncAttributeMaxDynamicSharedMemorySize, SMEM_128_128);
        cudaFuncSetAttribute(mma_gemm<128,128,EPI_GELU>,   cudaFuncAttributeMaxDynamicSharedMemorySize, SMEM_128_128);
        cudaFuncSetAttribute(mma_gemm<128,64, EPI_CTX>,    cudaFuncAttributeMaxDynamicSharedMemorySize, SMEM_128_64);
        cudaFuncSetAttribute(mma_gemm<64,128, EPI_PLAIN>,  cudaFuncAttributeMaxDynamicSharedMemorySize, SMEM_64_128);
    }

    const long sQK = (long)SEQ*HDIM;   // 32768
    const long sSC = (long)SEQ*SEQ;    // 262144

    // ---- setup, ordered so the fused QKV GEMM is launch index 5 (ncu -s 5 -c 1) ----
    tsplit_k<<<dim3(HID/32, HID/32),   dim3(32,8)>>>(Wq, wqkv_h,            wqkv_l,            HID, HID); // 0
    tsplit_k<<<dim3(HID/32, HID/32),   dim3(32,8)>>>(Wk, wqkv_h + HID*HID,  wqkv_l + HID*HID,  HID, HID); // 1
    tsplit_k<<<dim3(HID/32, HID/32),   dim3(32,8)>>>(Wv, wqkv_h + 2*HID*HID,wqkv_l + 2*HID*HID,HID, HID); // 2
    split_copy_k<<<(ROWS*HID+255)/256, 256>>>(emb, hid, hA_h, hA_l, ROWS*HID);                            // 3
    tsplit_k<<<dim3(HID/32, HID/32),   dim3(32,8)>>>(Wo, wo_h, wo_l, HID, HID);                           // 4
    // layer-0 QKV hoisted here = launch 5 (profiled)
    mma_gemm<128,128,EPI_QKV3><<<dim3(18,32,1),512,SMEM_128_128>>>(
        hA_h,hA_l, wqkv_h,wqkv_l, HID, HID, HID, 0,0,
        bq, bk, bv, nullptr, q_h,q_l, k_h,k_l, vt_h,vt_l, 0, nullptr,nullptr);                            // 5
    mask_k<<<(ROWS+255)/256, 256>>>(seg, mk);
    posbias_k<<<(SEQ*SEQ+255)/256, 256>>>(rel_emb, pb);
    tsplit_k<<<dim3(FFDIM/32, HID/32), dim3(32,8)>>>(W1, w1_h, w1_l, HID, FFDIM);
    tsplit_k<<<dim3(HID/32, FFDIM/32), dim3(32,8)>>>(W2, w2_h, w2_l, FFDIM, HID);

    for (int L=0; L<NLAYERS; L++){
        // fused QKV projection (M=4096, N=2304, K=768); layer 0's is hoisted above
        if (L > 0)
            mma_gemm<128,128,EPI_QKV3><<<dim3(18,32,1),512,SMEM_128_128>>>(
                hA_h,hA_l, wqkv_h,wqkv_l, HID, HID, HID, 0,0,
                bq, bk, bv, nullptr, q_h,q_l, k_h,k_l, vt_h,vt_l, 0, nullptr,nullptr);

        // scores = Q K^T * scale + pb + mask  (96 x [512,512,64])
        mma_gemm<128,128,EPI_SCORES><<<dim3(4,4,NBH),512,SMEM_128_128>>>(
            q_h,q_l, k_h,k_l, HDIM, HDIM, HDIM, sQK,sQK,
            nullptr,nullptr,nullptr, sc, nullptr,nullptr, nullptr,nullptr, nullptr,nullptr, 0, pb, mk);

        softmax_k<<<(NBH*SEQ)/8, 256>>>(sc, p_h, p_l);

        // ctx = P V  (96 x [512,64,512]) -> [B*S, 768] bf16 split
        mma_gemm<128,64,EPI_CTX><<<dim3(1,4,NBH),512,SMEM_128_64>>>(
            p_h,p_l, vt_h,vt_l, SEQ, SEQ, SEQ, sSC, sQK,
            nullptr,nullptr,nullptr, nullptr, cx_h,cx_l, nullptr,nullptr, nullptr,nullptr, 0, nullptr,nullptr);

        // O projection (BM=64 -> 384 CTAs, better wave shape)
        mma_gemm<64,128,EPI_PLAIN><<<dim3(6,64,1),512,SMEM_64_128>>>(
            cx_h,cx_l, wo_h,wo_l, HID, HID, HID, 0,0,
            bo,nullptr,nullptr, tmp, nullptr,nullptr, nullptr,nullptr, nullptr,nullptr, HID, nullptr,nullptr);
        resln_k<<<ROWS,256>>>(hid, tmp, ln1_g, ln1_b, hid, hA_h, hA_l);

        // FF1 (M=4096, N=3072, K=768) with GELU
        mma_gemm<128,128,EPI_GELU><<<dim3(24,32,1),512,SMEM_128_128>>>(
            hA_h,hA_l, w1_h,w1_l, HID, HID, HID, 0,0,
            b1,nullptr,nullptr, nullptr, ff_h,ff_l, nullptr,nullptr, nullptr,nullptr, FFDIM, nullptr,nullptr);
        // FF2 (M=4096, N=768, K=3072) (BM=64 -> 384 CTAs)
        mma_gemm<64,128,EPI_PLAIN><<<dim3(6,64,1),512,SMEM_64_128>>>(
            ff_h,ff_l, w2_h,w2_l, FFDIM, FFDIM, FFDIM, 0,0,
            b2,nullptr,nullptr, tmp, nullptr,nullptr, nullptr,nullptr, nullptr,nullptr, HID, nullptr,nullptr);
        resln_k<<<ROWS,256>>>(hid, tmp, ln2_g, ln2_b, (L==NLAYERS-1) ? out : hid, hA_h, hA_l);
    }
}

// round 10
// speedup vs baseline: 2.7653x; 1.0562x over previous
#include <cuda_runtime.h>
#include <cuda_bf16.h>
#include <math.h>
#include <stdint.h>

// ---------------- constants ----------------
#define BATCH   8
#define SEQ     512
#define HID     768
#define NHEADS  12
#define HDIM    64
#define FFDIM   3072
#define NLAYERS 12
#define ROWS    (BATCH*SEQ)          // 4096
#define NBH     (BATCH*NHEADS)       // 96

typedef __nv_bfloat16 bf;

// ---------------- scratch (device globals; allocation-free) ----------------
__device__ float g_hidden[ROWS*HID];
__device__ float g_tmp   [ROWS*HID];
__device__ float g_pb    [NHEADS*SEQ*SEQ];
__device__ float g_mask  [ROWS];

__device__ bf g_hidA_hi[ROWS*HID], g_hidA_lo[ROWS*HID];
__device__ bf g_q_hi [ROWS*HID], g_q_lo [ROWS*HID];   // [B,H,S,64]
__device__ bf g_k_hi [ROWS*HID], g_k_lo [ROWS*HID];   // [B,H,S,64]
__device__ bf g_vt_hi[ROWS*HID], g_vt_lo[ROWS*HID];   // [B,H,64,S]
__device__ bf g_ctx_hi[ROWS*HID], g_ctx_lo[ROWS*HID]; // [B*S,768]
__device__ bf g_ff_hi[ROWS*FFDIM], g_ff_lo[ROWS*FFDIM];

__device__ bf g_WqkvT_hi[3*HID*HID], g_WqkvT_lo[3*HID*HID];  // [2304,768]
__device__ bf g_WoT_hi[HID*HID],  g_WoT_lo[HID*HID];
__device__ bf g_W1T_hi[HID*FFDIM], g_W1T_lo[HID*FFDIM]; // [3072,768]
__device__ bf g_W2T_hi[HID*FFDIM], g_W2T_lo[HID*FFDIM]; // [768,3072]

// ---------------- PTX helpers (sm_100 baseline only) ----------------
__device__ __forceinline__ uint32_t smem_u32(const void* p){
    uint32_t a;
    asm("{ .reg .u64 t; cvta.to.shared.u64 t, %1; cvt.u32.u64 %0, t; }" : "=r"(a) : "l"(p));
    return a;
}
__device__ __forceinline__ void cp16(uint32_t dst, const void* src){
    asm volatile("cp.async.cg.shared.global [%0], [%1], 16;" :: "r"(dst), "l"(src));
}
#define CP_COMMIT() asm volatile("cp.async.commit_group;" ::: "memory")
#define CP_WAIT(n)  asm volatile("cp.async.wait_group %0;" :: "n"(n) : "memory")

__device__ __forceinline__ void ldsm4(uint32_t* r, uint32_t addr){
    asm volatile("ldmatrix.sync.aligned.m8n8.x4.shared.b16 {%0,%1,%2,%3}, [%4];"
                 : "=r"(r[0]), "=r"(r[1]), "=r"(r[2]), "=r"(r[3]) : "r"(addr));
}

__device__ __forceinline__ void mma16816(float* d, const uint32_t* a,
                                         uint32_t b0, uint32_t b1){
    asm volatile(
        "mma.sync.aligned.m16n8k16.row.col.f32.bf16.bf16.f32 "
        "{%0,%1,%2,%3}, {%4,%5,%6,%7}, {%8,%9}, {%0,%1,%2,%3};"
        : "+f"(d[0]), "+f"(d[1]), "+f"(d[2]), "+f"(d[3])
        : "r"(a[0]), "r"(a[1]), "r"(a[2]), "r"(a[3]), "r"(b0), "r"(b1));
}

__device__ __forceinline__ void bsplit(float v, bf& h, bf& l){
    h = __float2bfloat16(v);
    l = __float2bfloat16(v - __bfloat162float(h));
}

// ---------------- reductions ----------------
__device__ __forceinline__ float warpSum(float v){
#pragma unroll
    for (int o=16;o>0;o>>=1) v += __shfl_xor_sync(0xffffffffu, v, o);
    return v;
}
__device__ float blockSum(float v){
    __shared__ float sh[8];
    __shared__ float total;
    int lane = threadIdx.x & 31, wid = threadIdx.x >> 5;
    v = warpSum(v);
    __syncthreads();
    if (lane == 0) sh[wid] = v;
    __syncthreads();
    if (wid == 0){
        float r = (lane < 8) ? sh[lane] : 0.f;
        r = warpSum(r);
        if (lane == 0) total = r;
    }
    __syncthreads();
    return total;
}

// ---------------- small kernels ----------------
__global__ void split_copy_k(const float* __restrict__ src, float* __restrict__ dstF,
                             bf* __restrict__ hi, bf* __restrict__ lo, int n){
    int i = blockIdx.x*blockDim.x + threadIdx.x;
    if (i >= n) return;
    float v = src[i];
    dstF[i] = v;
    bf h, l; bsplit(v, h, l);
    hi[i] = h; lo[i] = l;
}

__global__ void mask_k(const int* __restrict__ seg, float* __restrict__ mask){
    int i = blockIdx.x*blockDim.x + threadIdx.x;
    if (i < ROWS) mask[i] = (seg[i] > 0) ? 0.f : -10000.f;
}

__device__ __forceinline__ int rel_bucket(int qpos, int kpos){
    int rel = kpos - qpos;
    int off = (rel > 0) ? 16 : 0;
    int ar  = rel < 0 ? -rel : rel;
    if (ar < 8) return off + ar;
    float t = logf((float)ar / 8.0f) / 2.772588722239781f * 8.0f;
    int v = 8 + (int)t;
    if (v > 15) v = 15;
    return off + v;
}

__global__ void posbias_k(const float* __restrict__ rel_emb, float* __restrict__ pb){
    int idx = blockIdx.x*blockDim.x + threadIdx.x;
    if (idx >= SEQ*SEQ) return;
    int q = idx >> 9, k = idx & 511;
    int bkt = rel_bucket(q, k);
#pragma unroll
    for (int h=0; h<NHEADS; h++)
        pb[((long)h*SEQ + q)*SEQ + k] = rel_emb[bkt*NHEADS + h];
}

// W[K,N] fp32 -> WT hi/lo [N,K] bf16, 32x32 smem-tiled
__global__ void tsplit_k(const float* __restrict__ W,
                         bf* __restrict__ Thi, bf* __restrict__ Tlo,
                         int K, int N){
    __shared__ float t[32][33];
    int k0 = blockIdx.y*32, n0 = blockIdx.x*32;
    int x = threadIdx.x, y = threadIdx.y;
#pragma unroll
    for (int i=y; i<32; i+=8) t[i][x] = W[(long)(k0+i)*N + n0 + x];
    __syncthreads();
#pragma unroll
    for (int i=y; i<32; i+=8){
        float v = t[x][i];
        bf h, l; bsplit(v, h, l);
        long o = (long)(n0+i)*K + k0 + x;
        Thi[o] = h; Tlo[o] = l;
    }
}

__global__ __launch_bounds__(256) void resln_k(
    const float* __restrict__ resid, const float* __restrict__ x,
    const float* __restrict__ g, const float* __restrict__ b,
    float* __restrict__ out,
    bf* __restrict__ ohi, bf* __restrict__ olo)
{
    long base = (long)blockIdx.x * HID;
    int t = threadIdx.x;
    float v[3]; float s = 0.f;
#pragma unroll
    for (int i=0;i<3;i++){ v[i] = resid[base + t + 256*i] + x[base + t + 256*i]; s += v[i]; }
    s = blockSum(s);
    float mean = s * (1.f/768.f);
    float q = 0.f;
#pragma unroll
    for (int i=0;i<3;i++){ float d = v[i]-mean; q += d*d; }
    q = blockSum(q);
    float inv = 1.f / sqrtf(q*(1.f/768.f) + 1e-6f);
#pragma unroll
    for (int i=0;i<3;i++){
        int c = t + 256*i;
        float r = g[c]*(v[i]-mean)*inv + b[c];
        out[base + c] = r;
        bf h, l; bsplit(r, h, l);
        ohi[base + c] = h; olo[base + c] = l;
    }
}

// ---------------- fused flash attention ----------------
// grid (4 q-tiles, 96 bh), 512 threads (16 warps, 4x4).
// Per bh: ctx[q,dd] = softmax(Q K^T /8 + pb + mask) V, all tiles streamed in smem.
#define FLASH_SMEM 167936

__global__ __launch_bounds__(512,1) void flash_k(
    const bf* __restrict__ Qh, const bf* __restrict__ Ql,
    const bf* __restrict__ Kh, const bf* __restrict__ Kl,
    const bf* __restrict__ Vth, const bf* __restrict__ Vtl,
    const float* __restrict__ pbias, const float* __restrict__ mk,
    bf* __restrict__ ctxHi, bf* __restrict__ ctxLo)
{
    constexpr int Q_HI=0, Q_LO=16384, K_HI=32768, K_LO=49152;
    constexpr int V_HI=65536, V_LO=81920, P_HI=98304, P_LO=131072;
    constexpr int REDM=163840, REDS=165888;
    extern __shared__ __align__(16) char smem[];
    const uint32_t sb = smem_u32(smem);
    float* redM = (float*)(smem + REDM);
    float* redS = (float*)(smem + REDS);

    const int tid=threadIdx.x, lane=tid&31, warp=tid>>5;
    const int warpM = warp>>2, warpN = warp&3;
    const int q0 = blockIdx.x*128, bh = blockIdx.y;
    const int b = bh/NHEADS, h = bh - b*NHEADS;
    const long baseQK = (long)bh*SEQ*HDIM;
    const long baseV  = (long)bh*HDIM*SEQ;

    const int lt = lane>>3, lrow = ((lt&1)<<3)+(lane&7), lcol = (lt>>1)<<4;
    const int qr = lane>>2, qc = (lane&3)*2;

    // Q load (once) — grouped with KV(0)'s commit
    for (int ci = tid; ci < 2048; ci += 512){
        int r = ci>>3, c16 = ci&7, rr = r&127;
        const bf* src = ((r<128)?Qh:Ql) + baseQK + (long)(q0+rr)*HDIM + c16*8;
        cp16(sb + (r<128?Q_HI:Q_LO) + rr*128 + (uint32_t)((c16*16)^((rr&7)<<4)), src);
    }
    auto loadKV = [&](int j){
        for (int ci = tid; ci < 4096; ci += 512){
            if (ci < 2048){
                int r = ci>>3, c16 = ci&7, rr = r&127;
                const bf* src = ((r<128)?Kh:Kl) + baseQK + (long)(j*128+rr)*HDIM + c16*8;
                cp16(sb + (r<128?K_HI:K_LO) + rr*128 + (uint32_t)((c16*16)^((rr&7)<<4)), src);
            } else {
                int t = ci-2048, r = t>>4, c16 = t&15, dd = r&63;
                const bf* src = ((r<64)?Vth:Vtl) + baseV + (long)dd*SEQ + j*128 + c16*8;
                cp16(sb + (r<64?V_HI:V_LO) + dd*256 + (uint32_t)((c16*16)^((dd&7)<<4)), src);
            }
        }
        CP_COMMIT();
    };
    loadKV(0);

    float m_run[4], l_run[4];
#pragma unroll
    for (int i=0;i<4;i++){ m_run[i] = -3.0e38f; l_run[i] = 0.f; }
    float oacc[2][2][4];
#pragma unroll
    for (int mt=0;mt<2;mt++)
#pragma unroll
        for (int nt=0;nt<2;nt++)
#pragma unroll
            for (int e=0;e<4;e++) oacc[mt][nt][e] = 0.f;

    for (int j=0;j<4;j++){
        CP_WAIT(0); __syncthreads();

        // ---- S = Q K^T (3-term split) ----
        float acc[2][4][4];
#pragma unroll
        for (int mt=0;mt<2;mt++)
#pragma unroll
            for (int nt=0;nt<4;nt++)
#pragma unroll
                for (int e=0;e<4;e++) acc[mt][nt][e] = 0.f;
#pragma unroll
        for (int kk=0;kk<4;kk++){
            const uint32_t kb = (uint32_t)(kk<<5);
            uint32_t ah[2][4], al[2][4];
#pragma unroll
            for (int mt=0;mt<2;mt++){
                int r = warpM*32 + mt*16 + lrow;
                uint32_t cb = (kb + lcol) ^ ((uint32_t)(r&7)<<4);
                ldsm4(ah[mt], sb + Q_HI + r*128 + cb);
                ldsm4(al[mt], sb + Q_LO + r*128 + cb);
            }
            uint32_t bhf[2][4], blf[2][4];
#pragma unroll
            for (int g=0; g<2; g++){
                int r = warpN*32 + g*16 + lrow;
                uint32_t cb = (kb + lcol) ^ ((uint32_t)(r&7)<<4);
                ldsm4(bhf[g], sb + K_HI + r*128 + cb);
                ldsm4(blf[g], sb + K_LO + r*128 + cb);
            }
#pragma unroll
            for (int mt=0;mt<2;mt++)
#pragma unroll
                for (int nt=0;nt<4;nt++){
                    int g = nt>>1, sH = nt&1;
                    mma16816(acc[mt][nt], ah[mt], bhf[g][sH], bhf[g][sH+2]);
                    mma16816(acc[mt][nt], ah[mt], blf[g][sH], blf[g][sH+2]);
                    mma16816(acc[mt][nt], al[mt], bhf[g][sH], bhf[g][sH+2]);
                }
        }

        // ---- scale + pb + mask, per-row max ----
        float pmax[4] = {-3.0e38f,-3.0e38f,-3.0e38f,-3.0e38f};
#pragma unroll
        for (int mt=0;mt<2;mt++){
            int r0 = q0 + warpM*32 + mt*16 + qr;
            const float* pbr0 = pbias + ((long)h*SEQ + r0)*SEQ;
            const float* pbr1 = pbr0 + 8*SEQ;
#pragma unroll
            for (int nt=0;nt<4;nt++){
                int col = j*128 + warpN*32 + nt*8 + qc;
                float2 p0 = *(const float2*)(pbr0 + col);
                float2 p1 = *(const float2*)(pbr1 + col);
                float2 mv = *(const float2*)(mk + b*SEQ + col);
                acc[mt][nt][0] = acc[mt][nt][0]*0.125f + p0.x + mv.x;
                acc[mt][nt][1] = acc[mt][nt][1]*0.125f + p0.y + mv.y;
                acc[mt][nt][2] = acc[mt][nt][2]*0.125f + p1.x + mv.x;
                acc[mt][nt][3] = acc[mt][nt][3]*0.125f + p1.y + mv.y;
                pmax[mt*2]   = fmaxf(pmax[mt*2],   fmaxf(acc[mt][nt][0], acc[mt][nt][1]));
                pmax[mt*2+1] = fmaxf(pmax[mt*2+1], fmaxf(acc[mt][nt][2], acc[mt][nt][3]));
            }
        }
#pragma unroll
        for (int ri=0;ri<4;ri++){
            pmax[ri] = fmaxf(pmax[ri], __shfl_xor_sync(0xffffffffu, pmax[ri], 1));
            pmax[ri] = fmaxf(pmax[ri], __shfl_xor_sync(0xffffffffu, pmax[ri], 2));
        }
        if ((lane&3)==0){
#pragma unroll
            for (int ri=0;ri<4;ri++){
                int rl = warpM*32 + (ri>>1)*16 + qr + (ri&1)*8;
                redM[rl*4 + warpN] = pmax[ri];
            }
        }
        __syncthreads();

        float alpha[4];
#pragma unroll
        for (int ri=0;ri<4;ri++){
            int rl = warpM*32 + (ri>>1)*16 + qr + (ri&1)*8;
            float tm = fmaxf(fmaxf(redM[rl*4],redM[rl*4+1]), fmaxf(redM[rl*4+2],redM[rl*4+3]));
            float mn = fmaxf(m_run[ri], tm);
            alpha[ri] = expf(m_run[ri] - mn);
            m_run[ri] = mn;
        }

        // ---- p = exp(s-m), write P hi/lo to smem, partial sums ----
        float psum[4] = {0.f,0.f,0.f,0.f};
#pragma unroll
        for (int mt=0;mt<2;mt++){
            int rl0 = warpM*32 + mt*16 + qr;
            int rl1 = rl0 + 8;
#pragma unroll
            for (int nt=0;nt<4;nt++){
                float e0 = expf(acc[mt][nt][0] - m_run[mt*2]);
                float e1 = expf(acc[mt][nt][1] - m_run[mt*2]);
                float e2 = expf(acc[mt][nt][2] - m_run[mt*2+1]);
                float e3 = expf(acc[mt][nt][3] - m_run[mt*2+1]);
                psum[mt*2]   += e0 + e1;
                psum[mt*2+1] += e2 + e3;
                int colb = (warpN*32 + nt*8 + qc)*2;
                bf h0,l0,h1,l1,h2,l2,h3,l3;
                bsplit(e0,h0,l0); bsplit(e1,h1,l1);
                bsplit(e2,h2,l2); bsplit(e3,h3,l3);
                uint32_t sw0 = (uint32_t)colb ^ ((uint32_t)(rl0&7)<<4);
                uint32_t sw1 = (uint32_t)colb ^ ((uint32_t)(rl1&7)<<4);
                *(__nv_bfloat162*)(smem + P_HI + rl0*256 + sw0) = __nv_bfloat162(h0,h1);
                *(__nv_bfloat162*)(smem + P_LO + rl0*256 + sw0) = __nv_bfloat162(l0,l1);
                *(__nv_bfloat162*)(smem + P_HI + rl1*256 + sw1) = __nv_bfloat162(h2,h3);
                *(__nv_bfloat162*)(smem + P_LO + rl1*256 + sw1) = __nv_bfloat162(l2,l3);
            }
        }
#pragma unroll
        for (int ri=0;ri<4;ri++){
            psum[ri] += __shfl_xor_sync(0xffffffffu, psum[ri], 1);
            psum[ri] += __shfl_xor_sync(0xffffffffu, psum[ri], 2);
        }
        if ((lane&3)==0){
#pragma unroll
            for (int ri=0;ri<4;ri++){
                int rl = warpM*32 + (ri>>1)*16 + qr + (ri&1)*8;
                redS[rl*4 + warpN] = psum[ri];
            }
        }
        __syncthreads();

#pragma unroll
        for (int ri=0;ri<4;ri++){
            int rl = warpM*32 + (ri>>1)*16 + qr + (ri&1)*8;
            float ts = redS[rl*4] + redS[rl*4+1] + redS[rl*4+2] + redS[rl*4+3];
            l_run[ri] = alpha[ri]*l_run[ri] + ts;
        }
        // rescale O
#pragma unroll
        for (int mt=0;mt<2;mt++)
#pragma unroll
            for (int nt=0;nt<2;nt++)
#pragma unroll
                for (int e=0;e<4;e++) oacc[mt][nt][e] *= alpha[mt*2 + (e>>1)];

        // ---- O += P V (3-term split), k = 128 in 8 k16 steps ----
#pragma unroll
        for (int ks=0;ks<8;ks++){
            const uint32_t kb2 = (uint32_t)(ks<<5);
            uint32_t pah[2][4], pal[2][4];
#pragma unroll
            for (int mt=0;mt<2;mt++){
                int r = warpM*32 + mt*16 + lrow;
                uint32_t cb = (kb2 + lcol) ^ ((uint32_t)(r&7)<<4);
                ldsm4(pah[mt], sb + P_HI + r*256 + cb);
                ldsm4(pal[mt], sb + P_LO + r*256 + cb);
            }
            uint32_t vbh[4], vbl[4];
            {
                int n = warpN*16 + lrow;
                uint32_t cb = (kb2 + lcol) ^ ((uint32_t)(n&7)<<4);
                ldsm4(vbh, sb + V_HI + n*256 + cb);
                ldsm4(vbl, sb + V_LO + n*256 + cb);
            }
#pragma unroll
            for (int mt=0;mt<2;mt++)
#pragma unroll
                for (int nt=0;nt<2;nt++){
                    mma16816(oacc[mt][nt], pah[mt], vbh[nt], vbh[nt+2]);
                    mma16816(oacc[mt][nt], pah[mt], vbl[nt], vbl[nt+2]);
                    mma16816(oacc[mt][nt], pal[mt], vbh[nt], vbh[nt+2]);
                }
        }
        __syncthreads();
        if (j < 3) loadKV(j+1);
    }

    // ---- epilogue: o /= l, write ctx bf16 hi/lo ----
    float inv[4];
#pragma unroll
    for (int ri=0;ri<4;ri++) inv[ri] = 1.f / l_run[ri];
#pragma unroll
    for (int mt=0;mt<2;mt++){
        int m0 = q0 + warpM*32 + mt*16 + qr;
#pragma unroll
        for (int nt=0;nt<2;nt++){
            int col = h*HDIM + warpN*16 + nt*8 + qc;
            long i0 = ((long)(b*SEQ + m0))*HID + col;
            long i1 = i0 + 8L*HID;
            float e0 = oacc[mt][nt][0]*inv[mt*2];
            float e1 = oacc[mt][nt][1]*inv[mt*2];
            float e2 = oacc[mt][nt][2]*inv[mt*2+1];
            float e3 = oacc[mt][nt][3]*inv[mt*2+1];
            bf h0,l0,h1,l1,h2,l2,h3,l3;
            bsplit(e0,h0,l0); bsplit(e1,h1,l1);
            bsplit(e2,h2,l2); bsplit(e3,h3,l3);
            *(__nv_bfloat162*)&ctxHi[i0] = __nv_bfloat162(h0,h1);
            *(__nv_bfloat162*)&ctxLo[i0] = __nv_bfloat162(l0,l1);
            *(__nv_bfloat162*)&ctxHi[i1] = __nv_bfloat162(h2,h3);
            *(__nv_bfloat162*)&ctxLo[i1] = __nv_bfloat162(l2,l3);
        }
    }
}

// ---------------- mma.sync GEMM (BK=64, 3-stage cp.async, ldmatrix, 512 thr) ----------------
enum { EPI_PLAIN=0, EPI_GELU=1, EPI_QKV3=2 };

template<int BM_, int BN_, int EPI>
__global__ __launch_bounds__(512,1) void mma_gemm(
    const bf* __restrict__ Ahi, const bf* __restrict__ Alo,
    const bf* __restrict__ Bhi, const bf* __restrict__ Blo,
    int K, int lda, int ldb,
    const float* __restrict__ bias, const float* __restrict__ bias2, const float* __restrict__ bias3,
    float* __restrict__ outF,
    bf* __restrict__ outHi, bf* __restrict__ outLo,
    bf* __restrict__ out2Hi, bf* __restrict__ out2Lo,
    bf* __restrict__ out3Hi, bf* __restrict__ out3Lo,
    int ldc)
{
    constexpr int WGM = BM_ / 32;
    constexpr int WGN = 16 / WGM;
    constexpr int WM  = 32;
    constexpr int WN  = BN_ / WGN;
    constexpr int MT  = 2;
    constexpr int NTT = WN / 8;
    constexpr int NG  = (NTT/2 > 0) ? NTT/2 : 1;
    constexpr int A_HI = 0;
    constexpr int A_LO = BM_*128;
    constexpr int B_HI = 2*BM_*128;
    constexpr int B_LO = 2*BM_*128 + BN_*128;
    constexpr int STAGE = 2*BM_*128 + 2*BN_*128;
    constexpr int TOT_ROWS = 2*BM_ + 2*BN_;

    extern __shared__ __align__(16) char smem[];
    const uint32_t sbase = smem_u32(smem);

    const int tid = threadIdx.x, lane = tid & 31, warp = tid >> 5;
    const int warpM = warp / WGN, warpN = warp % WGN;
    const int mBase = blockIdx.y * BM_, nBase = blockIdx.x * BN_;

    auto issue = [&](int c){
        const int s = c % 3, k0 = c << 6;
        const uint32_t segbase = sbase + (uint32_t)(s * STAGE);
#pragma unroll 2
        for (int ci = tid; ci < TOT_ROWS*8; ci += 512){
            int r = ci >> 3, c16 = ci & 7;
            const bf* src; uint32_t toff; int rr;
            if (r < BM_)            { rr = r;          src = Ahi + (long)(mBase+rr)*lda + k0; toff = A_HI; }
            else if (r < 2*BM_)     { rr = r-BM_;      src = Alo + (long)(mBase+rr)*lda + k0; toff = A_LO; }
            else if (r < 2*BM_+BN_) { rr = r-2*BM_;    src = Bhi + (long)(nBase+rr)*ldb + k0; toff = B_HI; }
            else                    { rr = r-2*BM_-BN_;src = Blo + (long)(nBase+rr)*ldb + k0; toff = B_LO; }
            uint32_t dst = segbase + toff + (uint32_t)(rr*128) + (uint32_t)((c16*16) ^ ((rr&7)<<4));
            cp16(dst, src + c16*8);
        }
        CP_COMMIT();
    };

    float acc[MT][NTT][4];
#pragma unroll
    for (int i=0;i<MT;i++)
#pragma unroll
        for (int j=0;j<NTT;j++)
#pragma unroll
            for (int e=0;e<4;e++) acc[i][j][e] = 0.f;

    const int lt  = lane >> 3;
    const int lrow = ((lt & 1) << 3) + (lane & 7);
    const int lcol = (lt >> 1) << 4;

    const int CH = K >> 6;
    issue(0);
    if (CH > 1) issue(1);

    for (int c = 0; c < CH; ++c){
        if (c + 1 < CH) { CP_WAIT(1); } else { CP_WAIT(0); }
        __syncthreads();
        if (c + 2 < CH) issue(c + 2);

        const uint32_t st = sbase + (uint32_t)((c % 3) * STAGE);
#pragma unroll
        for (int kk = 0; kk < 4; ++kk){
            const uint32_t kb = (uint32_t)(kk << 5);
            uint32_t ah[MT][4], al[MT][4];
#pragma unroll
            for (int mt = 0; mt < MT; ++mt){
                int r = warpM*WM + mt*16 + lrow;
                uint32_t cb = (kb + lcol) ^ ((uint32_t)(r&7) << 4);
                ldsm4(ah[mt], st + A_HI + r*128 + cb);
                ldsm4(al[mt], st + A_LO + r*128 + cb);
            }
            uint32_t bh[NG][4], bl[NG][4];
#pragma unroll
            for (int g = 0; g < NG; ++g){
                int r = warpN*WN + g*16 + lrow;
                uint32_t cb = (kb + lcol) ^ ((uint32_t)(r&7) << 4);
                ldsm4(bh[g], st + B_HI + r*128 + cb);
                ldsm4(bl[g], st + B_LO + r*128 + cb);
            }
#pragma unroll
            for (int mt = 0; mt < MT; ++mt)
#pragma unroll
                for (int nt = 0; nt < NTT; ++nt){
                    int g = nt >> 1, sH = nt & 1;
                    mma16816(acc[mt][nt], ah[mt], bh[g][sH], bh[g][sH+2]);
                    mma16816(acc[mt][nt], ah[mt], bl[g][sH], bl[g][sH+2]);
                    mma16816(acc[mt][nt], al[mt], bh[g][sH], bh[g][sH+2]);
                }
        }
    }
    __syncthreads();

    // epilogue via padded smem
    float* sD = (float*)smem;
    constexpr int LDD = BN_ + 1;
#pragma unroll
    for (int mt = 0; mt < MT; ++mt)
#pragma unroll
        for (int nt = 0; nt < NTT; ++nt){
            int r0 = warpM*WM + mt*16 + (lane >> 2);
            int c0 = warpN*WN + nt*8 + (lane & 3)*2;
            sD[r0*LDD + c0]       = acc[mt][nt][0];
            sD[r0*LDD + c0 + 1]   = acc[mt][nt][1];
            sD[(r0+8)*LDD + c0]   = acc[mt][nt][2];
            sD[(r0+8)*LDD + c0+1] = acc[mt][nt][3];
        }
    __syncthreads();

    if (EPI == EPI_QKV3){
        const int which = nBase / HID;
        const int nloc0 = nBase - which*HID;
        const float* bs = (which==0) ? bias : (which==1) ? bias2 : bias3;
        bf* oHi = (which==0) ? outHi : (which==1) ? out2Hi : out3Hi;
        bf* oLo = (which==0) ? outLo : (which==1) ? out2Lo : out3Lo;
        if (which < 2){
            for (int t = tid; t < BM_*32; t += 512){
                int m = t >> 5, nq = t & 31;
                int nl = nloc0 + nq*4;
                int mg = mBase + m, b_ = mg >> 9, sidx = mg & 511;
                int h = nl >> 6, dd = nl & 63;
                float e[4];
#pragma unroll
                for (int j=0;j<4;j++) e[j] = sD[m*LDD + nq*4 + j] + bs[nl+j];
                bf h0,h1,h2,h3,l0,l1,l2,l3;
                bsplit(e[0],h0,l0); bsplit(e[1],h1,l1);
                bsplit(e[2],h2,l2); bsplit(e[3],h3,l3);
                long idx = ((long)(b_*NHEADS + h)*SEQ + sidx)*HDIM + dd;
                *(__nv_bfloat162*)&oHi[idx]   = __nv_bfloat162(h0,h1);
                *(__nv_bfloat162*)&oHi[idx+2] = __nv_bfloat162(h2,h3);
                *(__nv_bfloat162*)&oLo[idx]   = __nv_bfloat162(l0,l1);
                *(__nv_bfloat162*)&oLo[idx+2] = __nv_bfloat162(l2,l3);
            }
        } else {
            for (int t = tid; t < BM_*128; t += 512){
                int m = t & (BM_-1), n = t / BM_;
                int nl = nloc0 + n, h = nl >> 6, dd = nl & 63;
                int mg = mBase + m, b_ = mg >> 9, sidx = mg & 511;
                float v = sD[m*LDD + n] + bs[nl];
                bf hh, ll; bsplit(v, hh, ll);
                long idx = ((long)(b_*NHEADS + h)*HDIM + dd)*SEQ + sidx;
                oHi[idx] = hh; oLo[idx] = ll;
            }
        }
    } else {
        constexpr int NQ = BN_ / 4;
        for (int t = tid; t < BM_*NQ; t += 512){
            int m = t / NQ, nq = t % NQ;
            int n0 = nBase + nq*4;
            int mg = mBase + m;
            float e[4];
#pragma unroll
            for (int j=0;j<4;j++) e[j] = sD[m*LDD + nq*4 + j];
            if (EPI == EPI_PLAIN){
#pragma unroll
                for (int j=0;j<4;j++) e[j] += bias[n0+j];
                float4 v = {e[0],e[1],e[2],e[3]};
                *(float4*)&outF[(long)mg*ldc + n0] = v;
            } else { // EPI_GELU
#pragma unroll
                for (int j=0;j<4;j++){
                    float t2 = e[j] + bias[n0+j];
                    e[j] = 0.5f*t2*(1.f + erff(t2*0.70710678118654752f));
                }
                bf h0,h1,h2,h3,l0,l1,l2,l3;
                bsplit(e[0],h0,l0); bsplit(e[1],h1,l1);
                bsplit(e[2],h2,l2); bsplit(e[3],h3,l3);
                long idx = (long)mg*ldc + n0;
                *(__nv_bfloat162*)&outHi[idx]   = __nv_bfloat162(h0,h1);
                *(__nv_bfloat162*)&outHi[idx+2] = __nv_bfloat162(h2,h3);
                *(__nv_bfloat162*)&outLo[idx]   = __nv_bfloat162(l0,l1);
                *(__nv_bfloat162*)&outLo[idx+2] = __nv_bfloat162(l2,l3);
            }
        }
    }
}

// ---------------- host ----------------
#define SMEM_128_128 196608
#define SMEM_64_128  147456

extern "C" void kernel_launch(void* const* d_in, const int* in_sizes, int n_in,
                              void* d_out, int out_size)
{
    const float* emb     = (const float*)d_in[0];
    const int*   seg     = (const int*)  d_in[1];
    const float* rel_emb = (const float*)d_in[2];
    const float* Wq = (const float*)d_in[3];  const float* bq = (const float*)d_in[4];
    const float* Wk = (const float*)d_in[5];  const float* bk = (const float*)d_in[6];
    const float* Wv = (const float*)d_in[7];  const float* bv = (const float*)d_in[8];
    const float* Wo = (const float*)d_in[9];  const float* bo = (const float*)d_in[10];
    const float* ln1_g = (const float*)d_in[11]; const float* ln1_b = (const float*)d_in[12];
    const float* W1 = (const float*)d_in[13]; const float* b1 = (const float*)d_in[14];
    const float* W2 = (const float*)d_in[15]; const float* b2 = (const float*)d_in[16];
    const float* ln2_g = (const float*)d_in[17]; const float* ln2_b = (const float*)d_in[18];
    float* out = (float*)d_out;

    static bool inited = false;
    static float *hid, *tmp, *pb, *mk;
    static bf *hA_h,*hA_l,*q_h,*q_l,*k_h,*k_l,*vt_h,*vt_l,*cx_h,*cx_l,*ff_h,*ff_l;
    static bf *wqkv_h,*wqkv_l,*wo_h,*wo_l,*w1_h,*w1_l,*w2_h,*w2_l;
    if (!inited){
        inited = true;
        cudaGetSymbolAddress((void**)&hid, g_hidden);
        cudaGetSymbolAddress((void**)&tmp, g_tmp);
        cudaGetSymbolAddress((void**)&pb,  g_pb);
        cudaGetSymbolAddress((void**)&mk,  g_mask);
        cudaGetSymbolAddress((void**)&hA_h, g_hidA_hi); cudaGetSymbolAddress((void**)&hA_l, g_hidA_lo);
        cudaGetSymbolAddress((void**)&q_h,  g_q_hi);    cudaGetSymbolAddress((void**)&q_l,  g_q_lo);
        cudaGetSymbolAddress((void**)&k_h,  g_k_hi);    cudaGetSymbolAddress((void**)&k_l,  g_k_lo);
        cudaGetSymbolAddress((void**)&vt_h, g_vt_hi);   cudaGetSymbolAddress((void**)&vt_l, g_vt_lo);
        cudaGetSymbolAddress((void**)&cx_h, g_ctx_hi);  cudaGetSymbolAddress((void**)&cx_l, g_ctx_lo);
        cudaGetSymbolAddress((void**)&ff_h, g_ff_hi);   cudaGetSymbolAddress((void**)&ff_l, g_ff_lo);
        cudaGetSymbolAddress((void**)&wqkv_h, g_WqkvT_hi); cudaGetSymbolAddress((void**)&wqkv_l, g_WqkvT_lo);
        cudaGetSymbolAddress((void**)&wo_h, g_WoT_hi);  cudaGetSymbolAddress((void**)&wo_l, g_WoT_lo);
        cudaGetSymbolAddress((void**)&w1_h, g_W1T_hi);  cudaGetSymbolAddress((void**)&w1_l, g_W1T_lo);
        cudaGetSymbolAddress((void**)&w2_h, g_W2T_hi);  cudaGetSymbolAddress((void**)&w2_l, g_W2T_lo);
        cudaFuncSetAttribute(mma_gemm<128,128,EPI_QKV3>, cudaFuncAttributeMaxDynamicSharedMemorySize, SMEM_128_128);
        cudaFuncSetAttribute(mma_gemm<128,128,EPI_GELU>, cudaFuncAttributeMaxDynamicSharedMemorySize, SMEM_128_128);
        cudaFuncSetAttribute(mma_gemm<64,128, EPI_PLAIN>,cudaFuncAttributeMaxDynamicSharedMemorySize, SMEM_64_128);
        cudaFuncSetAttribute(flash_k, cudaFuncAttributeMaxDynamicSharedMemorySize, FLASH_SMEM);
    }

    // ---- setup ----
    tsplit_k<<<dim3(HID/32, HID/32),   dim3(32,8)>>>(Wq, wqkv_h,            wqkv_l,            HID, HID);
    tsplit_k<<<dim3(HID/32, HID/32),   dim3(32,8)>>>(Wk, wqkv_h + HID*HID,  wqkv_l + HID*HID,  HID, HID);
    tsplit_k<<<dim3(HID/32, HID/32),   dim3(32,8)>>>(Wv, wqkv_h + 2*HID*HID,wqkv_l + 2*HID*HID,HID, HID);
    split_copy_k<<<(ROWS*HID+255)/256, 256>>>(emb, hid, hA_h, hA_l, ROWS*HID);
    tsplit_k<<<dim3(HID/32, HID/32),   dim3(32,8)>>>(Wo, wo_h, wo_l, HID, HID);
    // layer-0 QKV hoisted (profiling target)
    mma_gemm<128,128,EPI_QKV3><<<dim3(18,32,1),512,SMEM_128_128>>>(
        hA_h,hA_l, wqkv_h,wqkv_l, HID, HID, HID,
        bq, bk, bv, nullptr, q_h,q_l, k_h,k_l, vt_h,vt_l, 0);
    mask_k<<<(ROWS+255)/256, 256>>>(seg, mk);
    posbias_k<<<(SEQ*SEQ+255)/256, 256>>>(rel_emb, pb);
    tsplit_k<<<dim3(FFDIM/32, HID/32), dim3(32,8)>>>(W1, w1_h, w1_l, HID, FFDIM);
    tsplit_k<<<dim3(HID/32, FFDIM/32), dim3(32,8)>>>(W2, w2_h, w2_l, FFDIM, HID);

    for (int L=0; L<NLAYERS; L++){
        if (L > 0)
            mma_gemm<128,128,EPI_QKV3><<<dim3(18,32,1),512,SMEM_128_128>>>(
                hA_h,hA_l, wqkv_h,wqkv_l, HID, HID, HID,
                bq, bk, bv, nullptr, q_h,q_l, k_h,k_l, vt_h,vt_l, 0);

        // fused attention: scores + softmax + P*V in one kernel
        flash_k<<<dim3(4, NBH), 512, FLASH_SMEM>>>(
            q_h,q_l, k_h,k_l, vt_h,vt_l, pb, mk, cx_h, cx_l);

        // O projection
        mma_gemm<64,128,EPI_PLAIN><<<dim3(6,64,1),512,SMEM_64_128>>>(
            cx_h,cx_l, wo_h,wo_l, HID, HID, HID,
            bo,nullptr,nullptr, tmp, nullptr,nullptr, nullptr,nullptr, nullptr,nullptr, HID);
        resln_k<<<ROWS,256>>>(hid, tmp, ln1_g, ln1_b, hid, hA_h, hA_l);

        // FF1 (GELU)
        mma_gemm<128,128,EPI_GELU><<<dim3(24,32,1),512,SMEM_128_128>>>(
            hA_h,hA_l, w1_h,w1_l, HID, HID, HID,
            b1,nullptr,nullptr, nullptr, ff_h,ff_l, nullptr,nullptr, nullptr,nullptr, FFDIM);
        // FF2
        mma_gemm<64,128,EPI_PLAIN><<<dim3(6,64,1),512,SMEM_64_128>>>(
            ff_h,ff_l, w2_h,w2_l, FFDIM, FFDIM, FFDIM,
            b2,nullptr,nullptr, tmp, nullptr,nullptr, nullptr,nullptr, nullptr,nullptr, HID);
        resln_k<<<ROWS,256>>>(hid, tmp, ln2_g, ln2_b, (L==NLAYERS-1) ? out : hid, hA_h, hA_l);
    }
}

// round 11
// speedup vs baseline: 2.9330x; 1.0606x over previous
#include <cuda_runtime.h>
#include <cuda_bf16.h>
#include <math.h>
#include <stdint.h>

// ---------------- constants ----------------
#define BATCH   8
#define SEQ     512
#define HID     768
#define NHEADS  12
#define HDIM    64
#define FFDIM   3072
#define NLAYERS 12
#define ROWS    (BATCH*SEQ)          // 4096
#define NBH     (BATCH*NHEADS)       // 96

typedef __nv_bfloat16 bf;

// ---------------- scratch (device globals; allocation-free) ----------------
__device__ float g_hidden[ROWS*HID];
__device__ float g_tmp   [ROWS*HID];
__device__ float g_pb    [NHEADS*SEQ*SEQ];
__device__ float g_mask  [ROWS];

__device__ bf g_hidA_hi[ROWS*HID], g_hidA_lo[ROWS*HID];
__device__ bf g_q_hi [ROWS*HID], g_q_lo [ROWS*HID];   // [B,H,S,64]
__device__ bf g_k_hi [ROWS*HID], g_k_lo [ROWS*HID];   // [B,H,S,64]
__device__ bf g_vt_hi[ROWS*HID], g_vt_lo[ROWS*HID];   // [B,H,64,S]
__device__ bf g_ctx_hi[ROWS*HID], g_ctx_lo[ROWS*HID]; // [B*S,768]
__device__ bf g_ff_hi[ROWS*FFDIM], g_ff_lo[ROWS*FFDIM];

__device__ bf g_WqkvT_hi[3*HID*HID], g_WqkvT_lo[3*HID*HID];  // [2304,768]
__device__ bf g_WoT_hi[HID*HID],  g_WoT_lo[HID*HID];
__device__ bf g_W1T_hi[HID*FFDIM], g_W1T_lo[HID*FFDIM]; // [3072,768]
__device__ bf g_W2T_hi[HID*FFDIM], g_W2T_lo[HID*FFDIM]; // [768,3072]

// ---------------- PTX helpers (sm_100 baseline only) ----------------
__device__ __forceinline__ uint32_t smem_u32(const void* p){
    uint32_t a;
    asm("{ .reg .u64 t; cvta.to.shared.u64 t, %1; cvt.u32.u64 %0, t; }" : "=r"(a) : "l"(p));
    return a;
}
__device__ __forceinline__ void cp16(uint32_t dst, const void* src){
    asm volatile("cp.async.cg.shared.global [%0], [%1], 16;" :: "r"(dst), "l"(src));
}
#define CP_COMMIT() asm volatile("cp.async.commit_group;" ::: "memory")
#define CP_WAIT(n)  asm volatile("cp.async.wait_group %0;" :: "n"(n) : "memory")

__device__ __forceinline__ void ldsm4(uint32_t* r, uint32_t addr){
    asm volatile("ldmatrix.sync.aligned.m8n8.x4.shared.b16 {%0,%1,%2,%3}, [%4];"
                 : "=r"(r[0]), "=r"(r[1]), "=r"(r[2]), "=r"(r[3]) : "r"(addr));
}

__device__ __forceinline__ void mma16816(float* d, const uint32_t* a,
                                         uint32_t b0, uint32_t b1){
    asm volatile(
        "mma.sync.aligned.m16n8k16.row.col.f32.bf16.bf16.f32 "
        "{%0,%1,%2,%3}, {%4,%5,%6,%7}, {%8,%9}, {%0,%1,%2,%3};"
        : "+f"(d[0]), "+f"(d[1]), "+f"(d[2]), "+f"(d[3])
        : "r"(a[0]), "r"(a[1]), "r"(a[2]), "r"(a[3]), "r"(b0), "r"(b1));
}

__device__ __forceinline__ void bsplit(float v, bf& h, bf& l){
    h = __float2bfloat16(v);
    l = __float2bfloat16(v - __bfloat162float(h));
}

// ---------------- reductions ----------------
__device__ __forceinline__ float warpSum(float v){
#pragma unroll
    for (int o=16;o>0;o>>=1) v += __shfl_xor_sync(0xffffffffu, v, o);
    return v;
}
__device__ float blockSum(float v){
    __shared__ float sh[8];
    __shared__ float total;
    int lane = threadIdx.x & 31, wid = threadIdx.x >> 5;
    v = warpSum(v);
    __syncthreads();
    if (lane == 0) sh[wid] = v;
    __syncthreads();
    if (wid == 0){
        float r = (lane < 8) ? sh[lane] : 0.f;
        r = warpSum(r);
        if (lane == 0) total = r;
    }
    __syncthreads();
    return total;
}

// ---------------- small kernels ----------------
__global__ void split_copy_k(const float* __restrict__ src, float* __restrict__ dstF,
                             bf* __restrict__ hi, bf* __restrict__ lo, int n){
    int i = blockIdx.x*blockDim.x + threadIdx.x;
    if (i >= n) return;
    float v = src[i];
    dstF[i] = v;
    bf h, l; bsplit(v, h, l);
    hi[i] = h; lo[i] = l;
}

__global__ void mask_k(const int* __restrict__ seg, float* __restrict__ mask){
    int i = blockIdx.x*blockDim.x + threadIdx.x;
    if (i < ROWS) mask[i] = (seg[i] > 0) ? 0.f : -10000.f;
}

__device__ __forceinline__ int rel_bucket(int qpos, int kpos){
    int rel = kpos - qpos;
    int off = (rel > 0) ? 16 : 0;
    int ar  = rel < 0 ? -rel : rel;
    if (ar < 8) return off + ar;
    float t = logf((float)ar / 8.0f) / 2.772588722239781f * 8.0f;
    int v = 8 + (int)t;
    if (v > 15) v = 15;
    return off + v;
}

__global__ void posbias_k(const float* __restrict__ rel_emb, float* __restrict__ pb){
    int idx = blockIdx.x*blockDim.x + threadIdx.x;
    if (idx >= SEQ*SEQ) return;
    int q = idx >> 9, k = idx & 511;
    int bkt = rel_bucket(q, k);
#pragma unroll
    for (int h=0; h<NHEADS; h++)
        pb[((long)h*SEQ + q)*SEQ + k] = rel_emb[bkt*NHEADS + h];
}

// W[K,N] fp32 -> WT hi/lo [N,K] bf16, 32x32 smem-tiled
__global__ void tsplit_k(const float* __restrict__ W,
                         bf* __restrict__ Thi, bf* __restrict__ Tlo,
                         int K, int N){
    __shared__ float t[32][33];
    int k0 = blockIdx.y*32, n0 = blockIdx.x*32;
    int x = threadIdx.x, y = threadIdx.y;
#pragma unroll
    for (int i=y; i<32; i+=8) t[i][x] = W[(long)(k0+i)*N + n0 + x];
    __syncthreads();
#pragma unroll
    for (int i=y; i<32; i+=8){
        float v = t[x][i];
        bf h, l; bsplit(v, h, l);
        long o = (long)(n0+i)*K + k0 + x;
        Thi[o] = h; Tlo[o] = l;
    }
}

__global__ __launch_bounds__(256) void resln_k(
    const float* __restrict__ resid, const float* __restrict__ x,
    const float* __restrict__ g, const float* __restrict__ b,
    float* __restrict__ out,
    bf* __restrict__ ohi, bf* __restrict__ olo)
{
    long base = (long)blockIdx.x * HID;
    int t = threadIdx.x;
    float v[3]; float s = 0.f;
#pragma unroll
    for (int i=0;i<3;i++){ v[i] = resid[base + t + 256*i] + x[base + t + 256*i]; s += v[i]; }
    s = blockSum(s);
    float mean = s * (1.f/768.f);
    float q = 0.f;
#pragma unroll
    for (int i=0;i<3;i++){ float d = v[i]-mean; q += d*d; }
    q = blockSum(q);
    float inv = 1.f / sqrtf(q*(1.f/768.f) + 1e-6f);
#pragma unroll
    for (int i=0;i<3;i++){
        int c = t + 256*i;
        float r = g[c]*(v[i]-mean)*inv + b[c];
        out[base + c] = r;
        bf h, l; bsplit(r, h, l);
        ohi[base + c] = h; olo[base + c] = l;
    }
}

// ---------------- fused flash attention (unchanged from R10) ----------------
#define FLASH_SMEM 167936

__global__ __launch_bounds__(512,1) void flash_k(
    const bf* __restrict__ Qh, const bf* __restrict__ Ql,
    const bf* __restrict__ Kh, const bf* __restrict__ Kl,
    const bf* __restrict__ Vth, const bf* __restrict__ Vtl,
    const float* __restrict__ pbias, const float* __restrict__ mk,
    bf* __restrict__ ctxHi, bf* __restrict__ ctxLo)
{
    constexpr int Q_HI=0, Q_LO=16384, K_HI=32768, K_LO=49152;
    constexpr int V_HI=65536, V_LO=81920, P_HI=98304, P_LO=131072;
    constexpr int REDM=163840, REDS=165888;
    extern __shared__ __align__(16) char smem[];
    const uint32_t sb = smem_u32(smem);
    float* redM = (float*)(smem + REDM);
    float* redS = (float*)(smem + REDS);

    const int tid=threadIdx.x, lane=tid&31, warp=tid>>5;
    const int warpM = warp>>2, warpN = warp&3;
    const int q0 = blockIdx.x*128, bh = blockIdx.y;
    const int b = bh/NHEADS, h = bh - b*NHEADS;
    const long baseQK = (long)bh*SEQ*HDIM;
    const long baseV  = (long)bh*HDIM*SEQ;

    const int lt = lane>>3, lrow = ((lt&1)<<3)+(lane&7), lcol = (lt>>1)<<4;
    const int qr = lane>>2, qc = (lane&3)*2;

    for (int ci = tid; ci < 2048; ci += 512){
        int r = ci>>3, c16 = ci&7, rr = r&127;
        const bf* src = ((r<128)?Qh:Ql) + baseQK + (long)(q0+rr)*HDIM + c16*8;
        cp16(sb + (r<128?Q_HI:Q_LO) + rr*128 + (uint32_t)((c16*16)^((rr&7)<<4)), src);
    }
    auto loadKV = [&](int j){
        for (int ci = tid; ci < 4096; ci += 512){
            if (ci < 2048){
                int r = ci>>3, c16 = ci&7, rr = r&127;
                const bf* src = ((r<128)?Kh:Kl) + baseQK + (long)(j*128+rr)*HDIM + c16*8;
                cp16(sb + (r<128?K_HI:K_LO) + rr*128 + (uint32_t)((c16*16)^((rr&7)<<4)), src);
            } else {
                int t = ci-2048, r = t>>4, c16 = t&15, dd = r&63;
                const bf* src = ((r<64)?Vth:Vtl) + baseV + (long)dd*SEQ + j*128 + c16*8;
                cp16(sb + (r<64?V_HI:V_LO) + dd*256 + (uint32_t)((c16*16)^((dd&7)<<4)), src);
            }
        }
        CP_COMMIT();
    };
    loadKV(0);

    float m_run[4], l_run[4];
#pragma unroll
    for (int i=0;i<4;i++){ m_run[i] = -3.0e38f; l_run[i] = 0.f; }
    float oacc[2][2][4];
#pragma unroll
    for (int mt=0;mt<2;mt++)
#pragma unroll
        for (int nt=0;nt<2;nt++)
#pragma unroll
            for (int e=0;e<4;e++) oacc[mt][nt][e] = 0.f;

    for (int j=0;j<4;j++){
        CP_WAIT(0); __syncthreads();

        float acc[2][4][4];
#pragma unroll
        for (int mt=0;mt<2;mt++)
#pragma unroll
            for (int nt=0;nt<4;nt++)
#pragma unroll
                for (int e=0;e<4;e++) acc[mt][nt][e] = 0.f;
#pragma unroll
        for (int kk=0;kk<4;kk++){
            const uint32_t kb = (uint32_t)(kk<<5);
            uint32_t ah[2][4], al[2][4];
#pragma unroll
            for (int mt=0;mt<2;mt++){
                int r = warpM*32 + mt*16 + lrow;
                uint32_t cb = (kb + lcol) ^ ((uint32_t)(r&7)<<4);
                ldsm4(ah[mt], sb + Q_HI + r*128 + cb);
                ldsm4(al[mt], sb + Q_LO + r*128 + cb);
            }
            uint32_t bhf[2][4], blf[2][4];
#pragma unroll
            for (int g=0; g<2; g++){
                int r = warpN*32 + g*16 + lrow;
                uint32_t cb = (kb + lcol) ^ ((uint32_t)(r&7)<<4);
                ldsm4(bhf[g], sb + K_HI + r*128 + cb);
                ldsm4(blf[g], sb + K_LO + r*128 + cb);
            }
#pragma unroll
            for (int mt=0;mt<2;mt++)
#pragma unroll
                for (int nt=0;nt<4;nt++){
                    int g = nt>>1, sH = nt&1;
                    mma16816(acc[mt][nt], ah[mt], bhf[g][sH], bhf[g][sH+2]);
                    mma16816(acc[mt][nt], ah[mt], blf[g][sH], blf[g][sH+2]);
                    mma16816(acc[mt][nt], al[mt], bhf[g][sH], bhf[g][sH+2]);
                }
        }

        float pmax[4] = {-3.0e38f,-3.0e38f,-3.0e38f,-3.0e38f};
#pragma unroll
        for (int mt=0;mt<2;mt++){
            int r0 = q0 + warpM*32 + mt*16 + qr;
            const float* pbr0 = pbias + ((long)h*SEQ + r0)*SEQ;
            const float* pbr1 = pbr0 + 8*SEQ;
#pragma unroll
            for (int nt=0;nt<4;nt++){
                int col = j*128 + warpN*32 + nt*8 + qc;
                float2 p0 = *(const float2*)(pbr0 + col);
                float2 p1 = *(const float2*)(pbr1 + col);
                float2 mv = *(const float2*)(mk + b*SEQ + col);
                acc[mt][nt][0] = acc[mt][nt][0]*0.125f + p0.x + mv.x;
                acc[mt][nt][1] = acc[mt][nt][1]*0.125f + p0.y + mv.y;
                acc[mt][nt][2] = acc[mt][nt][2]*0.125f + p1.x + mv.x;
                acc[mt][nt][3] = acc[mt][nt][3]*0.125f + p1.y + mv.y;
                pmax[mt*2]   = fmaxf(pmax[mt*2],   fmaxf(acc[mt][nt][0], acc[mt][nt][1]));
                pmax[mt*2+1] = fmaxf(pmax[mt*2+1], fmaxf(acc[mt][nt][2], acc[mt][nt][3]));
            }
        }
#pragma unroll
        for (int ri=0;ri<4;ri++){
            pmax[ri] = fmaxf(pmax[ri], __shfl_xor_sync(0xffffffffu, pmax[ri], 1));
            pmax[ri] = fmaxf(pmax[ri], __shfl_xor_sync(0xffffffffu, pmax[ri], 2));
        }
        if ((lane&3)==0){
#pragma unroll
            for (int ri=0;ri<4;ri++){
                int rl = warpM*32 + (ri>>1)*16 + qr + (ri&1)*8;
                redM[rl*4 + warpN] = pmax[ri];
            }
        }
        __syncthreads();

        float alpha[4];
#pragma unroll
        for (int ri=0;ri<4;ri++){
            int rl = warpM*32 + (ri>>1)*16 + qr + (ri&1)*8;
            float tm = fmaxf(fmaxf(redM[rl*4],redM[rl*4+1]), fmaxf(redM[rl*4+2],redM[rl*4+3]));
            float mn = fmaxf(m_run[ri], tm);
            alpha[ri] = expf(m_run[ri] - mn);
            m_run[ri] = mn;
        }

        float psum[4] = {0.f,0.f,0.f,0.f};
#pragma unroll
        for (int mt=0;mt<2;mt++){
            int rl0 = warpM*32 + mt*16 + qr;
            int rl1 = rl0 + 8;
#pragma unroll
            for (int nt=0;nt<4;nt++){
                float e0 = expf(acc[mt][nt][0] - m_run[mt*2]);
                float e1 = expf(acc[mt][nt][1] - m_run[mt*2]);
                float e2 = expf(acc[mt][nt][2] - m_run[mt*2+1]);
                float e3 = expf(acc[mt][nt][3] - m_run[mt*2+1]);
                psum[mt*2]   += e0 + e1;
                psum[mt*2+1] += e2 + e3;
                int colb = (warpN*32 + nt*8 + qc)*2;
                bf h0,l0,h1,l1,h2,l2,h3,l3;
                bsplit(e0,h0,l0); bsplit(e1,h1,l1);
                bsplit(e2,h2,l2); bsplit(e3,h3,l3);
                uint32_t sw0 = (uint32_t)colb ^ ((uint32_t)(rl0&7)<<4);
                uint32_t sw1 = (uint32_t)colb ^ ((uint32_t)(rl1&7)<<4);
                *(__nv_bfloat162*)(smem + P_HI + rl0*256 + sw0) = __nv_bfloat162(h0,h1);
                *(__nv_bfloat162*)(smem + P_LO + rl0*256 + sw0) = __nv_bfloat162(l0,l1);
                *(__nv_bfloat162*)(smem + P_HI + rl1*256 + sw1) = __nv_bfloat162(h2,h3);
                *(__nv_bfloat162*)(smem + P_LO + rl1*256 + sw1) = __nv_bfloat162(l2,l3);
            }
        }
#pragma unroll
        for (int ri=0;ri<4;ri++){
            psum[ri] += __shfl_xor_sync(0xffffffffu, psum[ri], 1);
            psum[ri] += __shfl_xor_sync(0xffffffffu, psum[ri], 2);
        }
        if ((lane&3)==0){
#pragma unroll
            for (int ri=0;ri<4;ri++){
                int rl = warpM*32 + (ri>>1)*16 + qr + (ri&1)*8;
                redS[rl*4 + warpN] = psum[ri];
            }
        }
        __syncthreads();

#pragma unroll
        for (int ri=0;ri<4;ri++){
            int rl = warpM*32 + (ri>>1)*16 + qr + (ri&1)*8;
            float ts = redS[rl*4] + redS[rl*4+1] + redS[rl*4+2] + redS[rl*4+3];
            l_run[ri] = alpha[ri]*l_run[ri] + ts;
        }
#pragma unroll
        for (int mt=0;mt<2;mt++)
#pragma unroll
            for (int nt=0;nt<2;nt++)
#pragma unroll
                for (int e=0;e<4;e++) oacc[mt][nt][e] *= alpha[mt*2 + (e>>1)];

#pragma unroll
        for (int ks=0;ks<8;ks++){
            const uint32_t kb2 = (uint32_t)(ks<<5);
            uint32_t pah[2][4], pal[2][4];
#pragma unroll
            for (int mt=0;mt<2;mt++){
                int r = warpM*32 + mt*16 + lrow;
                uint32_t cb = (kb2 + lcol) ^ ((uint32_t)(r&7)<<4);
                ldsm4(pah[mt], sb + P_HI + r*256 + cb);
                ldsm4(pal[mt], sb + P_LO + r*256 + cb);
            }
            uint32_t vbh[4], vbl[4];
            {
                int n = warpN*16 + lrow;
                uint32_t cb = (kb2 + lcol) ^ ((uint32_t)(n&7)<<4);
                ldsm4(vbh, sb + V_HI + n*256 + cb);
                ldsm4(vbl, sb + V_LO + n*256 + cb);
            }
#pragma unroll
            for (int mt=0;mt<2;mt++)
#pragma unroll
                for (int nt=0;nt<2;nt++){
                    mma16816(oacc[mt][nt], pah[mt], vbh[nt], vbh[nt+2]);
                    mma16816(oacc[mt][nt], pah[mt], vbl[nt], vbl[nt+2]);
                    mma16816(oacc[mt][nt], pal[mt], vbh[nt], vbh[nt+2]);
                }
        }
        __syncthreads();
        if (j < 3) loadKV(j+1);
    }

    float inv[4];
#pragma unroll
    for (int ri=0;ri<4;ri++) inv[ri] = 1.f / l_run[ri];
#pragma unroll
    for (int mt=0;mt<2;mt++){
        int m0 = q0 + warpM*32 + mt*16 + qr;
#pragma unroll
        for (int nt=0;nt<2;nt++){
            int col = h*HDIM + warpN*16 + nt*8 + qc;
            long i0 = ((long)(b*SEQ + m0))*HID + col;
            long i1 = i0 + 8L*HID;
            float e0 = oacc[mt][nt][0]*inv[mt*2];
            float e1 = oacc[mt][nt][1]*inv[mt*2];
            float e2 = oacc[mt][nt][2]*inv[mt*2+1];
            float e3 = oacc[mt][nt][3]*inv[mt*2+1];
            bf h0,l0,h1,l1,h2,l2,h3,l3;
            bsplit(e0,h0,l0); bsplit(e1,h1,l1);
            bsplit(e2,h2,l2); bsplit(e3,h3,l3);
            *(__nv_bfloat162*)&ctxHi[i0] = __nv_bfloat162(h0,h1);
            *(__nv_bfloat162*)&ctxLo[i0] = __nv_bfloat162(l0,l1);
            *(__nv_bfloat162*)&ctxHi[i1] = __nv_bfloat162(h2,h3);
            *(__nv_bfloat162*)&ctxLo[i1] = __nv_bfloat162(l2,l3);
        }
    }
}

// ---------------- mma.sync GEMM (BK=64, 2-stage cp.async, ldmatrix) ----------------
// Warp layout: WGM=BM_/32 rows x WGN=(NT/32)/WGM cols; warp tile 32 x (BN_/WGN).
enum { EPI_PLAIN=0, EPI_GELU=1, EPI_QKV3=2 };

template<int BM_, int BN_, int NT, int EPI>
__global__ __launch_bounds__(NT, (NT==256)?2:1) void mma_gemm(
    const bf* __restrict__ Ahi, const bf* __restrict__ Alo,
    const bf* __restrict__ Bhi, const bf* __restrict__ Blo,
    int K, int lda, int ldb,
    const float* __restrict__ bias, const float* __restrict__ bias2, const float* __restrict__ bias3,
    float* __restrict__ outF,
    bf* __restrict__ outHi, bf* __restrict__ outLo,
    bf* __restrict__ out2Hi, bf* __restrict__ out2Lo,
    bf* __restrict__ out3Hi, bf* __restrict__ out3Lo,
    int ldc)
{
    constexpr int NWARPS = NT/32;
    constexpr int WGM = BM_/32;
    constexpr int WGN = NWARPS/WGM;
    constexpr int WN  = BN_/WGN;          // 64 (512thr,128x256) or 32 (256thr,64x128)
    constexpr int MT  = 2;
    constexpr int NTT = WN/8;             // 8 or 4
    constexpr int NG  = NTT/2;            // 4 or 2
    constexpr int A_HI = 0;
    constexpr int A_LO = BM_*128;
    constexpr int B_HI = 2*BM_*128;
    constexpr int B_LO = 2*BM_*128 + BN_*128;
    constexpr int STAGE = 2*BM_*128 + 2*BN_*128;
    constexpr int TOT_ROWS = 2*BM_ + 2*BN_;

    extern __shared__ __align__(16) char smem[];
    const uint32_t sbase = smem_u32(smem);

    const int tid = threadIdx.x, lane = tid & 31, warp = tid >> 5;
    const int warpM = warp / WGN, warpN = warp % WGN;
    const int mBase = blockIdx.y * BM_, nBase = blockIdx.x * BN_;

    auto issue = [&](int c){
        const int s = c & 1, k0 = c << 6;
        const uint32_t segbase = sbase + (uint32_t)(s * STAGE);
        for (int ci = tid; ci < TOT_ROWS*8; ci += NT){
            int r = ci >> 3, c16 = ci & 7;
            const bf* src; uint32_t toff; int rr;
            if (r < BM_)            { rr = r;          src = Ahi + (long)(mBase+rr)*lda + k0; toff = A_HI; }
            else if (r < 2*BM_)     { rr = r-BM_;      src = Alo + (long)(mBase+rr)*lda + k0; toff = A_LO; }
            else if (r < 2*BM_+BN_) { rr = r-2*BM_;    src = Bhi + (long)(nBase+rr)*ldb + k0; toff = B_HI; }
            else                    { rr = r-2*BM_-BN_;src = Blo + (long)(nBase+rr)*ldb + k0; toff = B_LO; }
            uint32_t dst = segbase + toff + (uint32_t)(rr*128) + (uint32_t)((c16*16) ^ ((rr&7)<<4));
            cp16(dst, src + c16*8);
        }
        CP_COMMIT();
    };

    float acc[MT][NTT][4];
#pragma unroll
    for (int i=0;i<MT;i++)
#pragma unroll
        for (int j=0;j<NTT;j++)
#pragma unroll
            for (int e=0;e<4;e++) acc[i][j][e] = 0.f;

    const int lt  = lane >> 3;
    const int lrow = ((lt & 1) << 3) + (lane & 7);
    const int lcol = (lt >> 1) << 4;

    const int CH = K >> 6;
    issue(0);

    for (int c = 0; c < CH; ++c){
        if (c + 1 < CH) { issue(c + 1); CP_WAIT(1); }
        else            { CP_WAIT(0); }
        __syncthreads();

        const uint32_t st = sbase + (uint32_t)((c & 1) * STAGE);
#pragma unroll
        for (int kk = 0; kk < 4; ++kk){
            const uint32_t kb = (uint32_t)(kk << 5);
            uint32_t ah[MT][4], al[MT][4];
#pragma unroll
            for (int mt = 0; mt < MT; ++mt){
                int r = warpM*32 + mt*16 + lrow;
                uint32_t cb = (kb + lcol) ^ ((uint32_t)(r&7) << 4);
                ldsm4(ah[mt], st + A_HI + r*128 + cb);
                ldsm4(al[mt], st + A_LO + r*128 + cb);
            }
#pragma unroll
            for (int g = 0; g < NG; ++g){
                uint32_t bh[4], bl[4];
                int r = warpN*WN + g*16 + lrow;
                uint32_t cb = (kb + lcol) ^ ((uint32_t)(r&7) << 4);
                ldsm4(bh, st + B_HI + r*128 + cb);
                ldsm4(bl, st + B_LO + r*128 + cb);
#pragma unroll
                for (int mt = 0; mt < MT; ++mt)
#pragma unroll
                    for (int sH = 0; sH < 2; ++sH){
                        int nt = g*2 + sH;
                        mma16816(acc[mt][nt], ah[mt], bh[sH], bh[sH+2]);
                        mma16816(acc[mt][nt], ah[mt], bl[sH], bl[sH+2]);
                        mma16816(acc[mt][nt], al[mt], bh[sH], bh[sH+2]);
                    }
            }
        }
        __syncthreads();   // buffer c consumed; safe for issue(c+2) next iter
    }

    // epilogue via padded smem
    float* sD = (float*)smem;
    constexpr int LDD = BN_ + 1;
#pragma unroll
    for (int mt = 0; mt < MT; ++mt)
#pragma unroll
        for (int nt = 0; nt < NTT; ++nt){
            int r0 = warpM*32 + mt*16 + (lane >> 2);
            int c0 = warpN*WN + nt*8 + (lane & 3)*2;
            sD[r0*LDD + c0]       = acc[mt][nt][0];
            sD[r0*LDD + c0 + 1]   = acc[mt][nt][1];
            sD[(r0+8)*LDD + c0]   = acc[mt][nt][2];
            sD[(r0+8)*LDD + c0+1] = acc[mt][nt][3];
        }
    __syncthreads();

    if (EPI == EPI_QKV3){
        const int which = nBase / HID;      // 768 = 3*256, tiles never straddle
        const int nloc0 = nBase - which*HID;
        const float* bs = (which==0) ? bias : (which==1) ? bias2 : bias3;
        bf* oHi = (which==0) ? outHi : (which==1) ? out2Hi : out3Hi;
        bf* oLo = (which==0) ? outLo : (which==1) ? out2Lo : out3Lo;
        if (which < 2){
            constexpr int NQ = BN_/4;
            for (int t = tid; t < BM_*NQ; t += NT){
                int m = t / NQ, nq = t % NQ;
                int nl = nloc0 + nq*4;
                int mg = mBase + m, b_ = mg >> 9, sidx = mg & 511;
                int h = nl >> 6, dd = nl & 63;
                float e[4];
#pragma unroll
                for (int j=0;j<4;j++) e[j] = sD[m*LDD + nq*4 + j] + bs[nl+j];
                bf h0,h1,h2,h3,l0,l1,l2,l3;
                bsplit(e[0],h0,l0); bsplit(e[1],h1,l1);
                bsplit(e[2],h2,l2); bsplit(e[3],h3,l3);
                long idx = ((long)(b_*NHEADS + h)*SEQ + sidx)*HDIM + dd;
                *(__nv_bfloat162*)&oHi[idx]   = __nv_bfloat162(h0,h1);
                *(__nv_bfloat162*)&oHi[idx+2] = __nv_bfloat162(h2,h3);
                *(__nv_bfloat162*)&oLo[idx]   = __nv_bfloat162(l0,l1);
                *(__nv_bfloat162*)&oLo[idx+2] = __nv_bfloat162(l2,l3);
            }
        } else {
            for (int t = tid; t < BM_*BN_; t += NT){
                int m = t & (BM_-1), n = t / BM_;
                int nl = nloc0 + n, h = nl >> 6, dd = nl & 63;
                int mg = mBase + m, b_ = mg >> 9, sidx = mg & 511;
                float v = sD[m*LDD + n] + bs[nl];
                bf hh, ll; bsplit(v, hh, ll);
                long idx = ((long)(b_*NHEADS + h)*HDIM + dd)*SEQ + sidx;
                oHi[idx] = hh; oLo[idx] = ll;
            }
        }
    } else {
        constexpr int NQ = BN_ / 4;
        for (int t = tid; t < BM_*NQ; t += NT){
            int m = t / NQ, nq = t % NQ;
            int n0 = nBase + nq*4;
            int mg = mBase + m;
            float e[4];
#pragma unroll
            for (int j=0;j<4;j++) e[j] = sD[m*LDD + nq*4 + j];
            if (EPI == EPI_PLAIN){
#pragma unroll
                for (int j=0;j<4;j++) e[j] += bias[n0+j];
                float4 v = {e[0],e[1],e[2],e[3]};
                *(float4*)&outF[(long)mg*ldc + n0] = v;
            } else { // EPI_GELU
#pragma unroll
                for (int j=0;j<4;j++){
                    float t2 = e[j] + bias[n0+j];
                    e[j] = 0.5f*t2*(1.f + erff(t2*0.70710678118654752f));
                }
                bf h0,h1,h2,h3,l0,l1,l2,l3;
                bsplit(e[0],h0,l0); bsplit(e[1],h1,l1);
                bsplit(e[2],h2,l2); bsplit(e[3],h3,l3);
                long idx = (long)mg*ldc + n0;
                *(__nv_bfloat162*)&outHi[idx]   = __nv_bfloat162(h0,h1);
                *(__nv_bfloat162*)&outHi[idx+2] = __nv_bfloat162(h2,h3);
                *(__nv_bfloat162*)&outLo[idx]   = __nv_bfloat162(l0,l1);
                *(__nv_bfloat162*)&outLo[idx+2] = __nv_bfloat162(l2,l3);
            }
        }
    }
}

// ---------------- host ----------------
#define SMEM_BIG  196608   // 2 stages * 96KB (128x256); epilogue 128*257*4=131584 fits
#define SMEM_SML  98304    // 2 stages * 48KB (64x128); 2 CTAs/SM

extern "C" void kernel_launch(void* const* d_in, const int* in_sizes, int n_in,
                              void* d_out, int out_size)
{
    const float* emb     = (const float*)d_in[0];
    const int*   seg     = (const int*)  d_in[1];
    const float* rel_emb = (const float*)d_in[2];
    const float* Wq = (const float*)d_in[3];  const float* bq = (const float*)d_in[4];
    const float* Wk = (const float*)d_in[5];  const float* bk = (const float*)d_in[6];
    const float* Wv = (const float*)d_in[7];  const float* bv = (const float*)d_in[8];
    const float* Wo = (const float*)d_in[9];  const float* bo = (const float*)d_in[10];
    const float* ln1_g = (const float*)d_in[11]; const float* ln1_b = (const float*)d_in[12];
    const float* W1 = (const float*)d_in[13]; const float* b1 = (const float*)d_in[14];
    const float* W2 = (const float*)d_in[15]; const float* b2 = (const float*)d_in[16];
    const float* ln2_g = (const float*)d_in[17]; const float* ln2_b = (const float*)d_in[18];
    float* out = (float*)d_out;

    static bool inited = false;
    static float *hid, *tmp, *pb, *mk;
    static bf *hA_h,*hA_l,*q_h,*q_l,*k_h,*k_l,*vt_h,*vt_l,*cx_h,*cx_l,*ff_h,*ff_l;
    static bf *wqkv_h,*wqkv_l,*wo_h,*wo_l,*w1_h,*w1_l,*w2_h,*w2_l;
    if (!inited){
        inited = true;
        cudaGetSymbolAddress((void**)&hid, g_hidden);
        cudaGetSymbolAddress((void**)&tmp, g_tmp);
        cudaGetSymbolAddress((void**)&pb,  g_pb);
        cudaGetSymbolAddress((void**)&mk,  g_mask);
        cudaGetSymbolAddress((void**)&hA_h, g_hidA_hi); cudaGetSymbolAddress((void**)&hA_l, g_hidA_lo);
        cudaGetSymbolAddress((void**)&q_h,  g_q_hi);    cudaGetSymbolAddress((void**)&q_l,  g_q_lo);
        cudaGetSymbolAddress((void**)&k_h,  g_k_hi);    cudaGetSymbolAddress((void**)&k_l,  g_k_lo);
        cudaGetSymbolAddress((void**)&vt_h, g_vt_hi);   cudaGetSymbolAddress((void**)&vt_l, g_vt_lo);
        cudaGetSymbolAddress((void**)&cx_h, g_ctx_hi);  cudaGetSymbolAddress((void**)&cx_l, g_ctx_lo);
        cudaGetSymbolAddress((void**)&ff_h, g_ff_hi);   cudaGetSymbolAddress((void**)&ff_l, g_ff_lo);
        cudaGetSymbolAddress((void**)&wqkv_h, g_WqkvT_hi); cudaGetSymbolAddress((void**)&wqkv_l, g_WqkvT_lo);
        cudaGetSymbolAddress((void**)&wo_h, g_WoT_hi);  cudaGetSymbolAddress((void**)&wo_l, g_WoT_lo);
        cudaGetSymbolAddress((void**)&w1_h, g_W1T_hi);  cudaGetSymbolAddress((void**)&w1_l, g_W1T_lo);
        cudaGetSymbolAddress((void**)&w2_h, g_W2T_hi);  cudaGetSymbolAddress((void**)&w2_l, g_W2T_lo);
        cudaFuncSetAttribute(mma_gemm<128,256,512,EPI_QKV3>, cudaFuncAttributeMaxDynamicSharedMemorySize, SMEM_BIG);
        cudaFuncSetAttribute(mma_gemm<128,256,512,EPI_GELU>, cudaFuncAttributeMaxDynamicSharedMemorySize, SMEM_BIG);
        cudaFuncSetAttribute(mma_gemm<64,128,256,EPI_PLAIN>, cudaFuncAttributeMaxDynamicSharedMemorySize, SMEM_SML);
        cudaFuncSetAttribute(flash_k, cudaFuncAttributeMaxDynamicSharedMemorySize, FLASH_SMEM);
    }

    // ---- setup ----
    tsplit_k<<<dim3(HID/32, HID/32),   dim3(32,8)>>>(Wq, wqkv_h,            wqkv_l,            HID, HID);
    tsplit_k<<<dim3(HID/32, HID/32),   dim3(32,8)>>>(Wk, wqkv_h + HID*HID,  wqkv_l + HID*HID,  HID, HID);
    tsplit_k<<<dim3(HID/32, HID/32),   dim3(32,8)>>>(Wv, wqkv_h + 2*HID*HID,wqkv_l + 2*HID*HID,HID, HID);
    split_copy_k<<<(ROWS*HID+255)/256, 256>>>(emb, hid, hA_h, hA_l, ROWS*HID);
    tsplit_k<<<dim3(HID/32, HID/32),   dim3(32,8)>>>(Wo, wo_h, wo_l, HID, HID);
    // layer-0 QKV hoisted (profiling target, launch idx 5)
    mma_gemm<128,256,512,EPI_QKV3><<<dim3(9,32,1),512,SMEM_BIG>>>(
        hA_h,hA_l, wqkv_h,wqkv_l, HID, HID, HID,
        bq, bk, bv, nullptr, q_h,q_l, k_h,k_l, vt_h,vt_l, 0);
    mask_k<<<(ROWS+255)/256, 256>>>(seg, mk);
    posbias_k<<<(SEQ*SEQ+255)/256, 256>>>(rel_emb, pb);
    tsplit_k<<<dim3(FFDIM/32, HID/32), dim3(32,8)>>>(W1, w1_h, w1_l, HID, FFDIM);
    tsplit_k<<<dim3(HID/32, FFDIM/32), dim3(32,8)>>>(W2, w2_h, w2_l, FFDIM, HID);

    for (int L=0; L<NLAYERS; L++){
        if (L > 0)
            mma_gemm<128,256,512,EPI_QKV3><<<dim3(9,32,1),512,SMEM_BIG>>>(
                hA_h,hA_l, wqkv_h,wqkv_l, HID, HID, HID,
                bq, bk, bv, nullptr, q_h,q_l, k_h,k_l, vt_h,vt_l, 0);

        // fused attention
        flash_k<<<dim3(4, NBH), 512, FLASH_SMEM>>>(
            q_h,q_l, k_h,k_l, vt_h,vt_l, pb, mk, cx_h, cx_l);

        // O projection (64x128, 2 CTAs/SM)
        mma_gemm<64,128,256,EPI_PLAIN><<<dim3(6,64,1),256,SMEM_SML>>>(
            cx_h,cx_l, wo_h,wo_l, HID, HID, HID,
            bo,nullptr,nullptr, tmp, nullptr,nullptr, nullptr,nullptr, nullptr,nullptr, HID);
        resln_k<<<ROWS,256>>>(hid, tmp, ln1_g, ln1_b, hid, hA_h, hA_l);

        // FF1 (GELU), 128x256
        mma_gemm<128,256,512,EPI_GELU><<<dim3(12,32,1),512,SMEM_BIG>>>(
            hA_h,hA_l, w1_h,w1_l, HID, HID, HID,
            b1,nullptr,nullptr, nullptr, ff_h,ff_l, nullptr,nullptr, nullptr,nullptr, FFDIM);
        // FF2 (64x128, 2 CTAs/SM)
        mma_gemm<64,128,256,EPI_PLAIN><<<dim3(6,64,1),256,SMEM_SML>>>(
            ff_h,ff_l, w2_h,w2_l, FFDIM, FFDIM, FFDIM,
            b2,nullptr,nullptr, tmp, nullptr,nullptr, nullptr,nullptr, nullptr,nullptr, HID);
        resln_k<<<ROWS,256>>>(hid, tmp, ln2_g, ln2_b, (L==NLAYERS-1) ? out : hid, hA_h, hA_l);
    }
}